// round 9
// baseline (speedup 1.0000x reference)
#include <cuda_runtime.h>
#include <math.h>

#define Nn 30000
#define Ee 960000
#define ET (Ee + Nn)
#define Hh 2
#define Cc 128
#define HC 256
#define Gg 64
#define EPSB 1e-5f

typedef unsigned long long ull;

// ---------------- scratch (device globals; no allocation allowed) ----------------
__device__ float  g_xp[(size_t)Nn * HC];     // x @ gat_w          [N,256]
__device__ float  g_as[Nn * Hh];             // attention src dots [N,2]
__device__ float  g_ad[Nn * Hh];             // attention dst dots [N,2]
__device__ int    g_deg[Nn];                 // in-degree
__device__ int    g_ptr[Nn + 1];             // CSR offsets
__device__ int    g_cur[Nn];                 // scatter cursors
__device__ int4   g_csre[ET];                // CSR edge: {src, w0, w1, pad}
__device__ float  g_acc[(size_t)Nn * HC];    // normalized aggregation
__device__ float  g_h1[(size_t)Nn * Cc];     // elu(out) @ mlp_w + b
__device__ float  g_bnsum[2 * Cc];
__device__ float  g_sc0[Cc], g_sh0[Cc];
__device__ float  g_hp[Gg * Cc];
__device__ float  g_z1[Gg * 512];
__device__ float  g_sc1[512], g_sh1[512];
__device__ float  g_z2[Gg * 256];
__device__ float  g_sc2[256], g_sh2[256];

// ---------------- f32x2 helpers ----------------
__device__ __forceinline__ ull pk2(float lo, float hi) {
    ull d;
    asm("mov.b64 %0, {%1, %2};" : "=l"(d) : "r"(__float_as_uint(lo)), "r"(__float_as_uint(hi)));
    return d;
}
__device__ __forceinline__ float2 upk(ull v) {
    unsigned lo, hi;
    asm("mov.b64 {%0, %1}, %2;" : "=r"(lo), "=r"(hi) : "l"(v));
    return make_float2(__uint_as_float(lo), __uint_as_float(hi));
}
__device__ __forceinline__ ull fma2(ull a, ull b, ull c) {
    ull d;
    asm("fma.rn.f32x2 %0, %1, %2, %3;" : "=l"(d) : "l"(a), "l"(b), "l"(c));
    return d;
}

// ---------------- init ----------------
__global__ void k_init() {
    int i = blockIdx.x * blockDim.x + threadIdx.x;
    if (i < Nn)      g_deg[i] = 0;
    if (i < Gg * Cc) g_hp[i] = 0.f;
    if (i < 2 * Cc)  g_bnsum[i] = 0.f;
}

// ---------------- f32x2 GEMM: 128x128x32, 256 thr, 8x8/thread, 2 CTAs/SM --------
template <int MODE>
__global__ void __launch_bounds__(256, 2)
k_gemm(const float* __restrict__ Aext, const float* __restrict__ B,
       const float* __restrict__ cbias, const float* __restrict__ abias,
       const float* __restrict__ asrc, const float* __restrict__ adst,
       int M, int K, int Nc) {
    __shared__ float As[32][128];
    __shared__ float Bs[32][128];
    int t = threadIdx.x;
    int tx = t & 15, ty = t >> 4;
    int m0 = blockIdx.x * 128, n0 = blockIdx.y * 128;
    int ar_ = t >> 1, akc = (t & 1) * 16;
    int bkb = t >> 4, bc4 = (t & 15) * 8;
    int steps = K >> 5;
    bool rowok = (m0 + ar_) < M;
    const float* Ab = ((MODE == 0) ? Aext : (const float*)g_acc) + (size_t)(m0 + ar_) * K + akc;
    const float* Bb = B + (size_t)bkb * Nc + n0 + bc4;

    ull acc[4][8];
#pragma unroll
    for (int i = 0; i < 4; i++)
#pragma unroll
        for (int j = 0; j < 8; j++) acc[i][j] = 0ull;

    for (int it = 0; it < steps; it++) {
        int k0 = it << 5;
        float4 va[4];
        float4 vb[4];
#pragma unroll
        for (int q = 0; q < 4; q++) va[q] = make_float4(0.f, 0.f, 0.f, 0.f);
        if (rowok) {
#pragma unroll
            for (int q = 0; q < 4; q++) va[q] = *(const float4*)(Ab + k0 + q * 4);
            if (MODE == 1) {
                int gk = k0 + akc;
#pragma unroll
                for (int q = 0; q < 4; q++) {
                    float f[4] = {va[q].x, va[q].y, va[q].z, va[q].w};
#pragma unroll
                    for (int j = 0; j < 4; j++) {
                        float u = f[j] + __ldg(abias + gk + q * 4 + j);
                        f[j] = u > 0.f ? u : (__expf(u) - 1.f);
                    }
                    va[q] = make_float4(f[0], f[1], f[2], f[3]);
                }
            }
        }
        vb[0] = *(const float4*)(Bb + (size_t)k0 * Nc);
        vb[1] = *(const float4*)(Bb + (size_t)k0 * Nc + 4);
        vb[2] = *(const float4*)(Bb + (size_t)(k0 + 16) * Nc);
        vb[3] = *(const float4*)(Bb + (size_t)(k0 + 16) * Nc + 4);

        __syncthreads();
#pragma unroll
        for (int q = 0; q < 4; q++) {
            As[akc + q * 4 + 0][ar_] = va[q].x;
            As[akc + q * 4 + 1][ar_] = va[q].y;
            As[akc + q * 4 + 2][ar_] = va[q].z;
            As[akc + q * 4 + 3][ar_] = va[q].w;
        }
        *(float4*)&Bs[bkb][bc4]          = vb[0];
        *(float4*)&Bs[bkb][bc4 + 4]      = vb[1];
        *(float4*)&Bs[bkb + 16][bc4]     = vb[2];
        *(float4*)&Bs[bkb + 16][bc4 + 4] = vb[3];
        __syncthreads();

#pragma unroll
        for (int k = 0; k < 32; k++) {
            float4 x0 = *(const float4*)&As[k][ty * 8];
            float4 x1 = *(const float4*)&As[k][ty * 8 + 4];
            float4 y0 = *(const float4*)&Bs[k][tx * 8];
            float4 y1 = *(const float4*)&Bs[k][tx * 8 + 4];
            ull A2[4] = {pk2(x0.x, x0.y), pk2(x0.z, x0.w),
                         pk2(x1.x, x1.y), pk2(x1.z, x1.w)};
            float bb[8] = {y0.x, y0.y, y0.z, y0.w, y1.x, y1.y, y1.z, y1.w};
#pragma unroll
            for (int j = 0; j < 8; j++) {
                ull B2 = pk2(bb[j], bb[j]);
#pragma unroll
                for (int i = 0; i < 4; i++) acc[i][j] = fma2(A2[i], B2, acc[i][j]);
            }
        }
    }

    float* Cp = (MODE == 0) ? g_xp : g_h1;
    float cb[8];
#pragma unroll
    for (int j = 0; j < 8; j++) cb[j] = cbias ? cbias[n0 + tx * 8 + j] : 0.f;

    float sa[8], da[8];
    int h = n0 >> 7;
    if (MODE == 0) {
#pragma unroll
        for (int j = 0; j < 8; j++) {
            sa[j] = asrc[(h << 7) + tx * 8 + j];
            da[j] = adst[(h << 7) + tx * 8 + j];
        }
    }

#pragma unroll
    for (int i = 0; i < 4; i++) {
        float2 p[8];
#pragma unroll
        for (int j = 0; j < 8; j++) p[j] = upk(acc[i][j]);
        int re = m0 + ty * 8 + i * 2;
        int gc = n0 + tx * 8;
        if (re < M) {
            *(float4*)(Cp + (size_t)re * Nc + gc) =
                make_float4(p[0].x + cb[0], p[1].x + cb[1], p[2].x + cb[2], p[3].x + cb[3]);
            *(float4*)(Cp + (size_t)re * Nc + gc + 4) =
                make_float4(p[4].x + cb[4], p[5].x + cb[5], p[6].x + cb[6], p[7].x + cb[7]);
        }
        if (re + 1 < M) {
            *(float4*)(Cp + (size_t)(re + 1) * Nc + gc) =
                make_float4(p[0].y + cb[0], p[1].y + cb[1], p[2].y + cb[2], p[3].y + cb[3]);
            *(float4*)(Cp + (size_t)(re + 1) * Nc + gc + 4) =
                make_float4(p[4].y + cb[4], p[5].y + cb[5], p[6].y + cb[6], p[7].y + cb[7]);
        }
        if (MODE == 0) {
            float s0 = 0.f, d0 = 0.f, s1 = 0.f, d1 = 0.f;
#pragma unroll
            for (int j = 0; j < 8; j++) {
                s0 += p[j].x * sa[j]; d0 += p[j].x * da[j];
                s1 += p[j].y * sa[j]; d1 += p[j].y * da[j];
            }
#pragma unroll
            for (int msk = 1; msk < 16; msk <<= 1) {
                s0 += __shfl_xor_sync(0xFFFFFFFFu, s0, msk);
                d0 += __shfl_xor_sync(0xFFFFFFFFu, d0, msk);
                s1 += __shfl_xor_sync(0xFFFFFFFFu, s1, msk);
                d1 += __shfl_xor_sync(0xFFFFFFFFu, d1, msk);
            }
            if (tx == 0) {
                if (re < M)     { g_as[re * 2 + h] = s0;       g_ad[re * 2 + h] = d0; }
                if (re + 1 < M) { g_as[(re + 1) * 2 + h] = s1; g_ad[(re + 1) * 2 + h] = d1; }
            }
        }
    }
}

// ---------------- degree count ----------------
__global__ void k_degree(const int* __restrict__ ei) {
    int i = blockIdx.x * blockDim.x + threadIdx.x;
    if (i >= ET) return;
    int dst = (i < Ee) ? ei[Ee + i] : (i - Ee);
    atomicAdd(&g_deg[dst], 1);
}

// ---------------- exclusive scan (single block) ----------------
__global__ void k_scan() {
    __shared__ int sh[1024];
    int t = threadIdx.x;
    int s = t * 30, e = min(Nn, s + 30);
    int sum = 0;
    for (int i = s; i < e; i++) sum += g_deg[i];
    sh[t] = sum;
    __syncthreads();
    for (int off = 1; off < 1024; off <<= 1) {
        int v = (t >= off) ? sh[t - off] : 0;
        __syncthreads();
        sh[t] += v;
        __syncthreads();
    }
    int run = t ? sh[t - 1] : 0;
    for (int i = s; i < e; i++) {
        g_ptr[i] = run;
        g_cur[i] = run;
        run += g_deg[i];
    }
    if (t == 1023) g_ptr[Nn] = sh[1023];
}

// ---------------- fused edge: logit -> exp -> CSR scatter (packed 16B) ----------
__global__ void k_edge(const int* __restrict__ ei) {
    int i = blockIdx.x * blockDim.x + threadIdx.x;
    if (i >= ET) return;
    int src, dst;
    if (i < Ee) { src = ei[i]; dst = ei[Ee + i]; }
    else        { src = dst = i - Ee; }
    float2 as = *(const float2*)(g_as + src * 2);
    float2 ad = *(const float2*)(g_ad + dst * 2);
    float l0 = as.x + ad.x; l0 = l0 > 0.f ? l0 : 0.2f * l0;
    float l1 = as.y + ad.y; l1 = l1 > 0.f ? l1 : 0.2f * l1;
    float w0 = __expf(l0), w1 = __expf(l1);
    int pos = atomicAdd(&g_cur[dst], 1);
    g_csre[pos] = make_int4(src, __float_as_int(w0), __float_as_int(w1), 0);
}

// ---------------- aggregation: block per dst, 256-edge staging, 4-edge ILP -------
__global__ void __launch_bounds__(256) k_agg() {
    __shared__ int4   se[256];
    __shared__ float4 sha[256];
    __shared__ float  shw[256];
    int dst = blockIdx.x;
    int t = threadIdx.x;
    int grp = t >> 6, l = t & 63;
    int beg = g_ptr[dst], end = g_ptr[dst + 1];
    int deg = end - beg;
    bool hi = l >= 32;
    float4 a0 = make_float4(0.f, 0.f, 0.f, 0.f);
    float4 a1 = a0, a2 = a0, a3 = a0;
    float wsum = 0.f;

    for (int base = 0; base < deg; base += 256) {
        int cnt = min(256, deg - base);
        if (t < cnt) se[t] = g_csre[beg + base + t];   // coalesced, once per chunk
        __syncthreads();
        int e = grp;
        for (; e + 12 < cnt; e += 16) {                // 4 edges in flight per group
            int4 e0 = se[e], e1 = se[e + 4], e2 = se[e + 8], e3 = se[e + 12];
            float w0 = hi ? __int_as_float(e0.z) : __int_as_float(e0.y);
            float w1 = hi ? __int_as_float(e1.z) : __int_as_float(e1.y);
            float w2 = hi ? __int_as_float(e2.z) : __int_as_float(e2.y);
            float w3 = hi ? __int_as_float(e3.z) : __int_as_float(e3.y);
            float4 v0 = __ldg((const float4*)(g_xp + (size_t)e0.x * HC) + l);
            float4 v1 = __ldg((const float4*)(g_xp + (size_t)e1.x * HC) + l);
            float4 v2 = __ldg((const float4*)(g_xp + (size_t)e2.x * HC) + l);
            float4 v3 = __ldg((const float4*)(g_xp + (size_t)e3.x * HC) + l);
            a0.x += v0.x * w0; a0.y += v0.y * w0; a0.z += v0.z * w0; a0.w += v0.w * w0;
            a1.x += v1.x * w1; a1.y += v1.y * w1; a1.z += v1.z * w1; a1.w += v1.w * w1;
            a2.x += v2.x * w2; a2.y += v2.y * w2; a2.z += v2.z * w2; a2.w += v2.w * w2;
            a3.x += v3.x * w3; a3.y += v3.y * w3; a3.z += v3.z * w3; a3.w += v3.w * w3;
            wsum += w0 + w1 + w2 + w3;
        }
        for (; e < cnt; e += 4) {
            int4 e0 = se[e];
            float w0 = hi ? __int_as_float(e0.z) : __int_as_float(e0.y);
            float4 v0 = __ldg((const float4*)(g_xp + (size_t)e0.x * HC) + l);
            a0.x += v0.x * w0; a0.y += v0.y * w0; a0.z += v0.z * w0; a0.w += v0.w * w0;
            wsum += w0;
        }
        __syncthreads();
    }
    a0.x += a1.x + a2.x + a3.x;
    a0.y += a1.y + a2.y + a3.y;
    a0.z += a1.z + a2.z + a3.z;
    a0.w += a1.w + a2.w + a3.w;
    sha[t] = a0; shw[t] = wsum;
    __syncthreads();
    if (grp == 0) {
        float4 a = sha[t], b = sha[t + 64], c = sha[t + 128], d = sha[t + 192];
        float rd = 1.f / (shw[t] + shw[t + 64] + shw[t + 128] + shw[t + 192]);
        float4 r = make_float4((a.x + b.x + c.x + d.x) * rd,
                               (a.y + b.y + c.y + d.y) * rd,
                               (a.z + b.z + c.z + d.z) * rd,
                               (a.w + b.w + c.w + d.w) * rd);
        *((float4*)(g_acc + (size_t)dst * HC) + l) = r;
    }
}

// ---------------- BN0 stats ----------------
__global__ void k_bn0_stats() {
    int c = threadIdx.x;  // 128
    float s = 0.f, s2 = 0.f;
    for (int n = blockIdx.x; n < Nn; n += gridDim.x) {
        float v = g_h1[(size_t)n * Cc + c];
        s += v; s2 += v * v;
    }
    atomicAdd(&g_bnsum[c], s);
    atomicAdd(&g_bnsum[Cc + c], s2);
}

__global__ void k_bn0_final(const float* __restrict__ g, const float* __restrict__ b) {
    int c = threadIdx.x;
    if (c < Cc) {
        float mean = g_bnsum[c] / (float)Nn;
        float var  = fmaxf(g_bnsum[Cc + c] / (float)Nn - mean * mean, 0.f);
        float sc = g[c] * rsqrtf(var + EPSB);
        g_sc0[c] = sc;
        g_sh0[c] = b[c] - mean * sc;
    }
}

// ---------------- normalize + pool ----------------
__global__ void k_pool(const int* __restrict__ batch) {
    int c = threadIdx.x;  // 128
    int per = (Nn + gridDim.x - 1) / gridDim.x;
    int s = blockIdx.x * per;
    int e = min(Nn, s + per);
    if (s >= e) return;
    float sc = g_sc0[c], sh = g_sh0[c];
    int cur = batch[s];
    float a = 0.f;
    for (int n = s; n < e; n++) {
        int gi = batch[n];
        if (gi != cur) { atomicAdd(&g_hp[cur * Cc + c], a); a = 0.f; cur = gi; }
        a += g_h1[(size_t)n * Cc + c] * sc + sh;
    }
    atomicAdd(&g_hp[cur * Cc + c], a);
}

// ---------------- FC stack ----------------
__global__ void k_fc1(const float* __restrict__ w, const float* __restrict__ b) {
    int idx = blockIdx.x * blockDim.x + threadIdx.x;
    if (idx >= Gg * 512) return;
    int c = idx & 511, r = idx >> 9;
    float s = b[c];
#pragma unroll 8
    for (int k = 0; k < Cc; k++) s += g_hp[r * Cc + k] * w[k * 512 + c];
    g_z1[idx] = s;
}

__global__ void k_bn1(const float* __restrict__ g, const float* __restrict__ b) {
    int c = blockIdx.x * blockDim.x + threadIdx.x;
    if (c >= 512) return;
    float s = 0.f, s2 = 0.f;
    for (int r = 0; r < Gg; r++) { float v = g_z1[r * 512 + c]; s += v; s2 += v * v; }
    float mean = s / (float)Gg;
    float var = fmaxf(s2 / (float)Gg - mean * mean, 0.f);
    float sc = g[c] * rsqrtf(var + EPSB);
    g_sc1[c] = sc; g_sh1[c] = b[c] - mean * sc;
}

__global__ void k_fc2(const float* __restrict__ w, const float* __restrict__ b) {
    int idx = blockIdx.x * blockDim.x + threadIdx.x;
    if (idx >= Gg * 256) return;
    int c = idx & 255, r = idx >> 8;
    float s = b[c];
#pragma unroll 8
    for (int k = 0; k < 512; k++) {
        float v = fmaxf(g_z1[r * 512 + k] * g_sc1[k] + g_sh1[k], 0.f);
        s += v * w[k * 256 + c];
    }
    g_z2[idx] = s;
}

__global__ void k_bn2(const float* __restrict__ g, const float* __restrict__ b) {
    int c = threadIdx.x;
    if (c >= 256) return;
    float s = 0.f, s2 = 0.f;
    for (int r = 0; r < Gg; r++) { float v = g_z2[r * 256 + c]; s += v; s2 += v * v; }
    float mean = s / (float)Gg;
    float var = fmaxf(s2 / (float)Gg - mean * mean, 0.f);
    float sc = g[c] * rsqrtf(var + EPSB);
    g_sc2[c] = sc; g_sh2[c] = b[c] - mean * sc;
}

__global__ void k_fc3(const float* __restrict__ w, const float* __restrict__ b,
                      const float* __restrict__ g3, const float* __restrict__ b3,
                      float* __restrict__ out) {
    __shared__ float red[256];
    __shared__ float z3[64];
    __shared__ float mv[2];
    int t = threadIdx.x;
    int r = t >> 2, p = t & 3;
    float s = 0.f;
    for (int k = p * 64; k < p * 64 + 64; k++) {
        float v = fmaxf(g_z2[r * 256 + k] * g_sc2[k] + g_sh2[k], 0.f);
        s += v * w[k];
    }
    red[t] = s;
    __syncthreads();
    if (p == 0) z3[r] = red[t] + red[t + 1] + red[t + 2] + red[t + 3] + b[0];
    __syncthreads();
    if (t == 0) {
        float m = 0.f;
        for (int i = 0; i < 64; i++) m += z3[i];
        m /= 64.f;
        float v = 0.f;
        for (int i = 0; i < 64; i++) { float d = z3[i] - m; v += d * d; }
        v /= 64.f;
        mv[0] = m; mv[1] = rsqrtf(v + EPSB);
    }
    __syncthreads();
    if (t < 64) out[t] = (z3[t] - mv[0]) * mv[1] * g3[0] + b3[0];
}

// ---------------- launch ----------------
extern "C" void kernel_launch(void* const* d_in, const int* in_sizes, int n_in,
                              void* d_out, int out_size) {
    const float* x        = (const float*)d_in[0];
    const float* gat_w    = (const float*)d_in[1];
    const float* gat_asrc = (const float*)d_in[2];
    const float* gat_adst = (const float*)d_in[3];
    const float* gat_bias = (const float*)d_in[4];
    const float* mlp_w    = (const float*)d_in[5];
    const float* mlp_b    = (const float*)d_in[6];
    const float* bn0_g    = (const float*)d_in[7];
    const float* bn0_b    = (const float*)d_in[8];
    const float* fc1_w    = (const float*)d_in[9];
    const float* fc1_b    = (const float*)d_in[10];
    const float* bn1_g    = (const float*)d_in[11];
    const float* bn1_b    = (const float*)d_in[12];
    const float* fc2_w    = (const float*)d_in[13];
    const float* fc2_b    = (const float*)d_in[14];
    const float* bn2_g    = (const float*)d_in[15];
    const float* bn2_b    = (const float*)d_in[16];
    const float* fc3_w    = (const float*)d_in[17];
    const float* fc3_b    = (const float*)d_in[18];
    const float* bn3_g    = (const float*)d_in[19];
    const float* bn3_b    = (const float*)d_in[20];
    const int*   ei       = (const int*)d_in[21];
    const int*   batch    = (const int*)d_in[22];
    float* out = (float*)d_out;

    // reorder: k_scan is the 4th launch this round (profiling slot)
    k_init<<<(Nn + 255) / 256, 256>>>();
    k_degree<<<(ET + 255) / 256, 256>>>(ei);
    k_gemm<0><<<dim3((Nn + 127) / 128, HC / 128), 256>>>(
        x, gat_w, nullptr, nullptr, gat_asrc, gat_adst, Nn, 448, HC);
    k_scan<<<1, 1024>>>();
    k_edge<<<(ET + 255) / 256, 256>>>(ei);
    k_agg<<<Nn, 256>>>();
    k_gemm<1><<<dim3((Nn + 127) / 128, Cc / 128), 256>>>(
        nullptr, mlp_w, mlp_b, gat_bias, nullptr, nullptr, Nn, HC, Cc);
    k_bn0_stats<<<512, 128>>>();
    k_bn0_final<<<1, 128>>>(bn0_g, bn0_b);
    k_pool<<<200, 128>>>(batch);
    k_fc1<<<(Gg * 512 + 255) / 256, 256>>>(fc1_w, fc1_b);
    k_bn1<<<2, 256>>>(bn1_g, bn1_b);
    k_fc2<<<(Gg * 256 + 255) / 256, 256>>>(fc2_w, fc2_b);
    k_bn2<<<1, 256>>>(bn2_g, bn2_b);
    k_fc3<<<1, 256>>>(fc3_w, fc3_b, bn3_g, bn3_b, out);
}

// round 10
// speedup vs baseline: 1.1179x; 1.1179x over previous
#include <cuda_runtime.h>
#include <math.h>

#define Nn 30000
#define Ee 960000
#define ET (Ee + Nn)
#define Hh 2
#define Cc 128
#define HC 256
#define Gg 64
#define EPSB 1e-5f
#define SB 118   // scan blocks = ceil(Nn/256)

typedef unsigned long long ull;

// ---------------- scratch (device globals; no allocation allowed) ----------------
__device__ float  g_xp[(size_t)Nn * HC];     // x @ gat_w          [N,256]
__device__ float  g_as[Nn * Hh];             // attention src dots [N,2]
__device__ float  g_ad[Nn * Hh];             // attention dst dots [N,2]
__device__ int    g_deg[Nn];                 // in-degree
__device__ int    g_ptr[Nn + 1];             // CSR offsets
__device__ int    g_cur[Nn];                 // scatter cursors
__device__ int    g_blk[SB];                 // per-block degree sums
__device__ int4   g_csre[ET];                // CSR edge: {src, w0, w1, pad}
__device__ float  g_acc[(size_t)Nn * HC];    // normalized aggregation
__device__ float  g_h1[(size_t)Nn * Cc];     // elu(out) @ mlp_w + b
__device__ float  g_bnsum[2 * Cc];
__device__ float  g_sc0[Cc], g_sh0[Cc];
__device__ float  g_hp[Gg * Cc];
__device__ float  g_z1[Gg * 512];
__device__ float  g_sc1[512], g_sh1[512];
__device__ float  g_z2[Gg * 256];
__device__ float  g_sc2[256], g_sh2[256];

// ---------------- f32x2 helpers ----------------
__device__ __forceinline__ ull pk2(float lo, float hi) {
    ull d;
    asm("mov.b64 %0, {%1, %2};" : "=l"(d) : "r"(__float_as_uint(lo)), "r"(__float_as_uint(hi)));
    return d;
}
__device__ __forceinline__ float2 upk(ull v) {
    unsigned lo, hi;
    asm("mov.b64 {%0, %1}, %2;" : "=r"(lo), "=r"(hi) : "l"(v));
    return make_float2(__uint_as_float(lo), __uint_as_float(hi));
}
__device__ __forceinline__ ull fma2(ull a, ull b, ull c) {
    ull d;
    asm("fma.rn.f32x2 %0, %1, %2, %3;" : "=l"(d) : "l"(a), "l"(b), "l"(c));
    return d;
}

// ---------------- init ----------------
__global__ void k_init() {
    int i = blockIdx.x * blockDim.x + threadIdx.x;
    if (i < Nn)      g_deg[i] = 0;
    if (i < Gg * Cc) g_hp[i] = 0.f;
    if (i < 2 * Cc)  g_bnsum[i] = 0.f;
}

// ---------------- f32x2 GEMM: 128x128x32, 256 thr, 8x8/thread, 2 CTAs/SM --------
template <int MODE>
__global__ void __launch_bounds__(256, 2)
k_gemm(const float* __restrict__ Aext, const float* __restrict__ B,
       const float* __restrict__ cbias, const float* __restrict__ abias,
       const float* __restrict__ asrc, const float* __restrict__ adst,
       int M, int K, int Nc) {
    __shared__ float As[32][128];
    __shared__ float Bs[32][128];
    int t = threadIdx.x;
    int tx = t & 15, ty = t >> 4;
    int m0 = blockIdx.x * 128, n0 = blockIdx.y * 128;
    int ar_ = t >> 1, akc = (t & 1) * 16;
    int bkb = t >> 4, bc4 = (t & 15) * 8;
    int steps = K >> 5;
    bool rowok = (m0 + ar_) < M;
    const float* Ab = ((MODE == 0) ? Aext : (const float*)g_acc) + (size_t)(m0 + ar_) * K + akc;
    const float* Bb = B + (size_t)bkb * Nc + n0 + bc4;

    ull acc[4][8];
#pragma unroll
    for (int i = 0; i < 4; i++)
#pragma unroll
        for (int j = 0; j < 8; j++) acc[i][j] = 0ull;

    for (int it = 0; it < steps; it++) {
        int k0 = it << 5;
        float4 va[4];
        float4 vb[4];
#pragma unroll
        for (int q = 0; q < 4; q++) va[q] = make_float4(0.f, 0.f, 0.f, 0.f);
        if (rowok) {
#pragma unroll
            for (int q = 0; q < 4; q++) va[q] = *(const float4*)(Ab + k0 + q * 4);
            if (MODE == 1) {
                int gk = k0 + akc;
#pragma unroll
                for (int q = 0; q < 4; q++) {
                    float f[4] = {va[q].x, va[q].y, va[q].z, va[q].w};
#pragma unroll
                    for (int j = 0; j < 4; j++) {
                        float u = f[j] + __ldg(abias + gk + q * 4 + j);
                        f[j] = u > 0.f ? u : (__expf(u) - 1.f);
                    }
                    va[q] = make_float4(f[0], f[1], f[2], f[3]);
                }
            }
        }
        vb[0] = *(const float4*)(Bb + (size_t)k0 * Nc);
        vb[1] = *(const float4*)(Bb + (size_t)k0 * Nc + 4);
        vb[2] = *(const float4*)(Bb + (size_t)(k0 + 16) * Nc);
        vb[3] = *(const float4*)(Bb + (size_t)(k0 + 16) * Nc + 4);

        __syncthreads();
#pragma unroll
        for (int q = 0; q < 4; q++) {
            As[akc + q * 4 + 0][ar_] = va[q].x;
            As[akc + q * 4 + 1][ar_] = va[q].y;
            As[akc + q * 4 + 2][ar_] = va[q].z;
            As[akc + q * 4 + 3][ar_] = va[q].w;
        }
        *(float4*)&Bs[bkb][bc4]          = vb[0];
        *(float4*)&Bs[bkb][bc4 + 4]      = vb[1];
        *(float4*)&Bs[bkb + 16][bc4]     = vb[2];
        *(float4*)&Bs[bkb + 16][bc4 + 4] = vb[3];
        __syncthreads();

#pragma unroll
        for (int k = 0; k < 32; k++) {
            float4 x0 = *(const float4*)&As[k][ty * 8];
            float4 x1 = *(const float4*)&As[k][ty * 8 + 4];
            float4 y0 = *(const float4*)&Bs[k][tx * 8];
            float4 y1 = *(const float4*)&Bs[k][tx * 8 + 4];
            ull A2[4] = {pk2(x0.x, x0.y), pk2(x0.z, x0.w),
                         pk2(x1.x, x1.y), pk2(x1.z, x1.w)};
            float bb[8] = {y0.x, y0.y, y0.z, y0.w, y1.x, y1.y, y1.z, y1.w};
#pragma unroll
            for (int j = 0; j < 8; j++) {
                ull B2 = pk2(bb[j], bb[j]);
#pragma unroll
                for (int i = 0; i < 4; i++) acc[i][j] = fma2(A2[i], B2, acc[i][j]);
            }
        }
    }

    float* Cp = (MODE == 0) ? g_xp : g_h1;
    float cb[8];
#pragma unroll
    for (int j = 0; j < 8; j++) cb[j] = cbias ? cbias[n0 + tx * 8 + j] : 0.f;

    float sa[8], da[8];
    int h = n0 >> 7;
    if (MODE == 0) {
#pragma unroll
        for (int j = 0; j < 8; j++) {
            sa[j] = asrc[(h << 7) + tx * 8 + j];
            da[j] = adst[(h << 7) + tx * 8 + j];
        }
    }

#pragma unroll
    for (int i = 0; i < 4; i++) {
        float2 p[8];
#pragma unroll
        for (int j = 0; j < 8; j++) p[j] = upk(acc[i][j]);
        int re = m0 + ty * 8 + i * 2;
        int gc = n0 + tx * 8;
        if (re < M) {
            *(float4*)(Cp + (size_t)re * Nc + gc) =
                make_float4(p[0].x + cb[0], p[1].x + cb[1], p[2].x + cb[2], p[3].x + cb[3]);
            *(float4*)(Cp + (size_t)re * Nc + gc + 4) =
                make_float4(p[4].x + cb[4], p[5].x + cb[5], p[6].x + cb[6], p[7].x + cb[7]);
        }
        if (re + 1 < M) {
            *(float4*)(Cp + (size_t)(re + 1) * Nc + gc) =
                make_float4(p[0].y + cb[0], p[1].y + cb[1], p[2].y + cb[2], p[3].y + cb[3]);
            *(float4*)(Cp + (size_t)(re + 1) * Nc + gc + 4) =
                make_float4(p[4].y + cb[4], p[5].y + cb[5], p[6].y + cb[6], p[7].y + cb[7]);
        }
        if (MODE == 0) {
            float s0 = 0.f, d0 = 0.f, s1 = 0.f, d1 = 0.f;
#pragma unroll
            for (int j = 0; j < 8; j++) {
                s0 += p[j].x * sa[j]; d0 += p[j].x * da[j];
                s1 += p[j].y * sa[j]; d1 += p[j].y * da[j];
            }
#pragma unroll
            for (int msk = 1; msk < 16; msk <<= 1) {
                s0 += __shfl_xor_sync(0xFFFFFFFFu, s0, msk);
                d0 += __shfl_xor_sync(0xFFFFFFFFu, d0, msk);
                s1 += __shfl_xor_sync(0xFFFFFFFFu, s1, msk);
                d1 += __shfl_xor_sync(0xFFFFFFFFu, d1, msk);
            }
            if (tx == 0) {
                if (re < M)     { g_as[re * 2 + h] = s0;       g_ad[re * 2 + h] = d0; }
                if (re + 1 < M) { g_as[(re + 1) * 2 + h] = s1; g_ad[(re + 1) * 2 + h] = d1; }
            }
        }
    }
}

// ---------------- degree count ----------------
__global__ void k_degree(const int* __restrict__ ei) {
    int i = blockIdx.x * blockDim.x + threadIdx.x;
    if (i >= ET) return;
    int dst = (i < Ee) ? ei[Ee + i] : (i - Ee);
    atomicAdd(&g_deg[dst], 1);
}

// ---------------- parallel scan, phase A: block-local exclusive scan ------------
__global__ void k_scanA() {
    __shared__ int sh[256];
    int b = blockIdx.x, t = threadIdx.x;
    int i = b * 256 + t;
    int d = (i < Nn) ? g_deg[i] : 0;
    sh[t] = d;
    __syncthreads();
    for (int off = 1; off < 256; off <<= 1) {
        int v = (t >= off) ? sh[t - off] : 0;
        __syncthreads();
        sh[t] += v;
        __syncthreads();
    }
    if (i < Nn) g_ptr[i] = sh[t] - d;   // local exclusive
    if (t == 255) g_blk[b] = sh[255];
}

// ---------------- parallel scan, phase B: add block offsets --------------------
__global__ void k_scanB() {
    __shared__ int sb[128];
    int b = blockIdx.x, t = threadIdx.x;
    if (t < 128) sb[t] = (t < SB) ? g_blk[t] : 0;
    __syncthreads();
    for (int off = 1; off < 128; off <<= 1) {
        int v = 0;
        if (t < 128 && t >= off) v = sb[t - off];
        __syncthreads();
        if (t < 128) sb[t] += v;
        __syncthreads();
    }
    int offb = (b > 0) ? sb[b - 1] : 0;
    int i = b * 256 + t;
    if (i < Nn) {
        int p = g_ptr[i] + offb;
        g_ptr[i] = p;
        g_cur[i] = p;
        if (i == Nn - 1) g_ptr[Nn] = p + g_deg[i];
    }
}

// ---------------- fused edge: logit -> exp -> CSR scatter (packed 16B) ----------
__global__ void k_edge(const int* __restrict__ ei) {
    int i = blockIdx.x * blockDim.x + threadIdx.x;
    if (i >= ET) return;
    int src, dst;
    if (i < Ee) { src = ei[i]; dst = ei[Ee + i]; }
    else        { src = dst = i - Ee; }
    float2 as = *(const float2*)(g_as + src * 2);
    float2 ad = *(const float2*)(g_ad + dst * 2);
    float l0 = as.x + ad.x; l0 = l0 > 0.f ? l0 : 0.2f * l0;
    float l1 = as.y + ad.y; l1 = l1 > 0.f ? l1 : 0.2f * l1;
    float w0 = __expf(l0), w1 = __expf(l1);
    int pos = atomicAdd(&g_cur[dst], 1);
    g_csre[pos] = make_int4(src, __float_as_int(w0), __float_as_int(w1), 0);
}

// ---------------- aggregation: block per dst, smem-staged records, 2-edge ILP ----
__global__ void __launch_bounds__(256) k_agg() {
    __shared__ int4   se[128];
    __shared__ float4 sha[256];
    __shared__ float  shw[256];
    int dst = blockIdx.x;
    int t = threadIdx.x;
    int grp = t >> 6, l = t & 63;
    int beg = g_ptr[dst], end = g_ptr[dst + 1];
    int deg = end - beg;
    bool hi = l >= 32;
    float4 acc0 = make_float4(0.f, 0.f, 0.f, 0.f);
    float4 acc1 = make_float4(0.f, 0.f, 0.f, 0.f);
    float wsum = 0.f;

    for (int base = 0; base < deg; base += 128) {
        int cnt = min(128, deg - base);
        if (t < cnt) se[t] = g_csre[beg + base + t];   // coalesced, once per chunk
        __syncthreads();
        int e = grp;
        for (; e + 4 < cnt; e += 8) {                  // 2 edges in flight per group
            int4 e0 = se[e], e1 = se[e + 4];
            float w0 = hi ? __int_as_float(e0.z) : __int_as_float(e0.y);
            float w1 = hi ? __int_as_float(e1.z) : __int_as_float(e1.y);
            float4 v0 = __ldg((const float4*)(g_xp + (size_t)e0.x * HC) + l);
            float4 v1 = __ldg((const float4*)(g_xp + (size_t)e1.x * HC) + l);
            acc0.x += v0.x * w0; acc0.y += v0.y * w0;
            acc0.z += v0.z * w0; acc0.w += v0.w * w0;
            acc1.x += v1.x * w1; acc1.y += v1.y * w1;
            acc1.z += v1.z * w1; acc1.w += v1.w * w1;
            wsum += w0 + w1;
        }
        if (e < cnt) {
            int4 e0 = se[e];
            float w0 = hi ? __int_as_float(e0.z) : __int_as_float(e0.y);
            float4 v0 = __ldg((const float4*)(g_xp + (size_t)e0.x * HC) + l);
            acc0.x += v0.x * w0; acc0.y += v0.y * w0;
            acc0.z += v0.z * w0; acc0.w += v0.w * w0;
            wsum += w0;
        }
        __syncthreads();
    }
    acc0.x += acc1.x; acc0.y += acc1.y; acc0.z += acc1.z; acc0.w += acc1.w;
    sha[t] = acc0; shw[t] = wsum;
    __syncthreads();
    if (grp == 0) {
        float4 a = sha[t], b = sha[t + 64], c = sha[t + 128], d = sha[t + 192];
        float rd = 1.f / (shw[t] + shw[t + 64] + shw[t + 128] + shw[t + 192]);
        float4 r = make_float4((a.x + b.x + c.x + d.x) * rd,
                               (a.y + b.y + c.y + d.y) * rd,
                               (a.z + b.z + c.z + d.z) * rd,
                               (a.w + b.w + c.w + d.w) * rd);
        *((float4*)(g_acc + (size_t)dst * HC) + l) = r;
    }
}

// ---------------- BN0 stats ----------------
__global__ void k_bn0_stats() {
    int c = threadIdx.x;  // 128
    float s = 0.f, s2 = 0.f;
    for (int n = blockIdx.x; n < Nn; n += gridDim.x) {
        float v = g_h1[(size_t)n * Cc + c];
        s += v; s2 += v * v;
    }
    atomicAdd(&g_bnsum[c], s);
    atomicAdd(&g_bnsum[Cc + c], s2);
}

__global__ void k_bn0_final(const float* __restrict__ g, const float* __restrict__ b) {
    int c = threadIdx.x;
    if (c < Cc) {
        float mean = g_bnsum[c] / (float)Nn;
        float var  = fmaxf(g_bnsum[Cc + c] / (float)Nn - mean * mean, 0.f);
        float sc = g[c] * rsqrtf(var + EPSB);
        g_sc0[c] = sc;
        g_sh0[c] = b[c] - mean * sc;
    }
}

// ---------------- normalize + pool ----------------
__global__ void k_pool(const int* __restrict__ batch) {
    int c = threadIdx.x;  // 128
    int per = (Nn + gridDim.x - 1) / gridDim.x;
    int s = blockIdx.x * per;
    int e = min(Nn, s + per);
    if (s >= e) return;
    float sc = g_sc0[c], sh = g_sh0[c];
    int cur = batch[s];
    float a = 0.f;
    for (int n = s; n < e; n++) {
        int gi = batch[n];
        if (gi != cur) { atomicAdd(&g_hp[cur * Cc + c], a); a = 0.f; cur = gi; }
        a += g_h1[(size_t)n * Cc + c] * sc + sh;
    }
    atomicAdd(&g_hp[cur * Cc + c], a);
}

// ---------------- FC stack ----------------
__global__ void k_fc1(const float* __restrict__ w, const float* __restrict__ b) {
    int idx = blockIdx.x * blockDim.x + threadIdx.x;
    if (idx >= Gg * 512) return;
    int c = idx & 511, r = idx >> 9;
    float s = b[c];
#pragma unroll 8
    for (int k = 0; k < Cc; k++) s += g_hp[r * Cc + k] * w[k * 512 + c];
    g_z1[idx] = s;
}

__global__ void k_bn1(const float* __restrict__ g, const float* __restrict__ b) {
    int c = blockIdx.x * blockDim.x + threadIdx.x;
    if (c >= 512) return;
    float s = 0.f, s2 = 0.f;
    for (int r = 0; r < Gg; r++) { float v = g_z1[r * 512 + c]; s += v; s2 += v * v; }
    float mean = s / (float)Gg;
    float var = fmaxf(s2 / (float)Gg - mean * mean, 0.f);
    float sc = g[c] * rsqrtf(var + EPSB);
    g_sc1[c] = sc; g_sh1[c] = b[c] - mean * sc;
}

__global__ void k_fc2(const float* __restrict__ w, const float* __restrict__ b) {
    int idx = blockIdx.x * blockDim.x + threadIdx.x;
    if (idx >= Gg * 256) return;
    int c = idx & 255, r = idx >> 8;
    float s = b[c];
#pragma unroll 8
    for (int k = 0; k < 512; k++) {
        float v = fmaxf(g_z1[r * 512 + k] * g_sc1[k] + g_sh1[k], 0.f);
        s += v * w[k * 256 + c];
    }
    g_z2[idx] = s;
}

__global__ void k_bn2(const float* __restrict__ g, const float* __restrict__ b) {
    int c = threadIdx.x;
    if (c >= 256) return;
    float s = 0.f, s2 = 0.f;
    for (int r = 0; r < Gg; r++) { float v = g_z2[r * 256 + c]; s += v; s2 += v * v; }
    float mean = s / (float)Gg;
    float var = fmaxf(s2 / (float)Gg - mean * mean, 0.f);
    float sc = g[c] * rsqrtf(var + EPSB);
    g_sc2[c] = sc; g_sh2[c] = b[c] - mean * sc;
}

__global__ void k_fc3(const float* __restrict__ w, const float* __restrict__ b,
                      const float* __restrict__ g3, const float* __restrict__ b3,
                      float* __restrict__ out) {
    __shared__ float red[256];
    __shared__ float z3[64];
    __shared__ float mv[2];
    int t = threadIdx.x;
    int r = t >> 2, p = t & 3;
    float s = 0.f;
    for (int k = p * 64; k < p * 64 + 64; k++) {
        float v = fmaxf(g_z2[r * 256 + k] * g_sc2[k] + g_sh2[k], 0.f);
        s += v * w[k];
    }
    red[t] = s;
    __syncthreads();
    if (p == 0) z3[r] = red[t] + red[t + 1] + red[t + 2] + red[t + 3] + b[0];
    __syncthreads();
    if (t == 0) {
        float m = 0.f;
        for (int i = 0; i < 64; i++) m += z3[i];
        m /= 64.f;
        float v = 0.f;
        for (int i = 0; i < 64; i++) { float d = z3[i] - m; v += d * d; }
        v /= 64.f;
        mv[0] = m; mv[1] = rsqrtf(v + EPSB);
    }
    __syncthreads();
    if (t < 64) out[t] = (z3[t] - mv[0]) * mv[1] * g3[0] + b3[0];
}

// ---------------- launch ----------------
extern "C" void kernel_launch(void* const* d_in, const int* in_sizes, int n_in,
                              void* d_out, int out_size) {
    const float* x        = (const float*)d_in[0];
    const float* gat_w    = (const float*)d_in[1];
    const float* gat_asrc = (const float*)d_in[2];
    const float* gat_adst = (const float*)d_in[3];
    const float* gat_bias = (const float*)d_in[4];
    const float* mlp_w    = (const float*)d_in[5];
    const float* mlp_b    = (const float*)d_in[6];
    const float* bn0_g    = (const float*)d_in[7];
    const float* bn0_b    = (const float*)d_in[8];
    const float* fc1_w    = (const float*)d_in[9];
    const float* fc1_b    = (const float*)d_in[10];
    const float* bn1_g    = (const float*)d_in[11];
    const float* bn1_b    = (const float*)d_in[12];
    const float* fc2_w    = (const float*)d_in[13];
    const float* fc2_b    = (const float*)d_in[14];
    const float* bn2_g    = (const float*)d_in[15];
    const float* bn2_b    = (const float*)d_in[16];
    const float* fc3_w    = (const float*)d_in[17];
    const float* fc3_b    = (const float*)d_in[18];
    const float* bn3_g    = (const float*)d_in[19];
    const float* bn3_b    = (const float*)d_in[20];
    const int*   ei       = (const int*)d_in[21];
    const int*   batch    = (const int*)d_in[22];
    float* out = (float*)d_out;

    // gemm0 is the 4th launch (profile slot)
    k_init<<<(Nn + 255) / 256, 256>>>();
    k_degree<<<(ET + 255) / 256, 256>>>(ei);
    k_scanA<<<SB, 256>>>();
    k_gemm<0><<<dim3((Nn + 127) / 128, HC / 128), 256>>>(
        x, gat_w, nullptr, nullptr, gat_asrc, gat_adst, Nn, 448, HC);
    k_scanB<<<SB, 256>>>();
    k_edge<<<(ET + 255) / 256, 256>>>(ei);
    k_agg<<<Nn, 256>>>();
    k_gemm<1><<<dim3((Nn + 127) / 128, Cc / 128), 256>>>(
        nullptr, mlp_w, mlp_b, gat_bias, nullptr, nullptr, Nn, HC, Cc);
    k_bn0_stats<<<512, 128>>>();
    k_bn0_final<<<1, 128>>>(bn0_g, bn0_b);
    k_pool<<<200, 128>>>(batch);
    k_fc1<<<(Gg * 512 + 255) / 256, 256>>>(fc1_w, fc1_b);
    k_bn1<<<2, 256>>>(bn1_g, bn1_b);
    k_fc2<<<(Gg * 256 + 255) / 256, 256>>>(fc2_w, fc2_b);
    k_bn2<<<1, 256>>>(bn2_g, bn2_b);
    k_fc3<<<1, 256>>>(fc3_w, fc3_b, bn3_g, bn3_b, out);
}

// round 11
// speedup vs baseline: 1.1398x; 1.0196x over previous
#include <cuda_runtime.h>
#include <math.h>

#define Nn 30000
#define Ee 960000
#define ET (Ee + Nn)
#define Hh 2
#define Cc 128
#define HC 256
#define Gg 64
#define EPSB 1e-5f
#define SB 118   // scan blocks = ceil(Nn/256)

typedef unsigned long long ull;

// ---------------- scratch (device globals; no allocation allowed) ----------------
__device__ float  g_xp[(size_t)Nn * HC];     // x @ gat_w          [N,256]
__device__ float  g_as[Nn * Hh];             // attention src dots [N,2]
__device__ float  g_ad[Nn * Hh];             // attention dst dots [N,2]
__device__ int    g_deg[Nn];                 // in-degree
__device__ int    g_ptr[Nn + 1];             // CSR offsets
__device__ int    g_cur[Nn];                 // scatter cursors
__device__ int    g_blk[SB];                 // per-block degree sums
__device__ int4   g_csre[ET];                // CSR edge: {src, w0, w1, pad}
__device__ float  g_acc[(size_t)Nn * HC];    // normalized aggregation
__device__ float  g_h1[(size_t)Nn * Cc];     // elu(out) @ mlp_w + b
__device__ float  g_bnsum[2 * Cc];
__device__ float  g_sc0[Cc], g_sh0[Cc];
__device__ float  g_hp[Gg * Cc];
__device__ float  g_z1[Gg * 512];
__device__ float  g_sc1[512], g_sh1[512];
__device__ float  g_z2[Gg * 256];
__device__ float  g_sc2[256], g_sh2[256];

// ---------------- f32x2 helpers ----------------
__device__ __forceinline__ ull pk2(float lo, float hi) {
    ull d;
    asm("mov.b64 %0, {%1, %2};" : "=l"(d) : "r"(__float_as_uint(lo)), "r"(__float_as_uint(hi)));
    return d;
}
__device__ __forceinline__ float2 upk(ull v) {
    unsigned lo, hi;
    asm("mov.b64 {%0, %1}, %2;" : "=r"(lo), "=r"(hi) : "l"(v));
    return make_float2(__uint_as_float(lo), __uint_as_float(hi));
}
__device__ __forceinline__ ull fma2(ull a, ull b, ull c) {
    ull d;
    asm("fma.rn.f32x2 %0, %1, %2, %3;" : "=l"(d) : "l"(a), "l"(b), "l"(c));
    return d;
}

// ---------------- init ----------------
__global__ void k_init() {
    int i = blockIdx.x * blockDim.x + threadIdx.x;
    if (i < Nn)      g_deg[i] = 0;
    if (i < Gg * Cc) g_hp[i] = 0.f;
    if (i < 2 * Cc)  g_bnsum[i] = 0.f;
}

// ---------------- f32x2 GEMM: 128x128x32, 256 thr, 8x8/thread, 2 CTAs/SM --------
template <int MODE>
__global__ void __launch_bounds__(256, 2)
k_gemm(const float* __restrict__ Aext, const float* __restrict__ B,
       const float* __restrict__ cbias, const float* __restrict__ abias,
       const float* __restrict__ asrc, const float* __restrict__ adst,
       int M, int K, int Nc) {
    __shared__ float As[32][128];
    __shared__ float Bs[32][128];
    int t = threadIdx.x;
    int tx = t & 15, ty = t >> 4;
    int m0 = blockIdx.x * 128, n0 = blockIdx.y * 128;
    int ar_ = t >> 1, akc = (t & 1) * 16;
    int bkb = t >> 4, bc4 = (t & 15) * 8;
    int steps = K >> 5;
    bool rowok = (m0 + ar_) < M;
    const float* Ab = ((MODE == 0) ? Aext : (const float*)g_acc) + (size_t)(m0 + ar_) * K + akc;
    const float* Bb = B + (size_t)bkb * Nc + n0 + bc4;

    ull acc[4][8];
#pragma unroll
    for (int i = 0; i < 4; i++)
#pragma unroll
        for (int j = 0; j < 8; j++) acc[i][j] = 0ull;

    for (int it = 0; it < steps; it++) {
        int k0 = it << 5;
        float4 va[4];
        float4 vb[4];
#pragma unroll
        for (int q = 0; q < 4; q++) va[q] = make_float4(0.f, 0.f, 0.f, 0.f);
        if (rowok) {
#pragma unroll
            for (int q = 0; q < 4; q++) va[q] = *(const float4*)(Ab + k0 + q * 4);
            if (MODE == 1) {
                int gk = k0 + akc;
#pragma unroll
                for (int q = 0; q < 4; q++) {
                    float f[4] = {va[q].x, va[q].y, va[q].z, va[q].w};
#pragma unroll
                    for (int j = 0; j < 4; j++) {
                        float u = f[j] + __ldg(abias + gk + q * 4 + j);
                        f[j] = u > 0.f ? u : (__expf(u) - 1.f);
                    }
                    va[q] = make_float4(f[0], f[1], f[2], f[3]);
                }
            }
        }
        vb[0] = *(const float4*)(Bb + (size_t)k0 * Nc);
        vb[1] = *(const float4*)(Bb + (size_t)k0 * Nc + 4);
        vb[2] = *(const float4*)(Bb + (size_t)(k0 + 16) * Nc);
        vb[3] = *(const float4*)(Bb + (size_t)(k0 + 16) * Nc + 4);

        __syncthreads();
#pragma unroll
        for (int q = 0; q < 4; q++) {
            As[akc + q * 4 + 0][ar_] = va[q].x;
            As[akc + q * 4 + 1][ar_] = va[q].y;
            As[akc + q * 4 + 2][ar_] = va[q].z;
            As[akc + q * 4 + 3][ar_] = va[q].w;
        }
        *(float4*)&Bs[bkb][bc4]          = vb[0];
        *(float4*)&Bs[bkb][bc4 + 4]      = vb[1];
        *(float4*)&Bs[bkb + 16][bc4]     = vb[2];
        *(float4*)&Bs[bkb + 16][bc4 + 4] = vb[3];
        __syncthreads();

#pragma unroll
        for (int k = 0; k < 32; k++) {
            float4 x0 = *(const float4*)&As[k][ty * 8];
            float4 x1 = *(const float4*)&As[k][ty * 8 + 4];
            float4 y0 = *(const float4*)&Bs[k][tx * 8];
            float4 y1 = *(const float4*)&Bs[k][tx * 8 + 4];
            ull A2[4] = {pk2(x0.x, x0.y), pk2(x0.z, x0.w),
                         pk2(x1.x, x1.y), pk2(x1.z, x1.w)};
            float bb[8] = {y0.x, y0.y, y0.z, y0.w, y1.x, y1.y, y1.z, y1.w};
#pragma unroll
            for (int j = 0; j < 8; j++) {
                ull B2 = pk2(bb[j], bb[j]);
#pragma unroll
                for (int i = 0; i < 4; i++) acc[i][j] = fma2(A2[i], B2, acc[i][j]);
            }
        }
    }

    float* Cp = (MODE == 0) ? g_xp : g_h1;
    float cb[8];
#pragma unroll
    for (int j = 0; j < 8; j++) cb[j] = cbias ? cbias[n0 + tx * 8 + j] : 0.f;

    float sa[8], da[8];
    int h = n0 >> 7;
    if (MODE == 0) {
#pragma unroll
        for (int j = 0; j < 8; j++) {
            sa[j] = asrc[(h << 7) + tx * 8 + j];
            da[j] = adst[(h << 7) + tx * 8 + j];
        }
    }

#pragma unroll
    for (int i = 0; i < 4; i++) {
        float2 p[8];
#pragma unroll
        for (int j = 0; j < 8; j++) p[j] = upk(acc[i][j]);
        int re = m0 + ty * 8 + i * 2;
        int gc = n0 + tx * 8;
        if (re < M) {
            *(float4*)(Cp + (size_t)re * Nc + gc) =
                make_float4(p[0].x + cb[0], p[1].x + cb[1], p[2].x + cb[2], p[3].x + cb[3]);
            *(float4*)(Cp + (size_t)re * Nc + gc + 4) =
                make_float4(p[4].x + cb[4], p[5].x + cb[5], p[6].x + cb[6], p[7].x + cb[7]);
        }
        if (re + 1 < M) {
            *(float4*)(Cp + (size_t)(re + 1) * Nc + gc) =
                make_float4(p[0].y + cb[0], p[1].y + cb[1], p[2].y + cb[2], p[3].y + cb[3]);
            *(float4*)(Cp + (size_t)(re + 1) * Nc + gc + 4) =
                make_float4(p[4].y + cb[4], p[5].y + cb[5], p[6].y + cb[6], p[7].y + cb[7]);
        }
        if (MODE == 0) {
            float s0 = 0.f, d0 = 0.f, s1 = 0.f, d1 = 0.f;
#pragma unroll
            for (int j = 0; j < 8; j++) {
                s0 += p[j].x * sa[j]; d0 += p[j].x * da[j];
                s1 += p[j].y * sa[j]; d1 += p[j].y * da[j];
            }
#pragma unroll
            for (int msk = 1; msk < 16; msk <<= 1) {
                s0 += __shfl_xor_sync(0xFFFFFFFFu, s0, msk);
                d0 += __shfl_xor_sync(0xFFFFFFFFu, d0, msk);
                s1 += __shfl_xor_sync(0xFFFFFFFFu, s1, msk);
                d1 += __shfl_xor_sync(0xFFFFFFFFu, d1, msk);
            }
            if (tx == 0) {
                if (re < M)     { g_as[re * 2 + h] = s0;       g_ad[re * 2 + h] = d0; }
                if (re + 1 < M) { g_as[(re + 1) * 2 + h] = s1; g_ad[(re + 1) * 2 + h] = d1; }
            }
        }
    }
}

// ---------------- degree count ----------------
__global__ void k_degree(const int* __restrict__ ei) {
    int i = blockIdx.x * blockDim.x + threadIdx.x;
    if (i >= ET) return;
    int dst = (i < Ee) ? ei[Ee + i] : (i - Ee);
    atomicAdd(&g_deg[dst], 1);
}

// ---------------- parallel scan, phase A ----------------
__global__ void k_scanA() {
    __shared__ int sh[256];
    int b = blockIdx.x, t = threadIdx.x;
    int i = b * 256 + t;
    int d = (i < Nn) ? g_deg[i] : 0;
    sh[t] = d;
    __syncthreads();
    for (int off = 1; off < 256; off <<= 1) {
        int v = (t >= off) ? sh[t - off] : 0;
        __syncthreads();
        sh[t] += v;
        __syncthreads();
    }
    if (i < Nn) g_ptr[i] = sh[t] - d;
    if (t == 255) g_blk[b] = sh[255];
}

// ---------------- parallel scan, phase B ----------------
__global__ void k_scanB() {
    __shared__ int sb[128];
    int b = blockIdx.x, t = threadIdx.x;
    if (t < 128) sb[t] = (t < SB) ? g_blk[t] : 0;
    __syncthreads();
    for (int off = 1; off < 128; off <<= 1) {
        int v = 0;
        if (t < 128 && t >= off) v = sb[t - off];
        __syncthreads();
        if (t < 128) sb[t] += v;
        __syncthreads();
    }
    int offb = (b > 0) ? sb[b - 1] : 0;
    int i = b * 256 + t;
    if (i < Nn) {
        int p = g_ptr[i] + offb;
        g_ptr[i] = p;
        g_cur[i] = p;
        if (i == Nn - 1) g_ptr[Nn] = p + g_deg[i];
    }
}

// ---------------- fused edge: logit -> exp -> CSR scatter (packed 16B) ----------
__global__ void k_edge(const int* __restrict__ ei) {
    int i = blockIdx.x * blockDim.x + threadIdx.x;
    if (i >= ET) return;
    int src, dst;
    if (i < Ee) { src = ei[i]; dst = ei[Ee + i]; }
    else        { src = dst = i - Ee; }
    float2 as = *(const float2*)(g_as + src * 2);
    float2 ad = *(const float2*)(g_ad + dst * 2);
    float l0 = as.x + ad.x; l0 = l0 > 0.f ? l0 : 0.2f * l0;
    float l1 = as.y + ad.y; l1 = l1 > 0.f ? l1 : 0.2f * l1;
    float w0 = __expf(l0), w1 = __expf(l1);
    int pos = atomicAdd(&g_cur[dst], 1);
    g_csre[pos] = make_int4(src, __float_as_int(w0), __float_as_int(w1), 0);
}

// ---------------- aggregation: ONE WARP per dst, lane-local normalize -----------
// Lane l owns float4 slices l (head 0) and l+32 (head 1) of the 256-float row.
// Denominator needs no reduction: every lane accumulates the identical per-head
// sum of weights. No smem, no __syncthreads.
__global__ void __launch_bounds__(256) k_agg() {
    int w = (blockIdx.x * blockDim.x + threadIdx.x) >> 5;   // warp id == dst
    int lane = threadIdx.x & 31;
    if (w >= Nn) return;
    int beg = g_ptr[w], end = g_ptr[w + 1];
    const float4* xp4 = (const float4*)g_xp;

    float4 acc0 = make_float4(0.f, 0.f, 0.f, 0.f);   // head 0 slice
    float4 acc1 = make_float4(0.f, 0.f, 0.f, 0.f);   // head 1 slice
    float ws0 = 0.f, ws1 = 0.f;

    int e = beg;
    for (; e + 1 < end; e += 2) {                    // 2 edges in flight
        int4 r0 = __ldg(&g_csre[e]);
        int4 r1 = __ldg(&g_csre[e + 1]);
        const float4* p0 = xp4 + (size_t)r0.x * 64;
        const float4* p1 = xp4 + (size_t)r1.x * 64;
        float4 a0 = __ldg(p0 + lane);
        float4 b0 = __ldg(p0 + lane + 32);
        float4 a1 = __ldg(p1 + lane);
        float4 b1 = __ldg(p1 + lane + 32);
        float w00 = __int_as_float(r0.y), w01 = __int_as_float(r0.z);
        float w10 = __int_as_float(r1.y), w11 = __int_as_float(r1.z);
        acc0.x += a0.x * w00 + a1.x * w10; acc0.y += a0.y * w00 + a1.y * w10;
        acc0.z += a0.z * w00 + a1.z * w10; acc0.w += a0.w * w00 + a1.w * w10;
        acc1.x += b0.x * w01 + b1.x * w11; acc1.y += b0.y * w01 + b1.y * w11;
        acc1.z += b0.z * w01 + b1.z * w11; acc1.w += b0.w * w01 + b1.w * w11;
        ws0 += w00 + w10; ws1 += w01 + w11;
    }
    if (e < end) {
        int4 r0 = __ldg(&g_csre[e]);
        const float4* p0 = xp4 + (size_t)r0.x * 64;
        float4 a0 = __ldg(p0 + lane);
        float4 b0 = __ldg(p0 + lane + 32);
        float w00 = __int_as_float(r0.y), w01 = __int_as_float(r0.z);
        acc0.x += a0.x * w00; acc0.y += a0.y * w00;
        acc0.z += a0.z * w00; acc0.w += a0.w * w00;
        acc1.x += b0.x * w01; acc1.y += b0.y * w01;
        acc1.z += b0.z * w01; acc1.w += b0.w * w01;
        ws0 += w00; ws1 += w01;
    }
    float rd0 = 1.f / ws0, rd1 = 1.f / ws1;
    float4* op = (float4*)(g_acc + (size_t)w * HC);
    op[lane]      = make_float4(acc0.x * rd0, acc0.y * rd0, acc0.z * rd0, acc0.w * rd0);
    op[lane + 32] = make_float4(acc1.x * rd1, acc1.y * rd1, acc1.z * rd1, acc1.w * rd1);
}

// ---------------- BN0 stats ----------------
__global__ void k_bn0_stats() {
    int c = threadIdx.x;  // 128
    float s = 0.f, s2 = 0.f;
    for (int n = blockIdx.x; n < Nn; n += gridDim.x) {
        float v = g_h1[(size_t)n * Cc + c];
        s += v; s2 += v * v;
    }
    atomicAdd(&g_bnsum[c], s);
    atomicAdd(&g_bnsum[Cc + c], s2);
}

__global__ void k_bn0_final(const float* __restrict__ g, const float* __restrict__ b) {
    int c = threadIdx.x;
    if (c < Cc) {
        float mean = g_bnsum[c] / (float)Nn;
        float var  = fmaxf(g_bnsum[Cc + c] / (float)Nn - mean * mean, 0.f);
        float sc = g[c] * rsqrtf(var + EPSB);
        g_sc0[c] = sc;
        g_sh0[c] = b[c] - mean * sc;
    }
}

// ---------------- normalize + pool ----------------
__global__ void k_pool(const int* __restrict__ batch) {
    int c = threadIdx.x;  // 128
    int per = (Nn + gridDim.x - 1) / gridDim.x;
    int s = blockIdx.x * per;
    int e = min(Nn, s + per);
    if (s >= e) return;
    float sc = g_sc0[c], sh = g_sh0[c];
    int cur = batch[s];
    float a = 0.f;
    for (int n = s; n < e; n++) {
        int gi = batch[n];
        if (gi != cur) { atomicAdd(&g_hp[cur * Cc + c], a); a = 0.f; cur = gi; }
        a += g_h1[(size_t)n * Cc + c] * sc + sh;
    }
    atomicAdd(&g_hp[cur * Cc + c], a);
}

// ---------------- FC stack ----------------
__global__ void k_fc1(const float* __restrict__ w, const float* __restrict__ b) {
    int idx = blockIdx.x * blockDim.x + threadIdx.x;
    if (idx >= Gg * 512) return;
    int c = idx & 511, r = idx >> 9;
    float s = b[c];
#pragma unroll 8
    for (int k = 0; k < Cc; k++) s += g_hp[r * Cc + k] * w[k * 512 + c];
    g_z1[idx] = s;
}

__global__ void k_bn1(const float* __restrict__ g, const float* __restrict__ b) {
    int c = blockIdx.x * blockDim.x + threadIdx.x;
    if (c >= 512) return;
    float s = 0.f, s2 = 0.f;
    for (int r = 0; r < Gg; r++) { float v = g_z1[r * 512 + c]; s += v; s2 += v * v; }
    float mean = s / (float)Gg;
    float var = fmaxf(s2 / (float)Gg - mean * mean, 0.f);
    float sc = g[c] * rsqrtf(var + EPSB);
    g_sc1[c] = sc; g_sh1[c] = b[c] - mean * sc;
}

__global__ void k_fc2(const float* __restrict__ w, const float* __restrict__ b) {
    int idx = blockIdx.x * blockDim.x + threadIdx.x;
    if (idx >= Gg * 256) return;
    int c = idx & 255, r = idx >> 8;
    float s = b[c];
#pragma unroll 8
    for (int k = 0; k < 512; k++) {
        float v = fmaxf(g_z1[r * 512 + k] * g_sc1[k] + g_sh1[k], 0.f);
        s += v * w[k * 256 + c];
    }
    g_z2[idx] = s;
}

__global__ void k_bn2(const float* __restrict__ g, const float* __restrict__ b) {
    int c = threadIdx.x;
    if (c >= 256) return;
    float s = 0.f, s2 = 0.f;
    for (int r = 0; r < Gg; r++) { float v = g_z2[r * 256 + c]; s += v; s2 += v * v; }
    float mean = s / (float)Gg;
    float var = fmaxf(s2 / (float)Gg - mean * mean, 0.f);
    float sc = g[c] * rsqrtf(var + EPSB);
    g_sc2[c] = sc; g_sh2[c] = b[c] - mean * sc;
}

__global__ void k_fc3(const float* __restrict__ w, const float* __restrict__ b,
                      const float* __restrict__ g3, const float* __restrict__ b3,
                      float* __restrict__ out) {
    __shared__ float red[256];
    __shared__ float z3[64];
    __shared__ float mv[2];
    int t = threadIdx.x;
    int r = t >> 2, p = t & 3;
    float s = 0.f;
    for (int k = p * 64; k < p * 64 + 64; k++) {
        float v = fmaxf(g_z2[r * 256 + k] * g_sc2[k] + g_sh2[k], 0.f);
        s += v * w[k];
    }
    red[t] = s;
    __syncthreads();
    if (p == 0) z3[r] = red[t] + red[t + 1] + red[t + 2] + red[t + 3] + b[0];
    __syncthreads();
    if (t == 0) {
        float m = 0.f;
        for (int i = 0; i < 64; i++) m += z3[i];
        m /= 64.f;
        float v = 0.f;
        for (int i = 0; i < 64; i++) { float d = z3[i] - m; v += d * d; }
        v /= 64.f;
        mv[0] = m; mv[1] = rsqrtf(v + EPSB);
    }
    __syncthreads();
    if (t < 64) out[t] = (z3[t] - mv[0]) * mv[1] * g3[0] + b3[0];
}

// ---------------- launch ----------------
extern "C" void kernel_launch(void* const* d_in, const int* in_sizes, int n_in,
                              void* d_out, int out_size) {
    const float* x        = (const float*)d_in[0];
    const float* gat_w    = (const float*)d_in[1];
    const float* gat_asrc = (const float*)d_in[2];
    const float* gat_adst = (const float*)d_in[3];
    const float* gat_bias = (const float*)d_in[4];
    const float* mlp_w    = (const float*)d_in[5];
    const float* mlp_b    = (const float*)d_in[6];
    const float* bn0_g    = (const float*)d_in[7];
    const float* bn0_b    = (const float*)d_in[8];
    const float* fc1_w    = (const float*)d_in[9];
    const float* fc1_b    = (const float*)d_in[10];
    const float* bn1_g    = (const float*)d_in[11];
    const float* bn1_b    = (const float*)d_in[12];
    const float* fc2_w    = (const float*)d_in[13];
    const float* fc2_b    = (const float*)d_in[14];
    const float* bn2_g    = (const float*)d_in[15];
    const float* bn2_b    = (const float*)d_in[16];
    const float* fc3_w    = (const float*)d_in[17];
    const float* fc3_b    = (const float*)d_in[18];
    const float* bn3_g    = (const float*)d_in[19];
    const float* bn3_b    = (const float*)d_in[20];
    const int*   ei       = (const int*)d_in[21];
    const int*   batch    = (const int*)d_in[22];
    float* out = (float*)d_out;

    // gemm0 is the 4th launch (profile slot)
    k_init<<<(Nn + 255) / 256, 256>>>();
    k_degree<<<(ET + 255) / 256, 256>>>(ei);
    k_scanA<<<SB, 256>>>();
    k_gemm<0><<<dim3((Nn + 127) / 128, HC / 128), 256>>>(
        x, gat_w, nullptr, nullptr, gat_asrc, gat_adst, Nn, 448, HC);
    k_scanB<<<SB, 256>>>();
    k_edge<<<(ET + 255) / 256, 256>>>(ei);
    k_agg<<<(Nn * 32 + 255) / 256, 256>>>();
    k_gemm<1><<<dim3((Nn + 127) / 128, Cc / 128), 256>>>(
        nullptr, mlp_w, mlp_b, gat_bias, nullptr, nullptr, Nn, HC, Cc);
    k_bn0_stats<<<512, 128>>>();
    k_bn0_final<<<1, 128>>>(bn0_g, bn0_b);
    k_pool<<<200, 128>>>(batch);
    k_fc1<<<(Gg * 512 + 255) / 256, 256>>>(fc1_w, fc1_b);
    k_bn1<<<2, 256>>>(bn1_g, bn1_b);
    k_fc2<<<(Gg * 256 + 255) / 256, 256>>>(fc2_w, fc2_b);
    k_bn2<<<1, 256>>>(bn2_g, bn2_b);
    k_fc3<<<1, 256>>>(fc3_w, fc3_b, bn3_g, bn3_b, out);
}

// round 12
// speedup vs baseline: 1.2036x; 1.0560x over previous
#include <cuda_runtime.h>
#include <math.h>

#define Nn 30000
#define Ee 960000
#define ET (Ee + Nn)
#define Hh 2
#define Cc 128
#define HC 256
#define Gg 64
#define EPSB 1e-5f
#define SB 118   // scan blocks = ceil(Nn/256)

typedef unsigned long long ull;

// ---------------- scratch (device globals; no allocation allowed) ----------------
__device__ float  g_xp[(size_t)Nn * HC];     // x @ gat_w          [N,256]
__device__ float  g_as[Nn * Hh];             // attention src dots [N,2]
__device__ float  g_ad[Nn * Hh];             // attention dst dots [N,2]
__device__ int    g_deg[Nn];                 // in-degree
__device__ int    g_ptr[Nn + 1];             // CSR offsets
__device__ int    g_cur[Nn];                 // scatter cursors
__device__ int    g_blk[SB];                 // per-block degree sums
__device__ int4   g_csre[ET];                // CSR edge: {src, w0, w1, pad}
__device__ float  g_acc[(size_t)Nn * HC];    // normalized aggregation
__device__ float  g_h1[(size_t)Nn * Cc];     // elu(out) @ mlp_w + b  (raw, pre-BN)
__device__ float  g_bnsum[2 * Cc];
__device__ float  g_sc0[Cc], g_sh0[Cc];
__device__ int    g_gcnt[Gg];                // nodes per graph
__device__ float  g_hp[Gg * Cc];             // pooled (raw then fixed)
__device__ float  g_z1[Gg * 512];
__device__ float  g_sc1[512], g_sh1[512];
__device__ float  g_z2[Gg * 256];
__device__ float  g_sc2[256], g_sh2[256];

// ---------------- f32x2 helpers ----------------
__device__ __forceinline__ ull pk2(float lo, float hi) {
    ull d;
    asm("mov.b64 %0, {%1, %2};" : "=l"(d) : "r"(__float_as_uint(lo)), "r"(__float_as_uint(hi)));
    return d;
}
__device__ __forceinline__ float2 upk(ull v) {
    unsigned lo, hi;
    asm("mov.b64 {%0, %1}, %2;" : "=r"(lo), "=r"(hi) : "l"(v));
    return make_float2(__uint_as_float(lo), __uint_as_float(hi));
}
__device__ __forceinline__ ull fma2(ull a, ull b, ull c) {
    ull d;
    asm("fma.rn.f32x2 %0, %1, %2, %3;" : "=l"(d) : "l"(a), "l"(b), "l"(c));
    return d;
}

// ---------------- init ----------------
__global__ void k_init() {
    int i = blockIdx.x * blockDim.x + threadIdx.x;
    if (i < Nn)      g_deg[i] = 0;
    if (i < Gg * Cc) g_hp[i] = 0.f;
    if (i < 2 * Cc)  g_bnsum[i] = 0.f;
    if (i < Gg)      g_gcnt[i] = 0;
}

// ---------------- f32x2 GEMM: 128x128x32, 256 thr, 8x8/thread, 2 CTAs/SM --------
// Warp maps 4x8 lanes over a 32Mx64N warp tile (LDS: 384B/warp-k vs 576B before).
// MODE 0: C(g_xp) = Aext @ B;  epilogue also writes attention dots g_as/g_ad
// MODE 1: C(g_h1) = elu(g_acc + abias) @ B + cbias
template <int MODE>
__global__ void __launch_bounds__(256, 2)
k_gemm(const float* __restrict__ Aext, const float* __restrict__ B,
       const float* __restrict__ cbias, const float* __restrict__ abias,
       const float* __restrict__ asrc, const float* __restrict__ adst,
       int M, int K, int Nc) {
    __shared__ float As[32][128];
    __shared__ float Bs[32][128];
    __shared__ float srs[2][128];   // MODE0: per-wn partial src dots
    __shared__ float srd[2][128];   // MODE0: per-wn partial dst dots
    int t = threadIdx.x;
    int lane = t & 31, w = t >> 5;
    int wm = w & 3, wn = w >> 2;            // 4 warps along M, 2 along N
    int lm = lane >> 3, ln = lane & 7;      // 4x8 lanes
    int rbase = wm * 32 + lm * 8;           // thread rows rbase..rbase+7
    int cbase = wn * 64 + ln * 8;           // thread cols cbase..cbase+7
    int m0 = blockIdx.x * 128, n0 = blockIdx.y * 128;
    int ar_ = t >> 1, akc = (t & 1) * 16;
    int bkb = t >> 4, bc4 = (t & 15) * 8;
    int steps = K >> 5;
    bool rowok = (m0 + ar_) < M;
    const float* Ab = ((MODE == 0) ? Aext : (const float*)g_acc) + (size_t)(m0 + ar_) * K + akc;
    const float* Bb = B + (size_t)bkb * Nc + n0 + bc4;

    ull acc[4][8];
#pragma unroll
    for (int i = 0; i < 4; i++)
#pragma unroll
        for (int j = 0; j < 8; j++) acc[i][j] = 0ull;

    for (int it = 0; it < steps; it++) {
        int k0 = it << 5;
        float4 va[4];
        float4 vb[4];
#pragma unroll
        for (int q = 0; q < 4; q++) va[q] = make_float4(0.f, 0.f, 0.f, 0.f);
        if (rowok) {
#pragma unroll
            for (int q = 0; q < 4; q++) va[q] = *(const float4*)(Ab + k0 + q * 4);
            if (MODE == 1) {
                int gk = k0 + akc;
#pragma unroll
                for (int q = 0; q < 4; q++) {
                    float f[4] = {va[q].x, va[q].y, va[q].z, va[q].w};
#pragma unroll
                    for (int j = 0; j < 4; j++) {
                        float u = f[j] + __ldg(abias + gk + q * 4 + j);
                        f[j] = u > 0.f ? u : (__expf(u) - 1.f);
                    }
                    va[q] = make_float4(f[0], f[1], f[2], f[3]);
                }
            }
        }
        vb[0] = *(const float4*)(Bb + (size_t)k0 * Nc);
        vb[1] = *(const float4*)(Bb + (size_t)k0 * Nc + 4);
        vb[2] = *(const float4*)(Bb + (size_t)(k0 + 16) * Nc);
        vb[3] = *(const float4*)(Bb + (size_t)(k0 + 16) * Nc + 4);

        __syncthreads();
#pragma unroll
        for (int q = 0; q < 4; q++) {
            As[akc + q * 4 + 0][ar_] = va[q].x;
            As[akc + q * 4 + 1][ar_] = va[q].y;
            As[akc + q * 4 + 2][ar_] = va[q].z;
            As[akc + q * 4 + 3][ar_] = va[q].w;
        }
        *(float4*)&Bs[bkb][bc4]          = vb[0];
        *(float4*)&Bs[bkb][bc4 + 4]      = vb[1];
        *(float4*)&Bs[bkb + 16][bc4]     = vb[2];
        *(float4*)&Bs[bkb + 16][bc4 + 4] = vb[3];
        __syncthreads();

#pragma unroll
        for (int k = 0; k < 32; k++) {
            float4 x0 = *(const float4*)&As[k][rbase];
            float4 x1 = *(const float4*)&As[k][rbase + 4];
            float4 y0 = *(const float4*)&Bs[k][cbase];
            float4 y1 = *(const float4*)&Bs[k][cbase + 4];
            ull A2[4] = {pk2(x0.x, x0.y), pk2(x0.z, x0.w),
                         pk2(x1.x, x1.y), pk2(x1.z, x1.w)};
            float bb[8] = {y0.x, y0.y, y0.z, y0.w, y1.x, y1.y, y1.z, y1.w};
#pragma unroll
            for (int j = 0; j < 8; j++) {
                ull B2 = pk2(bb[j], bb[j]);
#pragma unroll
                for (int i = 0; i < 4; i++) acc[i][j] = fma2(A2[i], B2, acc[i][j]);
            }
        }
    }

    float* Cp = (MODE == 0) ? g_xp : g_h1;
    float cb[8];
#pragma unroll
    for (int j = 0; j < 8; j++) cb[j] = cbias ? cbias[n0 + cbase + j] : 0.f;

    float sa[8], da[8];
    int h = n0 >> 7;
    if (MODE == 0) {
#pragma unroll
        for (int j = 0; j < 8; j++) {
            sa[j] = asrc[(h << 7) + cbase + j];
            da[j] = adst[(h << 7) + cbase + j];
        }
    }

#pragma unroll
    for (int i = 0; i < 4; i++) {
        float2 p[8];
#pragma unroll
        for (int j = 0; j < 8; j++) p[j] = upk(acc[i][j]);
        int re = m0 + rbase + i * 2;
        int gc = n0 + cbase;
        if (re < M) {
            *(float4*)(Cp + (size_t)re * Nc + gc) =
                make_float4(p[0].x + cb[0], p[1].x + cb[1], p[2].x + cb[2], p[3].x + cb[3]);
            *(float4*)(Cp + (size_t)re * Nc + gc + 4) =
                make_float4(p[4].x + cb[4], p[5].x + cb[5], p[6].x + cb[6], p[7].x + cb[7]);
        }
        if (re + 1 < M) {
            *(float4*)(Cp + (size_t)(re + 1) * Nc + gc) =
                make_float4(p[0].y + cb[0], p[1].y + cb[1], p[2].y + cb[2], p[3].y + cb[3]);
            *(float4*)(Cp + (size_t)(re + 1) * Nc + gc + 4) =
                make_float4(p[4].y + cb[4], p[5].y + cb[5], p[6].y + cb[6], p[7].y + cb[7]);
        }
        if (MODE == 0) {
            float s0 = 0.f, d0 = 0.f, s1 = 0.f, d1 = 0.f;
#pragma unroll
            for (int j = 0; j < 8; j++) {
                s0 += p[j].x * sa[j]; d0 += p[j].x * da[j];
                s1 += p[j].y * sa[j]; d1 += p[j].y * da[j];
            }
#pragma unroll
            for (int msk = 1; msk < 8; msk <<= 1) {   // reduce over 8-lane ln group
                s0 += __shfl_xor_sync(0xFFFFFFFFu, s0, msk);
                d0 += __shfl_xor_sync(0xFFFFFFFFu, d0, msk);
                s1 += __shfl_xor_sync(0xFFFFFFFFu, s1, msk);
                d1 += __shfl_xor_sync(0xFFFFFFFFu, d1, msk);
            }
            if (ln == 0) {
                int rl = rbase + i * 2;
                srs[wn][rl] = s0; srd[wn][rl] = d0;
                srs[wn][rl + 1] = s1; srd[wn][rl + 1] = d1;
            }
        }
    }
    if (MODE == 0) {
        __syncthreads();
        if (t < 128) {
            int row = m0 + t;
            if (row < M) {
                g_as[row * 2 + h] = srs[0][t] + srs[1][t];
                g_ad[row * 2 + h] = srd[0][t] + srd[1][t];
            }
        }
    }
}

// ---------------- degree count ----------------
__global__ void k_degree(const int* __restrict__ ei) {
    int i = blockIdx.x * blockDim.x + threadIdx.x;
    if (i >= ET) return;
    int dst = (i < Ee) ? ei[Ee + i] : (i - Ee);
    atomicAdd(&g_deg[dst], 1);
}

// ---------------- parallel scan, phase A ----------------
__global__ void k_scanA() {
    __shared__ int sh[256];
    int b = blockIdx.x, t = threadIdx.x;
    int i = b * 256 + t;
    int d = (i < Nn) ? g_deg[i] : 0;
    sh[t] = d;
    __syncthreads();
    for (int off = 1; off < 256; off <<= 1) {
        int v = (t >= off) ? sh[t - off] : 0;
        __syncthreads();
        sh[t] += v;
        __syncthreads();
    }
    if (i < Nn) g_ptr[i] = sh[t] - d;
    if (t == 255) g_blk[b] = sh[255];
}

// ---------------- parallel scan, phase B ----------------
__global__ void k_scanB() {
    __shared__ int sb[128];
    int b = blockIdx.x, t = threadIdx.x;
    if (t < 128) sb[t] = (t < SB) ? g_blk[t] : 0;
    __syncthreads();
    for (int off = 1; off < 128; off <<= 1) {
        int v = 0;
        if (t < 128 && t >= off) v = sb[t - off];
        __syncthreads();
        if (t < 128) sb[t] += v;
        __syncthreads();
    }
    int offb = (b > 0) ? sb[b - 1] : 0;
    int i = b * 256 + t;
    if (i < Nn) {
        int p = g_ptr[i] + offb;
        g_ptr[i] = p;
        g_cur[i] = p;
        if (i == Nn - 1) g_ptr[Nn] = p + g_deg[i];
    }
}

// ---------------- fused edge: logit -> exp -> CSR scatter (packed 16B) ----------
__global__ void k_edge(const int* __restrict__ ei) {
    int i = blockIdx.x * blockDim.x + threadIdx.x;
    if (i >= ET) return;
    int src, dst;
    if (i < Ee) { src = ei[i]; dst = ei[Ee + i]; }
    else        { src = dst = i - Ee; }
    float2 as = *(const float2*)(g_as + src * 2);
    float2 ad = *(const float2*)(g_ad + dst * 2);
    float l0 = as.x + ad.x; l0 = l0 > 0.f ? l0 : 0.2f * l0;
    float l1 = as.y + ad.y; l1 = l1 > 0.f ? l1 : 0.2f * l1;
    float w0 = __expf(l0), w1 = __expf(l1);
    int pos = atomicAdd(&g_cur[dst], 1);
    g_csre[pos] = make_int4(src, __float_as_int(w0), __float_as_int(w1), 0);
}

// ---------------- aggregation: ONE WARP per dst, lane-local normalize -----------
__global__ void __launch_bounds__(256) k_agg() {
    int w = (blockIdx.x * blockDim.x + threadIdx.x) >> 5;
    int lane = threadIdx.x & 31;
    if (w >= Nn) return;
    int beg = g_ptr[w], end = g_ptr[w + 1];
    const float4* xp4 = (const float4*)g_xp;

    float4 acc0 = make_float4(0.f, 0.f, 0.f, 0.f);
    float4 acc1 = make_float4(0.f, 0.f, 0.f, 0.f);
    float ws0 = 0.f, ws1 = 0.f;

    int e = beg;
    for (; e + 1 < end; e += 2) {
        int4 r0 = __ldg(&g_csre[e]);
        int4 r1 = __ldg(&g_csre[e + 1]);
        const float4* p0 = xp4 + (size_t)r0.x * 64;
        const float4* p1 = xp4 + (size_t)r1.x * 64;
        float4 a0 = __ldg(p0 + lane);
        float4 b0 = __ldg(p0 + lane + 32);
        float4 a1 = __ldg(p1 + lane);
        float4 b1 = __ldg(p1 + lane + 32);
        float w00 = __int_as_float(r0.y), w01 = __int_as_float(r0.z);
        float w10 = __int_as_float(r1.y), w11 = __int_as_float(r1.z);
        acc0.x += a0.x * w00 + a1.x * w10; acc0.y += a0.y * w00 + a1.y * w10;
        acc0.z += a0.z * w00 + a1.z * w10; acc0.w += a0.w * w00 + a1.w * w10;
        acc1.x += b0.x * w01 + b1.x * w11; acc1.y += b0.y * w01 + b1.y * w11;
        acc1.z += b0.z * w01 + b1.z * w11; acc1.w += b0.w * w01 + b1.w * w11;
        ws0 += w00 + w10; ws1 += w01 + w11;
    }
    if (e < end) {
        int4 r0 = __ldg(&g_csre[e]);
        const float4* p0 = xp4 + (size_t)r0.x * 64;
        float4 a0 = __ldg(p0 + lane);
        float4 b0 = __ldg(p0 + lane + 32);
        float w00 = __int_as_float(r0.y), w01 = __int_as_float(r0.z);
        acc0.x += a0.x * w00; acc0.y += a0.y * w00;
        acc0.z += a0.z * w00; acc0.w += a0.w * w00;
        acc1.x += b0.x * w01; acc1.y += b0.y * w01;
        acc1.z += b0.z * w01; acc1.w += b0.w * w01;
        ws0 += w00; ws1 += w01;
    }
    float rd0 = 1.f / ws0, rd1 = 1.f / ws1;
    float4* op = (float4*)(g_acc + (size_t)w * HC);
    op[lane]      = make_float4(acc0.x * rd0, acc0.y * rd0, acc0.z * rd0, acc0.w * rd0);
    op[lane + 32] = make_float4(acc1.x * rd1, acc1.y * rd1, acc1.z * rd1, acc1.w * rd1);
}

// ---------------- fused pool(raw) + BN0 stats: ONE pass over g_h1 ---------------
// BN is affine => pooled_normalized = sc*sum_raw + cnt*sh, applied later by k_hpfix.
__global__ void k_poolstats(const int* __restrict__ batch) {
    int c = threadIdx.x;  // 128
    int per = (Nn + gridDim.x - 1) / gridDim.x;
    int s = blockIdx.x * per;
    int e = min(Nn, s + per);
    if (s >= e) return;
    float sum = 0.f, sum2 = 0.f;
    int cur = batch[s];
    float a = 0.f;
    int cnt = 0;
    for (int n = s; n < e; n++) {
        float v = g_h1[(size_t)n * Cc + c];
        sum += v; sum2 += v * v;
        int gi = batch[n];
        if (gi != cur) {
            atomicAdd(&g_hp[cur * Cc + c], a);
            if (c == 0) atomicAdd(&g_gcnt[cur], cnt);
            a = 0.f; cnt = 0; cur = gi;
        }
        a += v; cnt++;
    }
    atomicAdd(&g_hp[cur * Cc + c], a);
    if (c == 0) atomicAdd(&g_gcnt[cur], cnt);
    atomicAdd(&g_bnsum[c], sum);
    atomicAdd(&g_bnsum[Cc + c], sum2);
}

__global__ void k_bn0_final(const float* __restrict__ g, const float* __restrict__ b) {
    int c = threadIdx.x;
    if (c < Cc) {
        float mean = g_bnsum[c] / (float)Nn;
        float var  = fmaxf(g_bnsum[Cc + c] / (float)Nn - mean * mean, 0.f);
        float sc = g[c] * rsqrtf(var + EPSB);
        g_sc0[c] = sc;
        g_sh0[c] = b[c] - mean * sc;
    }
}

// ---------------- apply BN affine to raw pooled sums ----------------------------
__global__ void k_hpfix() {
    int i = blockIdx.x * blockDim.x + threadIdx.x;
    if (i < Gg * Cc) {
        int g = i >> 7, c = i & 127;
        g_hp[i] = g_hp[i] * g_sc0[c] + (float)g_gcnt[g] * g_sh0[c];
    }
}

// ---------------- FC stack ----------------
__global__ void k_fc1(const float* __restrict__ w, const float* __restrict__ b) {
    int idx = blockIdx.x * blockDim.x + threadIdx.x;
    if (idx >= Gg * 512) return;
    int c = idx & 511, r = idx >> 9;
    float s = b[c];
#pragma unroll 8
    for (int k = 0; k < Cc; k++) s += g_hp[r * Cc + k] * w[k * 512 + c];
    g_z1[idx] = s;
}

__global__ void k_bn1(const float* __restrict__ g, const float* __restrict__ b) {
    int c = blockIdx.x * blockDim.x + threadIdx.x;
    if (c >= 512) return;
    float s = 0.f, s2 = 0.f;
    for (int r = 0; r < Gg; r++) { float v = g_z1[r * 512 + c]; s += v; s2 += v * v; }
    float mean = s / (float)Gg;
    float var = fmaxf(s2 / (float)Gg - mean * mean, 0.f);
    float sc = g[c] * rsqrtf(var + EPSB);
    g_sc1[c] = sc; g_sh1[c] = b[c] - mean * sc;
}

__global__ void k_fc2(const float* __restrict__ w, const float* __restrict__ b) {
    int idx = blockIdx.x * blockDim.x + threadIdx.x;
    if (idx >= Gg * 256) return;
    int c = idx & 255, r = idx >> 8;
    float s = b[c];
#pragma unroll 8
    for (int k = 0; k < 512; k++) {
        float v = fmaxf(g_z1[r * 512 + k] * g_sc1[k] + g_sh1[k], 0.f);
        s += v * w[k * 256 + c];
    }
    g_z2[idx] = s;
}

__global__ void k_bn2(const float* __restrict__ g, const float* __restrict__ b) {
    int c = threadIdx.x;
    if (c >= 256) return;
    float s = 0.f, s2 = 0.f;
    for (int r = 0; r < Gg; r++) { float v = g_z2[r * 256 + c]; s += v; s2 += v * v; }
    float mean = s / (float)Gg;
    float var = fmaxf(s2 / (float)Gg - mean * mean, 0.f);
    float sc = g[c] * rsqrtf(var + EPSB);
    g_sc2[c] = sc; g_sh2[c] = b[c] - mean * sc;
}

__global__ void k_fc3(const float* __restrict__ w, const float* __restrict__ b,
                      const float* __restrict__ g3, const float* __restrict__ b3,
                      float* __restrict__ out) {
    __shared__ float red[256];
    __shared__ float z3[64];
    __shared__ float mv[2];
    int t = threadIdx.x;
    int r = t >> 2, p = t & 3;
    float s = 0.f;
    for (int k = p * 64; k < p * 64 + 64; k++) {
        float v = fmaxf(g_z2[r * 256 + k] * g_sc2[k] + g_sh2[k], 0.f);
        s += v * w[k];
    }
    red[t] = s;
    __syncthreads();
    if (p == 0) z3[r] = red[t] + red[t + 1] + red[t + 2] + red[t + 3] + b[0];
    __syncthreads();
    if (t == 0) {
        float m = 0.f;
        for (int i = 0; i < 64; i++) m += z3[i];
        m /= 64.f;
        float v = 0.f;
        for (int i = 0; i < 64; i++) { float d = z3[i] - m; v += d * d; }
        v /= 64.f;
        mv[0] = m; mv[1] = rsqrtf(v + EPSB);
    }
    __syncthreads();
    if (t < 64) out[t] = (z3[t] - mv[0]) * mv[1] * g3[0] + b3[0];
}

// ---------------- launch ----------------
extern "C" void kernel_launch(void* const* d_in, const int* in_sizes, int n_in,
                              void* d_out, int out_size) {
    const float* x        = (const float*)d_in[0];
    const float* gat_w    = (const float*)d_in[1];
    const float* gat_asrc = (const float*)d_in[2];
    const float* gat_adst = (const float*)d_in[3];
    const float* gat_bias = (const float*)d_in[4];
    const float* mlp_w    = (const float*)d_in[5];
    const float* mlp_b    = (const float*)d_in[6];
    const float* bn0_g    = (const float*)d_in[7];
    const float* bn0_b    = (const float*)d_in[8];
    const float* fc1_w    = (const float*)d_in[9];
    const float* fc1_b    = (const float*)d_in[10];
    const float* bn1_g    = (const float*)d_in[11];
    const float* bn1_b    = (const float*)d_in[12];
    const float* fc2_w    = (const float*)d_in[13];
    const float* fc2_b    = (const float*)d_in[14];
    const float* bn2_g    = (const float*)d_in[15];
    const float* bn2_b    = (const float*)d_in[16];
    const float* fc3_w    = (const float*)d_in[17];
    const float* fc3_b    = (const float*)d_in[18];
    const float* bn3_g    = (const float*)d_in[19];
    const float* bn3_b    = (const float*)d_in[20];
    const int*   ei       = (const int*)d_in[21];
    const int*   batch    = (const int*)d_in[22];
    float* out = (float*)d_out;

    // gemm0 is the 4th launch (profile slot)
    k_init<<<(Nn + 255) / 256, 256>>>();
    k_degree<<<(ET + 255) / 256, 256>>>(ei);
    k_scanA<<<SB, 256>>>();
    k_gemm<0><<<dim3((Nn + 127) / 128, HC / 128), 256>>>(
        x, gat_w, nullptr, nullptr, gat_asrc, gat_adst, Nn, 448, HC);
    k_scanB<<<SB, 256>>>();
    k_edge<<<(ET + 255) / 256, 256>>>(ei);
    k_agg<<<(Nn * 32 + 255) / 256, 256>>>();
    k_gemm<1><<<dim3((Nn + 127) / 128, Cc / 128), 256>>>(
        nullptr, mlp_w, mlp_b, gat_bias, nullptr, nullptr, Nn, HC, Cc);
    k_poolstats<<<200, 128>>>(batch);
    k_bn0_final<<<1, 128>>>(bn0_g, bn0_b);
    k_hpfix<<<(Gg * Cc + 255) / 256, 256>>>();
    k_fc1<<<(Gg * 512 + 255) / 256, 256>>>(fc1_w, fc1_b);
    k_bn1<<<2, 256>>>(bn1_g, bn1_b);
    k_fc2<<<(Gg * 256 + 255) / 256, 256>>>(fc2_w, fc2_b);
    k_bn2<<<1, 256>>>(bn2_g, bn2_b);
    k_fc3<<<1, 256>>>(fc3_w, fc3_b, bn3_g, bn3_b, out);
}

// round 13
// speedup vs baseline: 1.2430x; 1.0327x over previous
#include <cuda_runtime.h>
#include <cuda_fp16.h>
#include <math.h>

#define Nn 30000
#define Ee 960000
#define ET (Ee + Nn)
#define Hh 2
#define Cc 128
#define HC 256
#define Gg 64
#define EPSB 1e-5f
#define SB 118   // scan blocks = ceil(Nn/256)

typedef unsigned long long ull;

// ---------------- scratch (device globals; no allocation allowed) ----------------
__device__ __half g_xph[(size_t)Nn * HC];    // x @ gat_w  (fp16; only consumer = k_agg)
__device__ float  g_as[Nn * Hh];             // attention src dots [N,2]
__device__ float  g_ad[Nn * Hh];             // attention dst dots [N,2]
__device__ int    g_deg[Nn];                 // in-degree
__device__ int    g_ptr[Nn + 1];             // CSR offsets
__device__ int    g_cur[Nn];                 // scatter cursors
__device__ int    g_blk[SB];                 // per-block degree sums
__device__ int4   g_csre[ET];                // CSR edge: {src, w0, w1, pad}
__device__ float  g_acc[(size_t)Nn * HC];    // normalized aggregation
__device__ float  g_h1[(size_t)Nn * Cc];     // elu(out) @ mlp_w + b  (raw, pre-BN)
__device__ float  g_bnsum[2 * Cc];
__device__ float  g_sc0[Cc], g_sh0[Cc];
__device__ int    g_gcnt[Gg];                // nodes per graph
__device__ float  g_hp[Gg * Cc];             // pooled (raw then fixed)
__device__ float  g_z1[Gg * 512];
__device__ float  g_sc1[512], g_sh1[512];
__device__ float  g_z2[Gg * 256];
__device__ float  g_sc2[256], g_sh2[256];

// ---------------- f32x2 helpers ----------------
__device__ __forceinline__ ull pk2(float lo, float hi) {
    ull d;
    asm("mov.b64 %0, {%1, %2};" : "=l"(d) : "r"(__float_as_uint(lo)), "r"(__float_as_uint(hi)));
    return d;
}
__device__ __forceinline__ float2 upk(ull v) {
    unsigned lo, hi;
    asm("mov.b64 {%0, %1}, %2;" : "=r"(lo), "=r"(hi) : "l"(v));
    return make_float2(__uint_as_float(lo), __uint_as_float(hi));
}
__device__ __forceinline__ ull fma2(ull a, ull b, ull c) {
    ull d;
    asm("fma.rn.f32x2 %0, %1, %2, %3;" : "=l"(d) : "l"(a), "l"(b), "l"(c));
    return d;
}

// ---------------- init ----------------
__global__ void k_init() {
    int i = blockIdx.x * blockDim.x + threadIdx.x;
    if (i < Nn)      g_deg[i] = 0;
    if (i < Gg * Cc) g_hp[i] = 0.f;
    if (i < 2 * Cc)  g_bnsum[i] = 0.f;
    if (i < Gg)      g_gcnt[i] = 0;
}

// ---------------- f32x2 GEMM: 128x128x32, 256 thr, 8x8/thread, 2 CTAs/SM --------
// MODE 0: g_xph(fp16) = Aext @ B;  epilogue also writes attention dots g_as/g_ad
// MODE 1: g_h1(fp32)  = elu(g_acc + abias) @ B + cbias
template <int MODE>
__global__ void __launch_bounds__(256, 2)
k_gemm(const float* __restrict__ Aext, const float* __restrict__ B,
       const float* __restrict__ cbias, const float* __restrict__ abias,
       const float* __restrict__ asrc, const float* __restrict__ adst,
       int M, int K, int Nc) {
    __shared__ float As[32][128];
    __shared__ float Bs[32][128];
    __shared__ float srs[2][128];
    __shared__ float srd[2][128];
    int t = threadIdx.x;
    int lane = t & 31, w = t >> 5;
    int wm = w & 3, wn = w >> 2;
    int lm = lane >> 3, ln = lane & 7;
    int rbase = wm * 32 + lm * 8;
    int cbase = wn * 64 + ln * 8;
    int m0 = blockIdx.x * 128, n0 = blockIdx.y * 128;
    int ar_ = t >> 1, akc = (t & 1) * 16;
    int bkb = t >> 4, bc4 = (t & 15) * 8;
    int steps = K >> 5;
    bool rowok = (m0 + ar_) < M;
    const float* Ab = ((MODE == 0) ? Aext : (const float*)g_acc) + (size_t)(m0 + ar_) * K + akc;
    const float* Bb = B + (size_t)bkb * Nc + n0 + bc4;

    ull acc[4][8];
#pragma unroll
    for (int i = 0; i < 4; i++)
#pragma unroll
        for (int j = 0; j < 8; j++) acc[i][j] = 0ull;

    for (int it = 0; it < steps; it++) {
        int k0 = it << 5;
        float4 va[4];
        float4 vb[4];
#pragma unroll
        for (int q = 0; q < 4; q++) va[q] = make_float4(0.f, 0.f, 0.f, 0.f);
        if (rowok) {
#pragma unroll
            for (int q = 0; q < 4; q++) va[q] = *(const float4*)(Ab + k0 + q * 4);
            if (MODE == 1) {
                int gk = k0 + akc;
#pragma unroll
                for (int q = 0; q < 4; q++) {
                    float f[4] = {va[q].x, va[q].y, va[q].z, va[q].w};
#pragma unroll
                    for (int j = 0; j < 4; j++) {
                        float u = f[j] + __ldg(abias + gk + q * 4 + j);
                        f[j] = u > 0.f ? u : (__expf(u) - 1.f);
                    }
                    va[q] = make_float4(f[0], f[1], f[2], f[3]);
                }
            }
        }
        vb[0] = *(const float4*)(Bb + (size_t)k0 * Nc);
        vb[1] = *(const float4*)(Bb + (size_t)k0 * Nc + 4);
        vb[2] = *(const float4*)(Bb + (size_t)(k0 + 16) * Nc);
        vb[3] = *(const float4*)(Bb + (size_t)(k0 + 16) * Nc + 4);

        __syncthreads();
#pragma unroll
        for (int q = 0; q < 4; q++) {
            As[akc + q * 4 + 0][ar_] = va[q].x;
            As[akc + q * 4 + 1][ar_] = va[q].y;
            As[akc + q * 4 + 2][ar_] = va[q].z;
            As[akc + q * 4 + 3][ar_] = va[q].w;
        }
        *(float4*)&Bs[bkb][bc4]          = vb[0];
        *(float4*)&Bs[bkb][bc4 + 4]      = vb[1];
        *(float4*)&Bs[bkb + 16][bc4]     = vb[2];
        *(float4*)&Bs[bkb + 16][bc4 + 4] = vb[3];
        __syncthreads();

#pragma unroll
        for (int k = 0; k < 32; k++) {
            float4 x0 = *(const float4*)&As[k][rbase];
            float4 x1 = *(const float4*)&As[k][rbase + 4];
            float4 y0 = *(const float4*)&Bs[k][cbase];
            float4 y1 = *(const float4*)&Bs[k][cbase + 4];
            ull A2[4] = {pk2(x0.x, x0.y), pk2(x0.z, x0.w),
                         pk2(x1.x, x1.y), pk2(x1.z, x1.w)};
            float bb[8] = {y0.x, y0.y, y0.z, y0.w, y1.x, y1.y, y1.z, y1.w};
#pragma unroll
            for (int j = 0; j < 8; j++) {
                ull B2 = pk2(bb[j], bb[j]);
#pragma unroll
                for (int i = 0; i < 4; i++) acc[i][j] = fma2(A2[i], B2, acc[i][j]);
            }
        }
    }

    float cb[8];
#pragma unroll
    for (int j = 0; j < 8; j++) cb[j] = cbias ? cbias[n0 + cbase + j] : 0.f;

    float sa[8], da[8];
    int h = n0 >> 7;
    if (MODE == 0) {
#pragma unroll
        for (int j = 0; j < 8; j++) {
            sa[j] = asrc[(h << 7) + cbase + j];
            da[j] = adst[(h << 7) + cbase + j];
        }
    }

#pragma unroll
    for (int i = 0; i < 4; i++) {
        float2 p[8];
#pragma unroll
        for (int j = 0; j < 8; j++) p[j] = upk(acc[i][j]);
        int re = m0 + rbase + i * 2;
        int gc = n0 + cbase;
        if (MODE == 0) {
            // fp16 feature store (only consumer is the gather)
            if (re < M) {
                __half2 hh[4] = {
                    __floats2half2_rn(p[0].x, p[1].x), __floats2half2_rn(p[2].x, p[3].x),
                    __floats2half2_rn(p[4].x, p[5].x), __floats2half2_rn(p[6].x, p[7].x)};
                *(uint4*)(g_xph + (size_t)re * HC + gc) = *(uint4*)hh;
            }
            if (re + 1 < M) {
                __half2 hh[4] = {
                    __floats2half2_rn(p[0].y, p[1].y), __floats2half2_rn(p[2].y, p[3].y),
                    __floats2half2_rn(p[4].y, p[5].y), __floats2half2_rn(p[6].y, p[7].y)};
                *(uint4*)(g_xph + (size_t)(re + 1) * HC + gc) = *(uint4*)hh;
            }
        } else {
            if (re < M) {
                *(float4*)(g_h1 + (size_t)re * Nc + gc) =
                    make_float4(p[0].x + cb[0], p[1].x + cb[1], p[2].x + cb[2], p[3].x + cb[3]);
                *(float4*)(g_h1 + (size_t)re * Nc + gc + 4) =
                    make_float4(p[4].x + cb[4], p[5].x + cb[5], p[6].x + cb[6], p[7].x + cb[7]);
            }
            if (re + 1 < M) {
                *(float4*)(g_h1 + (size_t)(re + 1) * Nc + gc) =
                    make_float4(p[0].y + cb[0], p[1].y + cb[1], p[2].y + cb[2], p[3].y + cb[3]);
                *(float4*)(g_h1 + (size_t)(re + 1) * Nc + gc + 4) =
                    make_float4(p[4].y + cb[4], p[5].y + cb[5], p[6].y + cb[6], p[7].y + cb[7]);
            }
        }
        if (MODE == 0) {
            float s0 = 0.f, d0 = 0.f, s1 = 0.f, d1 = 0.f;
#pragma unroll
            for (int j = 0; j < 8; j++) {
                s0 += p[j].x * sa[j]; d0 += p[j].x * da[j];
                s1 += p[j].y * sa[j]; d1 += p[j].y * da[j];
            }
#pragma unroll
            for (int msk = 1; msk < 8; msk <<= 1) {
                s0 += __shfl_xor_sync(0xFFFFFFFFu, s0, msk);
                d0 += __shfl_xor_sync(0xFFFFFFFFu, d0, msk);
                s1 += __shfl_xor_sync(0xFFFFFFFFu, s1, msk);
                d1 += __shfl_xor_sync(0xFFFFFFFFu, d1, msk);
            }
            if (ln == 0) {
                int rl = rbase + i * 2;
                srs[wn][rl] = s0; srd[wn][rl] = d0;
                srs[wn][rl + 1] = s1; srd[wn][rl + 1] = d1;
            }
        }
    }
    if (MODE == 0) {
        __syncthreads();
        if (t < 128) {
            int row = m0 + t;
            if (row < M) {
                g_as[row * 2 + h] = srs[0][t] + srs[1][t];
                g_ad[row * 2 + h] = srd[0][t] + srd[1][t];
            }
        }
    }
}

// ---------------- degree count ----------------
__global__ void k_degree(const int* __restrict__ ei) {
    int i = blockIdx.x * blockDim.x + threadIdx.x;
    if (i >= ET) return;
    int dst = (i < Ee) ? ei[Ee + i] : (i - Ee);
    atomicAdd(&g_deg[dst], 1);
}

// ---------------- parallel scan, phase A ----------------
__global__ void k_scanA() {
    __shared__ int sh[256];
    int b = blockIdx.x, t = threadIdx.x;
    int i = b * 256 + t;
    int d = (i < Nn) ? g_deg[i] : 0;
    sh[t] = d;
    __syncthreads();
    for (int off = 1; off < 256; off <<= 1) {
        int v = (t >= off) ? sh[t - off] : 0;
        __syncthreads();
        sh[t] += v;
        __syncthreads();
    }
    if (i < Nn) g_ptr[i] = sh[t] - d;
    if (t == 255) g_blk[b] = sh[255];
}

// ---------------- parallel scan, phase B ----------------
__global__ void k_scanB() {
    __shared__ int sb[128];
    int b = blockIdx.x, t = threadIdx.x;
    if (t < 128) sb[t] = (t < SB) ? g_blk[t] : 0;
    __syncthreads();
    for (int off = 1; off < 128; off <<= 1) {
        int v = 0;
        if (t < 128 && t >= off) v = sb[t - off];
        __syncthreads();
        if (t < 128) sb[t] += v;
        __syncthreads();
    }
    int offb = (b > 0) ? sb[b - 1] : 0;
    int i = b * 256 + t;
    if (i < Nn) {
        int p = g_ptr[i] + offb;
        g_ptr[i] = p;
        g_cur[i] = p;
        if (i == Nn - 1) g_ptr[Nn] = p + g_deg[i];
    }
}

// ---------------- fused edge: logit -> exp -> CSR scatter (packed 16B) ----------
__global__ void k_edge(const int* __restrict__ ei) {
    int i = blockIdx.x * blockDim.x + threadIdx.x;
    if (i >= ET) return;
    int src, dst;
    if (i < Ee) { src = ei[i]; dst = ei[Ee + i]; }
    else        { src = dst = i - Ee; }
    float2 as = *(const float2*)(g_as + src * 2);
    float2 ad = *(const float2*)(g_ad + dst * 2);
    float l0 = as.x + ad.x; l0 = l0 > 0.f ? l0 : 0.2f * l0;
    float l1 = as.y + ad.y; l1 = l1 > 0.f ? l1 : 0.2f * l1;
    float w0 = __expf(l0), w1 = __expf(l1);
    int pos = atomicAdd(&g_cur[dst], 1);
    g_csre[pos] = make_int4(src, __float_as_int(w0), __float_as_int(w1), 0);
}

// ---------------- aggregation: warp/dst, fp16 gather (1 uint4 per lane) ---------
// Lane covers channels lane*8..lane*8+7: lanes 0-15 = head 0, 16-31 = head 1.
__device__ __forceinline__ void fma8h(float* a, uint4 v, float wt) {
    __half2* h = (__half2*)&v;
#pragma unroll
    for (int i = 0; i < 4; i++) {
        float2 f = __half22float2(h[i]);
        a[2 * i]     += f.x * wt;
        a[2 * i + 1] += f.y * wt;
    }
}
__global__ void __launch_bounds__(256) k_agg() {
    int w = (blockIdx.x * blockDim.x + threadIdx.x) >> 5;
    int lane = threadIdx.x & 31;
    if (w >= Nn) return;
    int beg = g_ptr[w], end = g_ptr[w + 1];
    const uint4* xh = (const uint4*)g_xph;   // 32 uint4 per row
    bool hside = lane >= 16;
    float acc[8] = {0.f, 0.f, 0.f, 0.f, 0.f, 0.f, 0.f, 0.f};
    float ws = 0.f;
    int e = beg;
    for (; e + 1 < end; e += 2) {
        int4 r0 = __ldg(&g_csre[e]);
        int4 r1 = __ldg(&g_csre[e + 1]);
        uint4 v0 = __ldg(xh + (size_t)r0.x * 32 + lane);
        uint4 v1 = __ldg(xh + (size_t)r1.x * 32 + lane);
        float w0 = __int_as_float(hside ? r0.z : r0.y);
        float w1 = __int_as_float(hside ? r1.z : r1.y);
        fma8h(acc, v0, w0);
        fma8h(acc, v1, w1);
        ws += w0 + w1;
    }
    if (e < end) {
        int4 r0 = __ldg(&g_csre[e]);
        uint4 v0 = __ldg(xh + (size_t)r0.x * 32 + lane);
        float w0 = __int_as_float(hside ? r0.z : r0.y);
        fma8h(acc, v0, w0);
        ws += w0;
    }
    float rd = 1.f / ws;
    float* op = g_acc + (size_t)w * HC + lane * 8;
    *(float4*)op       = make_float4(acc[0] * rd, acc[1] * rd, acc[2] * rd, acc[3] * rd);
    *(float4*)(op + 4) = make_float4(acc[4] * rd, acc[5] * rd, acc[6] * rd, acc[7] * rd);
}

// ---------------- fused pool(raw) + BN0 stats: ONE pass over g_h1 ---------------
__global__ void k_poolstats(const int* __restrict__ batch) {
    int c = threadIdx.x;  // 128
    int per = (Nn + gridDim.x - 1) / gridDim.x;
    int s = blockIdx.x * per;
    int e = min(Nn, s + per);
    if (s >= e) return;
    float sum = 0.f, sum2 = 0.f;
    int cur = batch[s];
    float a = 0.f;
    int cnt = 0;
    for (int n = s; n < e; n++) {
        float v = g_h1[(size_t)n * Cc + c];
        sum += v; sum2 += v * v;
        int gi = batch[n];
        if (gi != cur) {
            atomicAdd(&g_hp[cur * Cc + c], a);
            if (c == 0) atomicAdd(&g_gcnt[cur], cnt);
            a = 0.f; cnt = 0; cur = gi;
        }
        a += v; cnt++;
    }
    atomicAdd(&g_hp[cur * Cc + c], a);
    if (c == 0) atomicAdd(&g_gcnt[cur], cnt);
    atomicAdd(&g_bnsum[c], sum);
    atomicAdd(&g_bnsum[Cc + c], sum2);
}

__global__ void k_bn0_final(const float* __restrict__ g, const float* __restrict__ b) {
    int c = threadIdx.x;
    if (c < Cc) {
        float mean = g_bnsum[c] / (float)Nn;
        float var  = fmaxf(g_bnsum[Cc + c] / (float)Nn - mean * mean, 0.f);
        float sc = g[c] * rsqrtf(var + EPSB);
        g_sc0[c] = sc;
        g_sh0[c] = b[c] - mean * sc;
    }
}

__global__ void k_hpfix() {
    int i = blockIdx.x * blockDim.x + threadIdx.x;
    if (i < Gg * Cc) {
        int g = i >> 7, c = i & 127;
        g_hp[i] = g_hp[i] * g_sc0[c] + (float)g_gcnt[g] * g_sh0[c];
    }
}

// ---------------- FC stack ----------------
__global__ void k_fc1(const float* __restrict__ w, const float* __restrict__ b) {
    int idx = blockIdx.x * blockDim.x + threadIdx.x;
    if (idx >= Gg * 512) return;
    int c = idx & 511, r = idx >> 9;
    float s = b[c];
#pragma unroll 8
    for (int k = 0; k < Cc; k++) s += g_hp[r * Cc + k] * w[k * 512 + c];
    g_z1[idx] = s;
}

__global__ void k_bn1(const float* __restrict__ g, const float* __restrict__ b) {
    int c = blockIdx.x * blockDim.x + threadIdx.x;
    if (c >= 512) return;
    float s = 0.f, s2 = 0.f;
    for (int r = 0; r < Gg; r++) { float v = g_z1[r * 512 + c]; s += v; s2 += v * v; }
    float mean = s / (float)Gg;
    float var = fmaxf(s2 / (float)Gg - mean * mean, 0.f);
    float sc = g[c] * rsqrtf(var + EPSB);
    g_sc1[c] = sc; g_sh1[c] = b[c] - mean * sc;
}

__global__ void k_fc2(const float* __restrict__ w, const float* __restrict__ b) {
    int idx = blockIdx.x * blockDim.x + threadIdx.x;
    if (idx >= Gg * 256) return;
    int c = idx & 255, r = idx >> 8;
    float s = b[c];
#pragma unroll 8
    for (int k = 0; k < 512; k++) {
        float v = fmaxf(g_z1[r * 512 + k] * g_sc1[k] + g_sh1[k], 0.f);
        s += v * w[k * 256 + c];
    }
    g_z2[idx] = s;
}

__global__ void k_bn2(const float* __restrict__ g, const float* __restrict__ b) {
    int c = threadIdx.x;
    if (c >= 256) return;
    float s = 0.f, s2 = 0.f;
    for (int r = 0; r < Gg; r++) { float v = g_z2[r * 256 + c]; s += v; s2 += v * v; }
    float mean = s / (float)Gg;
    float var = fmaxf(s2 / (float)Gg - mean * mean, 0.f);
    float sc = g[c] * rsqrtf(var + EPSB);
    g_sc2[c] = sc; g_sh2[c] = b[c] - mean * sc;
}

__global__ void k_fc3(const float* __restrict__ w, const float* __restrict__ b,
                      const float* __restrict__ g3, const float* __restrict__ b3,
                      float* __restrict__ out) {
    __shared__ float red[256];
    __shared__ float z3[64];
    __shared__ float mv[2];
    int t = threadIdx.x;
    int r = t >> 2, p = t & 3;
    float s = 0.f;
    for (int k = p * 64; k < p * 64 + 64; k++) {
        float v = fmaxf(g_z2[r * 256 + k] * g_sc2[k] + g_sh2[k], 0.f);
        s += v * w[k];
    }
    red[t] = s;
    __syncthreads();
    if (p == 0) z3[r] = red[t] + red[t + 1] + red[t + 2] + red[t + 3] + b[0];
    __syncthreads();
    if (t == 0) {
        float m = 0.f;
        for (int i = 0; i < 64; i++) m += z3[i];
        m /= 64.f;
        float v = 0.f;
        for (int i = 0; i < 64; i++) { float d = z3[i] - m; v += d * d; }
        v /= 64.f;
        mv[0] = m; mv[1] = rsqrtf(v + EPSB);
    }
    __syncthreads();
    if (t < 64) out[t] = (z3[t] - mv[0]) * mv[1] * g3[0] + b3[0];
}

// ---------------- launch ----------------
extern "C" void kernel_launch(void* const* d_in, const int* in_sizes, int n_in,
                              void* d_out, int out_size) {
    const float* x        = (const float*)d_in[0];
    const float* gat_w    = (const float*)d_in[1];
    const float* gat_asrc = (const float*)d_in[2];
    const float* gat_adst = (const float*)d_in[3];
    const float* gat_bias = (const float*)d_in[4];
    const float* mlp_w    = (const float*)d_in[5];
    const float* mlp_b    = (const float*)d_in[6];
    const float* bn0_g    = (const float*)d_in[7];
    const float* bn0_b    = (const float*)d_in[8];
    const float* fc1_w    = (const float*)d_in[9];
    const float* fc1_b    = (const float*)d_in[10];
    const float* bn1_g    = (const float*)d_in[11];
    const float* bn1_b    = (const float*)d_in[12];
    const float* fc2_w    = (const float*)d_in[13];
    const float* fc2_b    = (const float*)d_in[14];
    const float* bn2_g    = (const float*)d_in[15];
    const float* bn2_b    = (const float*)d_in[16];
    const float* fc3_w    = (const float*)d_in[17];
    const float* fc3_b    = (const float*)d_in[18];
    const float* bn3_g    = (const float*)d_in[19];
    const float* bn3_b    = (const float*)d_in[20];
    const int*   ei       = (const int*)d_in[21];
    const int*   batch    = (const int*)d_in[22];
    float* out = (float*)d_out;

    // gemm0 is the 4th launch (profile slot)
    k_init<<<(Nn + 255) / 256, 256>>>();
    k_degree<<<(ET + 255) / 256, 256>>>(ei);
    k_scanA<<<SB, 256>>>();
    k_gemm<0><<<dim3((Nn + 127) / 128, HC / 128), 256>>>(
        x, gat_w, nullptr, nullptr, gat_asrc, gat_adst, Nn, 448, HC);
    k_scanB<<<SB, 256>>>();
    k_edge<<<(ET + 255) / 256, 256>>>(ei);
    k_agg<<<(Nn * 32 + 255) / 256, 256>>>();
    k_gemm<1><<<dim3((Nn + 127) / 128, Cc / 128), 256>>>(
        nullptr, mlp_w, mlp_b, gat_bias, nullptr, nullptr, Nn, HC, Cc);
    k_poolstats<<<200, 128>>>(batch);
    k_bn0_final<<<1, 128>>>(bn0_g, bn0_b);
    k_hpfix<<<(Gg * Cc + 255) / 256, 256>>>();
    k_fc1<<<(Gg * 512 + 255) / 256, 256>>>(fc1_w, fc1_b);
    k_bn1<<<2, 256>>>(bn1_g, bn1_b);
    k_fc2<<<(Gg * 256 + 255) / 256, 256>>>(fc2_w, fc2_b);
    k_bn2<<<1, 256>>>(bn2_g, bn2_b);
    k_fc3<<<1, 256>>>(fc3_w, fc3_b, bn3_g, bn3_b, out);
}

// round 14
// speedup vs baseline: 1.6383x; 1.3180x over previous
#include <cuda_runtime.h>
#include <cuda_fp16.h>
#include <mma.h>
#include <math.h>

using namespace nvcuda;

#define Nn 30000
#define NP 30016            // padded rows (multiple of 64)
#define Ee 960000
#define ET (Ee + Nn)
#define Hh 2
#define Cc 128
#define HC 256
#define Gg 64
#define EPSB 1e-5f
#define SB 118

// ---------------- scratch (device globals; no allocation allowed) ----------------
__device__ __half g_xph[(size_t)NP * HC];    // x @ gat_w (fp16; consumer = k_agg)
__device__ float  g_as[Nn * Hh];
__device__ float  g_ad[Nn * Hh];
__device__ int    g_deg[Nn];
__device__ int    g_ptr[Nn + 1];
__device__ int    g_cur[Nn];
__device__ int    g_blk[SB];
__device__ int4   g_csre[ET];
__device__ float  g_acc[(size_t)Nn * HC];
__device__ float  g_h1[(size_t)NP * Cc];     // raw (no bias); bias folded into poolstats
__device__ float  g_bnsum[2 * Cc];
__device__ float  g_sc0[Cc], g_sh0[Cc];
__device__ int    g_gcnt[Gg];
__device__ float  g_hp[Gg * Cc];
__device__ float  g_z1[Gg * 512];
__device__ float  g_sc1[512], g_sh1[512];
__device__ float  g_z2[Gg * 256];
__device__ float  g_sc2[256], g_sh2[256];

// ---------------- init ----------------
__global__ void k_init() {
    int i = blockIdx.x * blockDim.x + threadIdx.x;
    if (i < Nn)      g_deg[i] = 0;
    if (i < Gg * Cc) g_hp[i] = 0.f;
    if (i < 2 * Cc)  g_bnsum[i] = 0.f;
    if (i < Gg)      g_gcnt[i] = 0;
}

// ---------------- wmma GEMM: CTA 64x128, 8 warps (32x32 each), fp16 split ------
// MODE 0: g_xph(fp16) = x @ gat_w, K=448, Nc=256; epilogue: exact fp32 attn dots
// MODE 1: g_h1(fp32, no bias) = elu(g_acc + abias) @ mlp_w, K=256, Nc=128
#define APAD 40
#define BPAD 136
template <int MODE>
__global__ void __launch_bounds__(256, 2)
k_gemm(const float* __restrict__ Aext, const float* __restrict__ B,
       const float* __restrict__ abias,
       const float* __restrict__ asrc, const float* __restrict__ adst) {
    constexpr int K  = (MODE == 0) ? 448 : 256;
    constexpr int Nc = (MODE == 0) ? 256 : 128;
    // union: staging (A 64x40 h+l, B 32x136 h+l = 27648B) vs epilogue C (64x128 f32 = 32768B)
    __shared__ __align__(16) char smem_raw[32768];
    __shared__ float sb0[128], sb1[128];   // MODE0: asrc/adst slice
    __shared__ float sb_b[256];            // MODE1: abias
    __half* As_h = (__half*)smem_raw;                    // [64][40]
    __half* As_l = As_h + 64 * APAD;
    __half* Bs_h = As_l + 64 * APAD;                     // [32][136]
    __half* Bs_l = Bs_h + 32 * BPAD;

    int t = threadIdx.x;
    int w = t >> 5;
    int m_base = (w & 1) * 32, n_base = (w >> 1) * 32;
    int m0 = blockIdx.x * 64, n0 = blockIdx.y * 128;
    int h = n0 >> 7;
    const float* Ap = (MODE == 0) ? Aext : (const float*)g_acc;

    if (MODE == 0) {
        if (t < 128) { sb0[t] = asrc[(h << 7) + t]; sb1[t] = adst[(h << 7) + t]; }
    } else {
        if (t < 256) sb_b[t] = abias[t];
    }
    __syncthreads();

    wmma::fragment<wmma::accumulator, 16, 16, 16, float> fc[2][2];
#pragma unroll
    for (int i = 0; i < 2; i++)
#pragma unroll
        for (int j = 0; j < 2; j++) wmma::fill_fragment(fc[i][j], 0.f);

    for (int c = 0; c < K / 32; c++) {
        int k0 = c * 32;
        // stage regs first
        float4 av[2]; int arow[2], ak4[2];
        float4 bv[4]; int brow[4], bn4[4];
#pragma unroll
        for (int q = 0; q < 2; q++) {
            int idx = t + (q << 8);
            arow[q] = idx >> 3; ak4[q] = (idx & 7) << 2;
            int gr = m0 + arow[q];
            av[q] = make_float4(0.f, 0.f, 0.f, 0.f);
            if (gr < Nn) {
                av[q] = *(const float4*)(Ap + (size_t)gr * K + k0 + ak4[q]);
                if (MODE == 1) {
                    int gk = k0 + ak4[q];
                    float f[4] = {av[q].x, av[q].y, av[q].z, av[q].w};
#pragma unroll
                    for (int j = 0; j < 4; j++) {
                        float u = f[j] + sb_b[gk + j];
                        f[j] = u > 0.f ? u : (__expf(u) - 1.f);
                    }
                    av[q] = make_float4(f[0], f[1], f[2], f[3]);
                }
            }
        }
#pragma unroll
        for (int q = 0; q < 4; q++) {
            int idx = t + (q << 8);
            brow[q] = idx >> 5; bn4[q] = (idx & 31) << 2;
            bv[q] = *(const float4*)(B + (size_t)(k0 + brow[q]) * Nc + n0 + bn4[q]);
        }
        __syncthreads();   // prior frag reads done
#pragma unroll
        for (int q = 0; q < 2; q++) {
            float f[4] = {av[q].x, av[q].y, av[q].z, av[q].w};
            __half hh[4], ll[4];
#pragma unroll
            for (int j = 0; j < 4; j++) {
                hh[j] = __float2half(f[j]);
                ll[j] = __float2half(f[j] - __half2float(hh[j]));
            }
            *(uint2*)(As_h + arow[q] * APAD + ak4[q]) = *(uint2*)hh;
            *(uint2*)(As_l + arow[q] * APAD + ak4[q]) = *(uint2*)ll;
        }
#pragma unroll
        for (int q = 0; q < 4; q++) {
            float f[4] = {bv[q].x, bv[q].y, bv[q].z, bv[q].w};
            __half hh[4], ll[4];
#pragma unroll
            for (int j = 0; j < 4; j++) {
                hh[j] = __float2half(f[j]);
                ll[j] = __float2half(f[j] - __half2float(hh[j]));
            }
            *(uint2*)(Bs_h + brow[q] * BPAD + bn4[q]) = *(uint2*)hh;
            *(uint2*)(Bs_l + brow[q] * BPAD + bn4[q]) = *(uint2*)ll;
        }
        __syncthreads();

#pragma unroll
        for (int kk = 0; kk < 32; kk += 16) {
            wmma::fragment<wmma::matrix_a, 16, 16, 16, __half, wmma::row_major> fah[2], fal[2];
#pragma unroll
            for (int i = 0; i < 2; i++) {
                wmma::load_matrix_sync(fah[i], As_h + (m_base + i * 16) * APAD + kk, APAD);
                wmma::load_matrix_sync(fal[i], As_l + (m_base + i * 16) * APAD + kk, APAD);
            }
#pragma unroll
            for (int j = 0; j < 2; j++) {
                wmma::fragment<wmma::matrix_b, 16, 16, 16, __half, wmma::row_major> fbh, fbl;
                wmma::load_matrix_sync(fbh, Bs_h + kk * BPAD + n_base + j * 16, BPAD);
                wmma::load_matrix_sync(fbl, Bs_l + kk * BPAD + n_base + j * 16, BPAD);
#pragma unroll
                for (int i = 0; i < 2; i++) {
                    wmma::mma_sync(fc[i][j], fah[i], fbh, fc[i][j]);
                    wmma::mma_sync(fc[i][j], fah[i], fbl, fc[i][j]);
                    wmma::mma_sync(fc[i][j], fal[i], fbh, fc[i][j]);
                }
            }
        }
        __syncthreads();   // frag reads done before next staging overwrite
    }

    if (MODE == 1) {
        // direct fp32 store to padded g_h1 (no bias here)
#pragma unroll
        for (int i = 0; i < 2; i++)
#pragma unroll
            for (int j = 0; j < 2; j++)
                wmma::store_matrix_sync(
                    g_h1 + (size_t)(m0 + m_base + i * 16) * Cc + n_base + j * 16,
                    fc[i][j], Cc, wmma::mem_row_major);
    } else {
        // via smem: fp16 feature store + exact attention dots
        float* Cs = (float*)smem_raw;   // [64][128]
#pragma unroll
        for (int i = 0; i < 2; i++)
#pragma unroll
            for (int j = 0; j < 2; j++)
                wmma::store_matrix_sync(Cs + (m_base + i * 16) * 128 + n_base + j * 16,
                                        fc[i][j], 128, wmma::mem_row_major);
        __syncthreads();
        int r = t >> 2, q = t & 3;
        int gr = m0 + r;
        int c0 = q * 32;
        float s = 0.f, d = 0.f;
        __half hbuf[32];
#pragma unroll
        for (int c = 0; c < 32; c += 4) {
            float4 v = *(const float4*)(Cs + r * 128 + c0 + c);
            float vv[4] = {v.x, v.y, v.z, v.w};
#pragma unroll
            for (int j = 0; j < 4; j++) {
                s += vv[j] * sb0[c0 + c + j];
                d += vv[j] * sb1[c0 + c + j];
                hbuf[c + j] = __float2half(vv[j]);
            }
        }
        // rows padded: store unconditionally (gr < NP always)
        *(uint4*)(g_xph + (size_t)gr * HC + n0 + c0)      = *(uint4*)(hbuf);
        *(uint4*)(g_xph + (size_t)gr * HC + n0 + c0 + 8)  = *(uint4*)(hbuf + 8);
        *(uint4*)(g_xph + (size_t)gr * HC + n0 + c0 + 16) = *(uint4*)(hbuf + 16);
        *(uint4*)(g_xph + (size_t)gr * HC + n0 + c0 + 24) = *(uint4*)(hbuf + 24);
        s += __shfl_xor_sync(0xFFFFFFFFu, s, 1);
        s += __shfl_xor_sync(0xFFFFFFFFu, s, 2);
        d += __shfl_xor_sync(0xFFFFFFFFu, d, 1);
        d += __shfl_xor_sync(0xFFFFFFFFu, d, 2);
        if (q == 0 && gr < Nn) {
            g_as[gr * 2 + h] = s;
            g_ad[gr * 2 + h] = d;
        }
    }
}

// ---------------- degree count ----------------
__global__ void k_degree(const int* __restrict__ ei) {
    int i = blockIdx.x * blockDim.x + threadIdx.x;
    if (i >= ET) return;
    int dst = (i < Ee) ? ei[Ee + i] : (i - Ee);
    atomicAdd(&g_deg[dst], 1);
}

// ---------------- parallel scan, phase A ----------------
__global__ void k_scanA() {
    __shared__ int sh[256];
    int b = blockIdx.x, t = threadIdx.x;
    int i = b * 256 + t;
    int d = (i < Nn) ? g_deg[i] : 0;
    sh[t] = d;
    __syncthreads();
    for (int off = 1; off < 256; off <<= 1) {
        int v = (t >= off) ? sh[t - off] : 0;
        __syncthreads();
        sh[t] += v;
        __syncthreads();
    }
    if (i < Nn) g_ptr[i] = sh[t] - d;
    if (t == 255) g_blk[b] = sh[255];
}

// ---------------- parallel scan, phase B ----------------
__global__ void k_scanB() {
    __shared__ int sb[128];
    int b = blockIdx.x, t = threadIdx.x;
    if (t < 128) sb[t] = (t < SB) ? g_blk[t] : 0;
    __syncthreads();
    for (int off = 1; off < 128; off <<= 1) {
        int v = 0;
        if (t < 128 && t >= off) v = sb[t - off];
        __syncthreads();
        if (t < 128) sb[t] += v;
        __syncthreads();
    }
    int offb = (b > 0) ? sb[b - 1] : 0;
    int i = b * 256 + t;
    if (i < Nn) {
        int p = g_ptr[i] + offb;
        g_ptr[i] = p;
        g_cur[i] = p;
        if (i == Nn - 1) g_ptr[Nn] = p + g_deg[i];
    }
}

// ---------------- fused edge: logit -> exp -> CSR scatter ----------
__global__ void k_edge(const int* __restrict__ ei) {
    int i = blockIdx.x * blockDim.x + threadIdx.x;
    if (i >= ET) return;
    int src, dst;
    if (i < Ee) { src = ei[i]; dst = ei[Ee + i]; }
    else        { src = dst = i - Ee; }
    float2 as = *(const float2*)(g_as + src * 2);
    float2 ad = *(const float2*)(g_ad + dst * 2);
    float l0 = as.x + ad.x; l0 = l0 > 0.f ? l0 : 0.2f * l0;
    float l1 = as.y + ad.y; l1 = l1 > 0.f ? l1 : 0.2f * l1;
    float w0 = __expf(l0), w1 = __expf(l1);
    int pos = atomicAdd(&g_cur[dst], 1);
    g_csre[pos] = make_int4(src, __float_as_int(w0), __float_as_int(w1), 0);
}

// ---------------- aggregation: warp/dst, fp16 gather ---------
__device__ __forceinline__ void fma8h(float* a, uint4 v, float wt) {
    __half2* h = (__half2*)&v;
#pragma unroll
    for (int i = 0; i < 4; i++) {
        float2 f = __half22float2(h[i]);
        a[2 * i]     += f.x * wt;
        a[2 * i + 1] += f.y * wt;
    }
}
__global__ void __launch_bounds__(256) k_agg() {
    int w = (blockIdx.x * blockDim.x + threadIdx.x) >> 5;
    int lane = threadIdx.x & 31;
    if (w >= Nn) return;
    int beg = g_ptr[w], end = g_ptr[w + 1];
    const uint4* xh = (const uint4*)g_xph;
    bool hside = lane >= 16;
    float acc[8] = {0.f, 0.f, 0.f, 0.f, 0.f, 0.f, 0.f, 0.f};
    float ws = 0.f;
    int e = beg;
    for (; e + 1 < end; e += 2) {
        int4 r0 = __ldg(&g_csre[e]);
        int4 r1 = __ldg(&g_csre[e + 1]);
        uint4 v0 = __ldg(xh + (size_t)r0.x * 32 + lane);
        uint4 v1 = __ldg(xh + (size_t)r1.x * 32 + lane);
        float w0 = __int_as_float(hside ? r0.z : r0.y);
        float w1 = __int_as_float(hside ? r1.z : r1.y);
        fma8h(acc, v0, w0);
        fma8h(acc, v1, w1);
        ws += w0 + w1;
    }
    if (e < end) {
        int4 r0 = __ldg(&g_csre[e]);
        uint4 v0 = __ldg(xh + (size_t)r0.x * 32 + lane);
        float w0 = __int_as_float(hside ? r0.z : r0.y);
        fma8h(acc, v0, w0);
        ws += w0;
    }
    float rd = 1.f / ws;
    float* op = g_acc + (size_t)w * HC + lane * 8;
    *(float4*)op       = make_float4(acc[0] * rd, acc[1] * rd, acc[2] * rd, acc[3] * rd);
    *(float4*)(op + 4) = make_float4(acc[4] * rd, acc[5] * rd, acc[6] * rd, acc[7] * rd);
}

// ---------------- fused pool(raw) + BN0 stats (+mlp bias) ---------------
__global__ void k_poolstats(const int* __restrict__ batch, const float* __restrict__ mb) {
    int c = threadIdx.x;  // 128
    int per = (Nn + gridDim.x - 1) / gridDim.x;
    int s = blockIdx.x * per;
    int e = min(Nn, s + per);
    if (s >= e) return;
    float bias = __ldg(mb + c);
    float sum = 0.f, sum2 = 0.f;
    int cur = batch[s];
    float a = 0.f;
    int cnt = 0;
    for (int n = s; n < e; n++) {
        float v = g_h1[(size_t)n * Cc + c] + bias;
        sum += v; sum2 += v * v;
        int gi = batch[n];
        if (gi != cur) {
            atomicAdd(&g_hp[cur * Cc + c], a);
            if (c == 0) atomicAdd(&g_gcnt[cur], cnt);
            a = 0.f; cnt = 0; cur = gi;
        }
        a += v; cnt++;
    }
    atomicAdd(&g_hp[cur * Cc + c], a);
    if (c == 0) atomicAdd(&g_gcnt[cur], cnt);
    atomicAdd(&g_bnsum[c], sum);
    atomicAdd(&g_bnsum[Cc + c], sum2);
}

__global__ void k_bn0_final(const float* __restrict__ g, const float* __restrict__ b) {
    int c = threadIdx.x;
    if (c < Cc) {
        float mean = g_bnsum[c] / (float)Nn;
        float var  = fmaxf(g_bnsum[Cc + c] / (float)Nn - mean * mean, 0.f);
        float sc = g[c] * rsqrtf(var + EPSB);
        g_sc0[c] = sc;
        g_sh0[c] = b[c] - mean * sc;
    }
}

__global__ void k_hpfix() {
    int i = blockIdx.x * blockDim.x + threadIdx.x;
    if (i < Gg * Cc) {
        int g = i >> 7, c = i & 127;
        g_hp[i] = g_hp[i] * g_sc0[c] + (float)g_gcnt[g] * g_sh0[c];
    }
}

// ---------------- FC stack ----------------
__global__ void k_fc1(const float* __restrict__ w, const float* __restrict__ b) {
    int idx = blockIdx.x * blockDim.x + threadIdx.x;
    if (idx >= Gg * 512) return;
    int c = idx & 511, r = idx >> 9;
    float s = b[c];
#pragma unroll 8
    for (int k = 0; k < Cc; k++) s += g_hp[r * Cc + k] * w[k * 512 + c];
    g_z1[idx] = s;
}

__global__ void k_bn1(const float* __restrict__ g, const float* __restrict__ b) {
    int c = blockIdx.x * blockDim.x + threadIdx.x;
    if (c >= 512) return;
    float s = 0.f, s2 = 0.f;
    for (int r = 0; r < Gg; r++) { float v = g_z1[r * 512 + c]; s += v; s2 += v * v; }
    float mean = s / (float)Gg;
    float var = fmaxf(s2 / (float)Gg - mean * mean, 0.f);
    float sc = g[c] * rsqrtf(var + EPSB);
    g_sc1[c] = sc; g_sh1[c] = b[c] - mean * sc;
}

__global__ void k_fc2(const float* __restrict__ w, const float* __restrict__ b) {
    int idx = blockIdx.x * blockDim.x + threadIdx.x;
    if (idx >= Gg * 256) return;
    int c = idx & 255, r = idx >> 8;
    float s = b[c];
#pragma unroll 8
    for (int k = 0; k < 512; k++) {
        float v = fmaxf(g_z1[r * 512 + k] * g_sc1[k] + g_sh1[k], 0.f);
        s += v * w[k * 256 + c];
    }
    g_z2[idx] = s;
}

__global__ void k_bn2(const float* __restrict__ g, const float* __restrict__ b) {
    int c = threadIdx.x;
    if (c >= 256) return;
    float s = 0.f, s2 = 0.f;
    for (int r = 0; r < Gg; r++) { float v = g_z2[r * 256 + c]; s += v; s2 += v * v; }
    float mean = s / (float)Gg;
    float var = fmaxf(s2 / (float)Gg - mean * mean, 0.f);
    float sc = g[c] * rsqrtf(var + EPSB);
    g_sc2[c] = sc; g_sh2[c] = b[c] - mean * sc;
}

__global__ void k_fc3(const float* __restrict__ w, const float* __restrict__ b,
                      const float* __restrict__ g3, const float* __restrict__ b3,
                      float* __restrict__ out) {
    __shared__ float red[256];
    __shared__ float z3[64];
    __shared__ float mv[2];
    int t = threadIdx.x;
    int r = t >> 2, p = t & 3;
    float s = 0.f;
    for (int k = p * 64; k < p * 64 + 64; k++) {
        float v = fmaxf(g_z2[r * 256 + k] * g_sc2[k] + g_sh2[k], 0.f);
        s += v * w[k];
    }
    red[t] = s;
    __syncthreads();
    if (p == 0) z3[r] = red[t] + red[t + 1] + red[t + 2] + red[t + 3] + b[0];
    __syncthreads();
    if (t == 0) {
        float m = 0.f;
        for (int i = 0; i < 64; i++) m += z3[i];
        m /= 64.f;
        float v = 0.f;
        for (int i = 0; i < 64; i++) { float d = z3[i] - m; v += d * d; }
        v /= 64.f;
        mv[0] = m; mv[1] = rsqrtf(v + EPSB);
    }
    __syncthreads();
    if (t < 64) out[t] = (z3[t] - mv[0]) * mv[1] * g3[0] + b3[0];
}

// ---------------- launch ----------------
extern "C" void kernel_launch(void* const* d_in, const int* in_sizes, int n_in,
                              void* d_out, int out_size) {
    const float* x        = (const float*)d_in[0];
    const float* gat_w    = (const float*)d_in[1];
    const float* gat_asrc = (const float*)d_in[2];
    const float* gat_adst = (const float*)d_in[3];
    const float* gat_bias = (const float*)d_in[4];
    const float* mlp_w    = (const float*)d_in[5];
    const float* mlp_b    = (const float*)d_in[6];
    const float* bn0_g    = (const float*)d_in[7];
    const float* bn0_b    = (const float*)d_in[8];
    const float* fc1_w    = (const float*)d_in[9];
    const float* fc1_b    = (const float*)d_in[10];
    const float* bn1_g    = (const float*)d_in[11];
    const float* bn1_b    = (const float*)d_in[12];
    const float* fc2_w    = (const float*)d_in[13];
    const float* fc2_b    = (const float*)d_in[14];
    const float* bn2_g    = (const float*)d_in[15];
    const float* bn2_b    = (const float*)d_in[16];
    const float* fc3_w    = (const float*)d_in[17];
    const float* fc3_b    = (const float*)d_in[18];
    const float* bn3_g    = (const float*)d_in[19];
    const float* bn3_b    = (const float*)d_in[20];
    const int*   ei       = (const int*)d_in[21];
    const int*   batch    = (const int*)d_in[22];
    float* out = (float*)d_out;

    // gemm0 is the 4th launch (profile slot)
    k_init<<<(Nn + 255) / 256, 256>>>();
    k_degree<<<(ET + 255) / 256, 256>>>(ei);
    k_scanA<<<SB, 256>>>();
    k_gemm<0><<<dim3(NP / 64, 2), 256>>>(x, gat_w, nullptr, gat_asrc, gat_adst);
    k_scanB<<<SB, 256>>>();
    k_edge<<<(ET + 255) / 256, 256>>>(ei);
    k_agg<<<(Nn * 32 + 255) / 256, 256>>>();
    k_gemm<1><<<dim3(NP / 64, 1), 256>>>(nullptr, mlp_w, gat_bias, nullptr, nullptr);
    k_poolstats<<<200, 128>>>(batch, mlp_b);
    k_bn0_final<<<1, 128>>>(bn0_g, bn0_b);
    k_hpfix<<<(Gg * Cc + 255) / 256, 256>>>();
    k_fc1<<<(Gg * 512 + 255) / 256, 256>>>(fc1_w, fc1_b);
    k_bn1<<<2, 256>>>(bn1_g, bn1_b);
    k_fc2<<<(Gg * 256 + 255) / 256, 256>>>(fc2_w, fc2_b);
    k_bn2<<<1, 256>>>(bn2_g, bn2_b);
    k_fc3<<<1, 256>>>(fc3_w, fc3_b, bn3_g, bn3_b, out);
}

// round 15
// speedup vs baseline: 1.6566x; 1.0112x over previous
#include <cuda_runtime.h>
#include <cuda_fp16.h>
#include <mma.h>
#include <math.h>

using namespace nvcuda;

#define Nn 30000
#define NP 30016            // padded rows (multiple of 64)
#define Ee 960000
#define ET (Ee + Nn)
#define Hh 2
#define Cc 128
#define HC 256
#define Gg 64
#define EPSB 1e-5f
#define SB 118

// ---------------- scratch (device globals; no allocation allowed) ----------------
__device__ __half g_xph[(size_t)NP * HC];    // x @ gat_w (fp16; consumer = k_agg)
__device__ float  g_as[Nn * Hh];
__device__ float  g_ad[Nn * Hh];
__device__ int    g_deg[Nn];
__device__ int    g_ptr[Nn + 1];
__device__ int    g_cur[Nn];
__device__ int    g_blk[SB];
__device__ int4   g_csre[ET];
__device__ __half g_acch[(size_t)NP * HC];   // elu(agg + gat_bias) hi (gemm1 A)
__device__ __half g_accl[(size_t)NP * HC];   // ... lo
__device__ __half g_w0h[448 * 256], g_w0l[448 * 256];  // gat_w split
__device__ __half g_w1h[256 * 128], g_w1l[256 * 128];  // mlp_w split
__device__ float  g_h1[(size_t)NP * Cc];     // raw (no bias); bias folded into poolstats
__device__ float  g_bnsum[2 * Cc];
__device__ float  g_sc0[Cc], g_sh0[Cc];
__device__ int    g_gcnt[Gg];
__device__ float  g_hp[Gg * Cc];
__device__ float  g_z1[Gg * 512];
__device__ float  g_sc1[512], g_sh1[512];
__device__ float  g_z2[Gg * 256];
__device__ float  g_sc2[256], g_sh2[256];

// ---------------- init ----------------
__global__ void k_init() {
    int i = blockIdx.x * blockDim.x + threadIdx.x;
    if (i < Nn)      g_deg[i] = 0;
    if (i < Gg * Cc) g_hp[i] = 0.f;
    if (i < 2 * Cc)  g_bnsum[i] = 0.f;
    if (i < Gg)      g_gcnt[i] = 0;
}

// ---------------- weight pre-split (one cheap pass) ----------------
__global__ void k_prepw(const float* __restrict__ w0, const float* __restrict__ w1) {
    int i = blockIdx.x * blockDim.x + threadIdx.x;
    if (i < 448 * 256) {
        float v = w0[i];
        __half h = __float2half(v);
        g_w0h[i] = h;
        g_w0l[i] = __float2half(v - __half2float(h));
    }
    if (i < 256 * 128) {
        float v = w1[i];
        __half h = __float2half(v);
        g_w1h[i] = h;
        g_w1l[i] = __float2half(v - __half2float(h));
    }
}

// ---------------- wmma GEMM: CTA 64x128, 8 warps (32x32 each), fp16 split ------
// MODE 0: g_xph(fp16) = x @ gat_w (B pre-split); epilogue: exact fp32 attn dots
// MODE 1: g_h1(fp32) = g_acch/l @ mlp_w (A and B pre-split; ELU already applied)
#define APAD 40
#define BPAD 136
template <int MODE>
__global__ void __launch_bounds__(256, 2)
k_gemm(const float* __restrict__ Aext,
       const float* __restrict__ asrc, const float* __restrict__ adst) {
    constexpr int K  = (MODE == 0) ? 448 : 256;
    constexpr int Nc = (MODE == 0) ? 256 : 128;
    __shared__ __align__(16) char smem_raw[32768];
    __shared__ float sb0[128], sb1[128];
    __half* As_h = (__half*)smem_raw;                    // [64][40]
    __half* As_l = As_h + 64 * APAD;
    __half* Bs_h = As_l + 64 * APAD;                     // [32][136]
    __half* Bs_l = Bs_h + 32 * BPAD;

    int t = threadIdx.x;
    int w = t >> 5;
    int m_base = (w & 1) * 32, n_base = (w >> 1) * 32;
    int m0 = blockIdx.x * 64, n0 = blockIdx.y * 128;
    int h = n0 >> 7;
    const __half* Bh = (MODE == 0) ? g_w0h : g_w1h;
    const __half* Bl = (MODE == 0) ? g_w0l : g_w1l;

    if (MODE == 0) {
        if (t < 128) { sb0[t] = asrc[(h << 7) + t]; sb1[t] = adst[(h << 7) + t]; }
        __syncthreads();
    }

    wmma::fragment<wmma::accumulator, 16, 16, 16, float> fc[2][2];
#pragma unroll
    for (int i = 0; i < 2; i++)
#pragma unroll
        for (int j = 0; j < 2; j++) wmma::fill_fragment(fc[i][j], 0.f);

    // A-staging indices
    int arow_f = 0, ak4_f = 0;        // MODE0 (fp32 src): 2 float4/thread
    int arow_h = t >> 2, ak8_h = (t & 3) << 3;   // MODE1 (fp16 src): 1 uint4/thread
    // B-staging: 2 uint4/thread for h and l each
    for (int c = 0; c < K / 32; c++) {
        int k0 = c * 32;
        float4 av[2];
        uint4 avh, avl;
        uint4 bvh[2], bvl[2];
        if (MODE == 0) {
#pragma unroll
            for (int q = 0; q < 2; q++) {
                int idx = t + (q << 8);
                int ar = idx >> 3, ak = (idx & 7) << 2;
                if (q == 0) { arow_f = ar; ak4_f = ak; }
                int gr = m0 + ar;
                av[q] = make_float4(0.f, 0.f, 0.f, 0.f);
                if (gr < Nn)
                    av[q] = *(const float4*)(Aext + (size_t)gr * K + k0 + ak);
            }
        } else {
            avh = *(const uint4*)(g_acch + (size_t)(m0 + arow_h) * K + k0 + ak8_h);
            avl = *(const uint4*)(g_accl + (size_t)(m0 + arow_h) * K + k0 + ak8_h);
        }
#pragma unroll
        for (int q = 0; q < 2; q++) {
            int idx = t + (q << 8);
            int br = idx >> 4, bc8 = (idx & 15) << 3;
            bvh[q] = *(const uint4*)(Bh + (size_t)(k0 + br) * Nc + n0 + bc8);
            bvl[q] = *(const uint4*)(Bl + (size_t)(k0 + br) * Nc + n0 + bc8);
        }
        __syncthreads();
        if (MODE == 0) {
#pragma unroll
            for (int q = 0; q < 2; q++) {
                int idx = t + (q << 8);
                int ar = idx >> 3, ak = (idx & 7) << 2;
                float f[4] = {av[q].x, av[q].y, av[q].z, av[q].w};
                __half hh[4], ll[4];
#pragma unroll
                for (int j = 0; j < 4; j++) {
                    hh[j] = __float2half(f[j]);
                    ll[j] = __float2half(f[j] - __half2float(hh[j]));
                }
                *(uint2*)(As_h + ar * APAD + ak) = *(uint2*)hh;
                *(uint2*)(As_l + ar * APAD + ak) = *(uint2*)ll;
            }
        } else {
            *(uint4*)(As_h + arow_h * APAD + ak8_h) = avh;
            *(uint4*)(As_l + arow_h * APAD + ak8_h) = avl;
        }
#pragma unroll
        for (int q = 0; q < 2; q++) {
            int idx = t + (q << 8);
            int br = idx >> 4, bc8 = (idx & 15) << 3;
            *(uint4*)(Bs_h + br * BPAD + bc8) = bvh[q];
            *(uint4*)(Bs_l + br * BPAD + bc8) = bvl[q];
        }
        __syncthreads();

#pragma unroll
        for (int kk = 0; kk < 32; kk += 16) {
            wmma::fragment<wmma::matrix_a, 16, 16, 16, __half, wmma::row_major> fah[2], fal[2];
#pragma unroll
            for (int i = 0; i < 2; i++) {
                wmma::load_matrix_sync(fah[i], As_h + (m_base + i * 16) * APAD + kk, APAD);
                wmma::load_matrix_sync(fal[i], As_l + (m_base + i * 16) * APAD + kk, APAD);
            }
#pragma unroll
            for (int j = 0; j < 2; j++) {
                wmma::fragment<wmma::matrix_b, 16, 16, 16, __half, wmma::row_major> fbh, fbl;
                wmma::load_matrix_sync(fbh, Bs_h + kk * BPAD + n_base + j * 16, BPAD);
                wmma::load_matrix_sync(fbl, Bs_l + kk * BPAD + n_base + j * 16, BPAD);
#pragma unroll
                for (int i = 0; i < 2; i++) {
                    wmma::mma_sync(fc[i][j], fah[i], fbh, fc[i][j]);
                    wmma::mma_sync(fc[i][j], fah[i], fbl, fc[i][j]);
                    wmma::mma_sync(fc[i][j], fal[i], fbh, fc[i][j]);
                }
            }
        }
        __syncthreads();
    }

    if (MODE == 1) {
#pragma unroll
        for (int i = 0; i < 2; i++)
#pragma unroll
            for (int j = 0; j < 2; j++)
                wmma::store_matrix_sync(
                    g_h1 + (size_t)(m0 + m_base + i * 16) * Cc + n_base + j * 16,
                    fc[i][j], Cc, wmma::mem_row_major);
    } else {
        float* Cs = (float*)smem_raw;   // [64][128]
#pragma unroll
        for (int i = 0; i < 2; i++)
#pragma unroll
            for (int j = 0; j < 2; j++)
                wmma::store_matrix_sync(Cs + (m_base + i * 16) * 128 + n_base + j * 16,
                                        fc[i][j], 128, wmma::mem_row_major);
        __syncthreads();
        int r = t >> 2, q = t & 3;
        int gr = m0 + r;
        int c0 = q * 32;
        float s = 0.f, d = 0.f;
        __half hbuf[32];
#pragma unroll
        for (int c = 0; c < 32; c += 4) {
            float4 v = *(const float4*)(Cs + r * 128 + c0 + c);
            float vv[4] = {v.x, v.y, v.z, v.w};
#pragma unroll
            for (int j = 0; j < 4; j++) {
                s += vv[j] * sb0[c0 + c + j];
                d += vv[j] * sb1[c0 + c + j];
                hbuf[c + j] = __float2half(vv[j]);
            }
        }
        *(uint4*)(g_xph + (size_t)gr * HC + n0 + c0)      = *(uint4*)(hbuf);
        *(uint4*)(g_xph + (size_t)gr * HC + n0 + c0 + 8)  = *(uint4*)(hbuf + 8);
        *(uint4*)(g_xph + (size_t)gr * HC + n0 + c0 + 16) = *(uint4*)(hbuf + 16);
        *(uint4*)(g_xph + (size_t)gr * HC + n0 + c0 + 24) = *(uint4*)(hbuf + 24);
        s += __shfl_xor_sync(0xFFFFFFFFu, s, 1);
        s += __shfl_xor_sync(0xFFFFFFFFu, s, 2);
        d += __shfl_xor_sync(0xFFFFFFFFu, d, 1);
        d += __shfl_xor_sync(0xFFFFFFFFu, d, 2);
        if (q == 0 && gr < Nn) {
            g_as[gr * 2 + h] = s;
            g_ad[gr * 2 + h] = d;
        }
    }
}

// ---------------- degree count ----------------
__global__ void k_degree(const int* __restrict__ ei) {
    int i = blockIdx.x * blockDim.x + threadIdx.x;
    if (i >= ET) return;
    int dst = (i < Ee) ? ei[Ee + i] : (i - Ee);
    atomicAdd(&g_deg[dst], 1);
}

// ---------------- parallel scan ----------------
__global__ void k_scanA() {
    __shared__ int sh[256];
    int b = blockIdx.x, t = threadIdx.x;
    int i = b * 256 + t;
    int d = (i < Nn) ? g_deg[i] : 0;
    sh[t] = d;
    __syncthreads();
    for (int off = 1; off < 256; off <<= 1) {
        int v = (t >= off) ? sh[t - off] : 0;
        __syncthreads();
        sh[t] += v;
        __syncthreads();
    }
    if (i < Nn) g_ptr[i] = sh[t] - d;
    if (t == 255) g_blk[b] = sh[255];
}
__global__ void k_scanB() {
    __shared__ int sb[128];
    int b = blockIdx.x, t = threadIdx.x;
    if (t < 128) sb[t] = (t < SB) ? g_blk[t] : 0;
    __syncthreads();
    for (int off = 1; off < 128; off <<= 1) {
        int v = 0;
        if (t < 128 && t >= off) v = sb[t - off];
        __syncthreads();
        if (t < 128) sb[t] += v;
        __syncthreads();
    }
    int offb = (b > 0) ? sb[b - 1] : 0;
    int i = b * 256 + t;
    if (i < Nn) {
        int p = g_ptr[i] + offb;
        g_ptr[i] = p;
        g_cur[i] = p;
        if (i == Nn - 1) g_ptr[Nn] = p + g_deg[i];
    }
}

// ---------------- fused edge ----------
__global__ void k_edge(const int* __restrict__ ei) {
    int i = blockIdx.x * blockDim.x + threadIdx.x;
    if (i >= ET) return;
    int src, dst;
    if (i < Ee) { src = ei[i]; dst = ei[Ee + i]; }
    else        { src = dst = i - Ee; }
    float2 as = *(const float2*)(g_as + src * 2);
    float2 ad = *(const float2*)(g_ad + dst * 2);
    float l0 = as.x + ad.x; l0 = l0 > 0.f ? l0 : 0.2f * l0;
    float l1 = as.y + ad.y; l1 = l1 > 0.f ? l1 : 0.2f * l1;
    float w0 = __expf(l0), w1 = __expf(l1);
    int pos = atomicAdd(&g_cur[dst], 1);
    g_csre[pos] = make_int4(src, __float_as_int(w0), __float_as_int(w1), 0);
}

// ---------------- aggregation: warp/dst; epilogue does bias+ELU+fp16 split ------
__device__ __forceinline__ void fma8h(float* a, uint4 v, float wt) {
    __half2* h = (__half2*)&v;
#pragma unroll
    for (int i = 0; i < 4; i++) {
        float2 f = __half22float2(h[i]);
        a[2 * i]     += f.x * wt;
        a[2 * i + 1] += f.y * wt;
    }
}
__global__ void __launch_bounds__(256) k_agg(const float* __restrict__ gbias) {
    int w = (blockIdx.x * blockDim.x + threadIdx.x) >> 5;
    int lane = threadIdx.x & 31;
    if (w >= Nn) return;
    int beg = g_ptr[w], end = g_ptr[w + 1];
    const uint4* xh = (const uint4*)g_xph;
    bool hside = lane >= 16;
    float acc[8] = {0.f, 0.f, 0.f, 0.f, 0.f, 0.f, 0.f, 0.f};
    float ws = 0.f;
    int e = beg;
    for (; e + 1 < end; e += 2) {
        int4 r0 = __ldg(&g_csre[e]);
        int4 r1 = __ldg(&g_csre[e + 1]);
        uint4 v0 = __ldg(xh + (size_t)r0.x * 32 + lane);
        uint4 v1 = __ldg(xh + (size_t)r1.x * 32 + lane);
        float w0 = __int_as_float(hside ? r0.z : r0.y);
        float w1 = __int_as_float(hside ? r1.z : r1.y);
        fma8h(acc, v0, w0);
        fma8h(acc, v1, w1);
        ws += w0 + w1;
    }
    if (e < end) {
        int4 r0 = __ldg(&g_csre[e]);
        uint4 v0 = __ldg(xh + (size_t)r0.x * 32 + lane);
        float w0 = __int_as_float(hside ? r0.z : r0.y);
        fma8h(acc, v0, w0);
        ws += w0;
    }
    float rd = 1.f / ws;
    __half hb[8], lb[8];
#pragma unroll
    for (int i = 0; i < 8; i++) {
        float u = acc[i] * rd + __ldg(gbias + lane * 8 + i);
        u = u > 0.f ? u : (__expf(u) - 1.f);
        hb[i] = __float2half(u);
        lb[i] = __float2half(u - __half2float(hb[i]));
    }
    *(uint4*)(g_acch + (size_t)w * HC + lane * 8) = *(uint4*)hb;
    *(uint4*)(g_accl + (size_t)w * HC + lane * 8) = *(uint4*)lb;
}

// ---------------- fused pool(raw) + BN0 stats (+mlp bias) ---------------
__global__ void k_poolstats(const int* __restrict__ batch, const float* __restrict__ mb) {
    int c = threadIdx.x;
    int per = (Nn + gridDim.x - 1) / gridDim.x;
    int s = blockIdx.x * per;
    int e = min(Nn, s + per);
    if (s >= e) return;
    float bias = __ldg(mb + c);
    float sum = 0.f, sum2 = 0.f;
    int cur = batch[s];
    float a = 0.f;
    int cnt = 0;
    for (int n = s; n < e; n++) {
        float v = g_h1[(size_t)n * Cc + c] + bias;
        sum += v; sum2 += v * v;
        int gi = batch[n];
        if (gi != cur) {
            atomicAdd(&g_hp[cur * Cc + c], a);
            if (c == 0) atomicAdd(&g_gcnt[cur], cnt);
            a = 0.f; cnt = 0; cur = gi;
        }
        a += v; cnt++;
    }
    atomicAdd(&g_hp[cur * Cc + c], a);
    if (c == 0) atomicAdd(&g_gcnt[cur], cnt);
    atomicAdd(&g_bnsum[c], sum);
    atomicAdd(&g_bnsum[Cc + c], sum2);
}

__global__ void k_bn0_final(const float* __restrict__ g, const float* __restrict__ b) {
    int c = threadIdx.x;
    if (c < Cc) {
        float mean = g_bnsum[c] / (float)Nn;
        float var  = fmaxf(g_bnsum[Cc + c] / (float)Nn - mean * mean, 0.f);
        float sc = g[c] * rsqrtf(var + EPSB);
        g_sc0[c] = sc;
        g_sh0[c] = b[c] - mean * sc;
    }
}

__global__ void k_hpfix() {
    int i = blockIdx.x * blockDim.x + threadIdx.x;
    if (i < Gg * Cc) {
        int g = i >> 7, c = i & 127;
        g_hp[i] = g_hp[i] * g_sc0[c] + (float)g_gcnt[g] * g_sh0[c];
    }
}

// ---------------- FC stack ----------------
__global__ void k_fc1(const float* __restrict__ w, const float* __restrict__ b) {
    int idx = blockIdx.x * blockDim.x + threadIdx.x;
    if (idx >= Gg * 512) return;
    int c = idx & 511, r = idx >> 9;
    float s = b[c];
#pragma unroll 8
    for (int k = 0; k < Cc; k++) s += g_hp[r * Cc + k] * w[k * 512 + c];
    g_z1[idx] = s;
}

__global__ void k_bn1(const float* __restrict__ g, const float* __restrict__ b) {
    int c = blockIdx.x * blockDim.x + threadIdx.x;
    if (c >= 512) return;
    float s = 0.f, s2 = 0.f;
    for (int r = 0; r < Gg; r++) { float v = g_z1[r * 512 + c]; s += v; s2 += v * v; }
    float mean = s / (float)Gg;
    float var = fmaxf(s2 / (float)Gg - mean * mean, 0.f);
    float sc = g[c] * rsqrtf(var + EPSB);
    g_sc1[c] = sc; g_sh1[c] = b[c] - mean * sc;
}

__global__ void k_fc2(const float* __restrict__ w, const float* __restrict__ b) {
    int idx = blockIdx.x * blockDim.x + threadIdx.x;
    if (idx >= Gg * 256) return;
    int c = idx & 255, r = idx >> 8;
    float s = b[c];
#pragma unroll 8
    for (int k = 0; k < 512; k++) {
        float v = fmaxf(g_z1[r * 512 + k] * g_sc1[k] + g_sh1[k], 0.f);
        s += v * w[k * 256 + c];
    }
    g_z2[idx] = s;
}

__global__ void k_bn2(const float* __restrict__ g, const float* __restrict__ b) {
    int c = threadIdx.x;
    if (c >= 256) return;
    float s = 0.f, s2 = 0.f;
    for (int r = 0; r < Gg; r++) { float v = g_z2[r * 256 + c]; s += v; s2 += v * v; }
    float mean = s / (float)Gg;
    float var = fmaxf(s2 / (float)Gg - mean * mean, 0.f);
    float sc = g[c] * rsqrtf(var + EPSB);
    g_sc2[c] = sc; g_sh2[c] = b[c] - mean * sc;
}

__global__ void k_fc3(const float* __restrict__ w, const float* __restrict__ b,
                      const float* __restrict__ g3, const float* __restrict__ b3,
                      float* __restrict__ out) {
    __shared__ float red[256];
    __shared__ float z3[64];
    __shared__ float mv[2];
    int t = threadIdx.x;
    int r = t >> 2, p = t & 3;
    float s = 0.f;
    for (int k = p * 64; k < p * 64 + 64; k++) {
        float v = fmaxf(g_z2[r * 256 + k] * g_sc2[k] + g_sh2[k], 0.f);
        s += v * w[k];
    }
    red[t] = s;
    __syncthreads();
    if (p == 0) z3[r] = red[t] + red[t + 1] + red[t + 2] + red[t + 3] + b[0];
    __syncthreads();
    if (t == 0) {
        float m = 0.f;
        for (int i = 0; i < 64; i++) m += z3[i];
        m /= 64.f;
        float v = 0.f;
        for (int i = 0; i < 64; i++) { float d = z3[i] - m; v += d * d; }
        v /= 64.f;
        mv[0] = m; mv[1] = rsqrtf(v + EPSB);
    }
    __syncthreads();
    if (t < 64) out[t] = (z3[t] - mv[0]) * mv[1] * g3[0] + b3[0];
}

// ---------------- launch ----------------
extern "C" void kernel_launch(void* const* d_in, const int* in_sizes, int n_in,
                              void* d_out, int out_size) {
    const float* x        = (const float*)d_in[0];
    const float* gat_w    = (const float*)d_in[1];
    const float* gat_asrc = (const float*)d_in[2];
    const float* gat_adst = (const float*)d_in[3];
    const float* gat_bias = (const float*)d_in[4];
    const float* mlp_w    = (const float*)d_in[5];
    const float* mlp_b    = (const float*)d_in[6];
    const float* bn0_g    = (const float*)d_in[7];
    const float* bn0_b    = (const float*)d_in[8];
    const float* fc1_w    = (const float*)d_in[9];
    const float* fc1_b    = (const float*)d_in[10];
    const float* bn1_g    = (const float*)d_in[11];
    const float* bn1_b    = (const float*)d_in[12];
    const float* fc2_w    = (const float*)d_in[13];
    const float* fc2_b    = (const float*)d_in[14];
    const float* bn2_g    = (const float*)d_in[15];
    const float* bn2_b    = (const float*)d_in[16];
    const float* fc3_w    = (const float*)d_in[17];
    const float* fc3_b    = (const float*)d_in[18];
    const float* bn3_g    = (const float*)d_in[19];
    const float* bn3_b    = (const float*)d_in[20];
    const int*   ei       = (const int*)d_in[21];
    const int*   batch    = (const int*)d_in[22];
    float* out = (float*)d_out;

    // gemm0 is the 4th launch (profile slot)
    k_init<<<(Nn + 255) / 256, 256>>>();
    k_prepw<<<(448 * 256 + 255) / 256, 256>>>(gat_w, mlp_w);
    k_degree<<<(ET + 255) / 256, 256>>>(ei);
    k_gemm<0><<<dim3(NP / 64, 2), 256>>>(x, gat_asrc, gat_adst);
    k_scanA<<<SB, 256>>>();
    k_scanB<<<SB, 256>>>();
    k_edge<<<(ET + 255) / 256, 256>>>(ei);
    k_agg<<<(Nn * 32 + 255) / 256, 256>>>(gat_bias);
    k_gemm<1><<<dim3(NP / 64, 1), 256>>>(nullptr, nullptr, nullptr);
    k_poolstats<<<200, 128>>>(batch, mlp_b);
    k_bn0_final<<<1, 128>>>(bn0_g, bn0_b);
    k_hpfix<<<(Gg * Cc + 255) / 256, 256>>>();
    k_fc1<<<(Gg * 512 + 255) / 256, 256>>>(fc1_w, fc1_b);
    k_bn1<<<2, 256>>>(bn1_g, bn1_b);
    k_fc2<<<(Gg * 256 + 255) / 256, 256>>>(fc2_w, fc2_b);
    k_bn2<<<1, 256>>>(bn2_g, bn2_b);
    k_fc3<<<1, 256>>>(fc3_w, fc3_b, bn3_g, bn3_b, out);
}

// round 16
// speedup vs baseline: 1.7858x; 1.0780x over previous
#include <cuda_runtime.h>
#include <cuda_fp16.h>
#include <mma.h>
#include <math.h>

using namespace nvcuda;

#define Nn 30000
#define NP 30016
#define Ee 960000
#define ET (Ee + Nn)
#define Hh 2
#define Cc 128
#define HC 256
#define Gg 64
#define EPSB 1e-5f
#define SB 118

// ---------------- scratch ----------------
__device__ __half g_xph[(size_t)NP * HC];
__device__ float  g_as[Nn * Hh];
__device__ float  g_ad[Nn * Hh];
__device__ int    g_deg[Nn];
__device__ int    g_ptr[Nn + 1];
__device__ int    g_cur[Nn];
__device__ int    g_blk[SB];
__device__ int4   g_csre[ET];
__device__ __half g_acch[(size_t)NP * HC];
__device__ __half g_accl[(size_t)NP * HC];
__device__ __half g_w0h[448 * 256];
__device__ __half g_w1h[256 * 128], g_w1l[256 * 128];
__device__ float4 g_w4[448];                 // gat_w @ [asrc_h0|asrc_h1|adst_h0|adst_h1]
__device__ float  g_h1[(size_t)NP * Cc];
__device__ float  g_bnsum[2 * Cc];
__device__ float  g_sc0[Cc], g_sh0[Cc];
__device__ int    g_gcnt[Gg];
__device__ float  g_hp[Gg * Cc];
__device__ float  g_z1[Gg * 512];
__device__ float  g_sc1[512], g_sh1[512];
__device__ float  g_z2[Gg * 256];
__device__ float  g_sc2[256], g_sh2[256];

// ---------------- init ----------------
__global__ void k_init() {
    int i = blockIdx.x * blockDim.x + threadIdx.x;
    if (i < Nn)      g_deg[i] = 0;
    if (i < Gg * Cc) g_hp[i] = 0.f;
    if (i < 2 * Cc)  g_bnsum[i] = 0.f;
    if (i < Gg)      g_gcnt[i] = 0;
    if (i < (NP - Nn) * HC) {   // zero padded rows of gemm1 A
        g_acch[(size_t)Nn * HC + i] = __float2half(0.f);
        g_accl[(size_t)Nn * HC + i] = __float2half(0.f);
    }
}

// ---------------- weight prep: w0 single fp16, mlp split ----------------
__global__ void k_prepw(const float* __restrict__ w0, const float* __restrict__ w1) {
    int i = blockIdx.x * blockDim.x + threadIdx.x;
    if (i < 448 * 256) g_w0h[i] = __float2half(w0[i]);
    if (i < 256 * 128) {
        float v = w1[i];
        __half h = __float2half(v);
        g_w1h[i] = h;
        g_w1l[i] = __float2half(v - __half2float(h));
    }
}

// ---------------- fused attention vectors: w4 = gat_w @ [asrc|adst] ------------
__global__ void k_prepv(const float* __restrict__ w0,
                        const float* __restrict__ asrc, const float* __restrict__ adst) {
    int wid = (blockIdx.x * blockDim.x + threadIdx.x) >> 5;
    int lane = threadIdx.x & 31;
    if (wid >= 448) return;
    const float* row = w0 + wid * 256;
    float p0 = 0.f, p1 = 0.f, p2 = 0.f, p3 = 0.f;
#pragma unroll
    for (int j = 0; j < 4; j++) {
        int c = lane * 4 + j;
        float v0 = row[c], v1 = row[128 + c];
        p0 += v0 * asrc[c];       p1 += v1 * asrc[128 + c];
        p2 += v0 * adst[c];       p3 += v1 * adst[128 + c];
    }
#pragma unroll
    for (int m = 16; m; m >>= 1) {
        p0 += __shfl_down_sync(0xFFFFFFFFu, p0, m);
        p1 += __shfl_down_sync(0xFFFFFFFFu, p1, m);
        p2 += __shfl_down_sync(0xFFFFFFFFu, p2, m);
        p3 += __shfl_down_sync(0xFFFFFFFFu, p3, m);
    }
    if (lane == 0) g_w4[wid] = make_float4(p0, p1, p2, p3);
}

#define APAD 40
#define BPAD 136

// ---------------- gemm0: single fp16 term, fused exact fp32 dots ----------------
__global__ void __launch_bounds__(256, 2)
k_gemm0(const float* __restrict__ x) {
    constexpr int K = 448, Nc = 256;
    __shared__ __align__(16) char smem_raw[32768];
    __half* As = (__half*)smem_raw;          // [64][APAD]
    __half* Bs = As + 64 * APAD;             // [32][BPAD]
    int t = threadIdx.x;
    int w = t >> 5;
    int m_base = (w & 1) * 32, n_base = (w >> 1) * 32;
    int m0 = blockIdx.x * 64, n0 = blockIdx.y * 128;
    bool dodots = (blockIdx.y == 0);
    int r_own = t >> 3, ko = (t & 7) << 2;
    float dt[8] = {0.f, 0.f, 0.f, 0.f, 0.f, 0.f, 0.f, 0.f};

    wmma::fragment<wmma::accumulator, 16, 16, 16, float> fc[2][2];
#pragma unroll
    for (int i = 0; i < 2; i++)
#pragma unroll
        for (int j = 0; j < 2; j++) wmma::fill_fragment(fc[i][j], 0.f);

    for (int c = 0; c < K / 32; c++) {
        int k0 = c * 32;
        float4 av[2];
        uint4 bvh[2];
#pragma unroll
        for (int q = 0; q < 2; q++) {
            int gr = m0 + r_own + q * 32;
            av[q] = make_float4(0.f, 0.f, 0.f, 0.f);
            if (gr < Nn)
                av[q] = *(const float4*)(x + (size_t)gr * K + k0 + ko);
        }
        if (dodots) {
#pragma unroll
            for (int q = 0; q < 2; q++) {
                float f[4] = {av[q].x, av[q].y, av[q].z, av[q].w};
#pragma unroll
                for (int j = 0; j < 4; j++) {
                    float4 wv = __ldg(&g_w4[k0 + ko + j]);
                    dt[q * 4 + 0] += f[j] * wv.x;
                    dt[q * 4 + 1] += f[j] * wv.y;
                    dt[q * 4 + 2] += f[j] * wv.z;
                    dt[q * 4 + 3] += f[j] * wv.w;
                }
            }
        }
#pragma unroll
        for (int q = 0; q < 2; q++) {
            int idx = t + (q << 8);
            int br = idx >> 4, bc8 = (idx & 15) << 3;
            bvh[q] = *(const uint4*)(g_w0h + (size_t)(k0 + br) * Nc + n0 + bc8);
        }
        __syncthreads();
#pragma unroll
        for (int q = 0; q < 2; q++) {
            float f[4] = {av[q].x, av[q].y, av[q].z, av[q].w};
            __half hh[4];
#pragma unroll
            for (int j = 0; j < 4; j++) hh[j] = __float2half(f[j]);
            *(uint2*)(As + (r_own + q * 32) * APAD + ko) = *(uint2*)hh;
        }
#pragma unroll
        for (int q = 0; q < 2; q++) {
            int idx = t + (q << 8);
            int br = idx >> 4, bc8 = (idx & 15) << 3;
            *(uint4*)(Bs + br * BPAD + bc8) = bvh[q];
        }
        __syncthreads();
#pragma unroll
        for (int kk = 0; kk < 32; kk += 16) {
            wmma::fragment<wmma::matrix_a, 16, 16, 16, __half, wmma::row_major> fa[2];
#pragma unroll
            for (int i = 0; i < 2; i++)
                wmma::load_matrix_sync(fa[i], As + (m_base + i * 16) * APAD + kk, APAD);
#pragma unroll
            for (int j = 0; j < 2; j++) {
                wmma::fragment<wmma::matrix_b, 16, 16, 16, __half, wmma::row_major> fb;
                wmma::load_matrix_sync(fb, Bs + kk * BPAD + n_base + j * 16, BPAD);
#pragma unroll
                for (int i = 0; i < 2; i++)
                    wmma::mma_sync(fc[i][j], fa[i], fb, fc[i][j]);
            }
        }
        __syncthreads();
    }

    // exact dot writeback (reduce over 8-thread k-slices)
    if (dodots) {
#pragma unroll
        for (int p = 0; p < 8; p++) {
            dt[p] += __shfl_xor_sync(0xFFFFFFFFu, dt[p], 1);
            dt[p] += __shfl_xor_sync(0xFFFFFFFFu, dt[p], 2);
            dt[p] += __shfl_xor_sync(0xFFFFFFFFu, dt[p], 4);
        }
        if ((t & 7) == 0) {
            int gr0 = m0 + r_own;
            if (gr0 < Nn) {
                g_as[gr0 * 2 + 0] = dt[0]; g_as[gr0 * 2 + 1] = dt[1];
                g_ad[gr0 * 2 + 0] = dt[2]; g_ad[gr0 * 2 + 1] = dt[3];
            }
            int gr1 = gr0 + 32;
            if (gr1 < Nn) {
                g_as[gr1 * 2 + 0] = dt[4]; g_as[gr1 * 2 + 1] = dt[5];
                g_ad[gr1 * 2 + 0] = dt[6]; g_ad[gr1 * 2 + 1] = dt[7];
            }
        }
    }

    // epilogue: fp32 frags -> smem -> fp16 feature store
    float* Cs = (float*)smem_raw;   // [64][128]
#pragma unroll
    for (int i = 0; i < 2; i++)
#pragma unroll
        for (int j = 0; j < 2; j++)
            wmma::store_matrix_sync(Cs + (m_base + i * 16) * 128 + n_base + j * 16,
                                    fc[i][j], 128, wmma::mem_row_major);
    __syncthreads();
    int r = t >> 2, q = t & 3;
    int gr = m0 + r;
    int c0 = q * 32;
    __half hbuf[32];
#pragma unroll
    for (int c = 0; c < 32; c += 4) {
        float4 v = *(const float4*)(Cs + r * 128 + c0 + c);
        hbuf[c + 0] = __float2half(v.x); hbuf[c + 1] = __float2half(v.y);
        hbuf[c + 2] = __float2half(v.z); hbuf[c + 3] = __float2half(v.w);
    }
    *(uint4*)(g_xph + (size_t)gr * HC + n0 + c0)      = *(uint4*)(hbuf);
    *(uint4*)(g_xph + (size_t)gr * HC + n0 + c0 + 8)  = *(uint4*)(hbuf + 8);
    *(uint4*)(g_xph + (size_t)gr * HC + n0 + c0 + 16) = *(uint4*)(hbuf + 16);
    *(uint4*)(g_xph + (size_t)gr * HC + n0 + c0 + 24) = *(uint4*)(hbuf + 24);
}

// ---------------- gemm1: 3-term split (accuracy anchor) -------------------------
__global__ void __launch_bounds__(256, 2)
k_gemm1() {
    constexpr int K = 256, Nc = 128;
    __shared__ __align__(16) __half As_h[64 * APAD];
    __shared__ __align__(16) __half As_l[64 * APAD];
    __shared__ __align__(16) __half Bs_h[32 * BPAD];
    __shared__ __align__(16) __half Bs_l[32 * BPAD];
    int t = threadIdx.x;
    int w = t >> 5;
    int m_base = (w & 1) * 32, n_base = (w >> 1) * 32;
    int m0 = blockIdx.x * 64;
    int arow = t >> 2, ak8 = (t & 3) << 3;

    wmma::fragment<wmma::accumulator, 16, 16, 16, float> fc[2][2];
#pragma unroll
    for (int i = 0; i < 2; i++)
#pragma unroll
        for (int j = 0; j < 2; j++) wmma::fill_fragment(fc[i][j], 0.f);

    for (int c = 0; c < K / 32; c++) {
        int k0 = c * 32;
        uint4 avh = *(const uint4*)(g_acch + (size_t)(m0 + arow) * K + k0 + ak8);
        uint4 avl = *(const uint4*)(g_accl + (size_t)(m0 + arow) * K + k0 + ak8);
        uint4 bvh[2], bvl[2];
#pragma unroll
        for (int q = 0; q < 2; q++) {
            int idx = t + (q << 8);
            int br = idx >> 4, bc8 = (idx & 15) << 3;
            bvh[q] = *(const uint4*)(g_w1h + (size_t)(k0 + br) * Nc + bc8);
            bvl[q] = *(const uint4*)(g_w1l + (size_t)(k0 + br) * Nc + bc8);
        }
        __syncthreads();
        *(uint4*)(As_h + arow * APAD + ak8) = avh;
        *(uint4*)(As_l + arow * APAD + ak8) = avl;
#pragma unroll
        for (int q = 0; q < 2; q++) {
            int idx = t + (q << 8);
            int br = idx >> 4, bc8 = (idx & 15) << 3;
            *(uint4*)(Bs_h + br * BPAD + bc8) = bvh[q];
            *(uint4*)(Bs_l + br * BPAD + bc8) = bvl[q];
        }
        __syncthreads();
#pragma unroll
        for (int kk = 0; kk < 32; kk += 16) {
            wmma::fragment<wmma::matrix_a, 16, 16, 16, __half, wmma::row_major> fah[2], fal[2];
#pragma unroll
            for (int i = 0; i < 2; i++) {
                wmma::load_matrix_sync(fah[i], As_h + (m_base + i * 16) * APAD + kk, APAD);
                wmma::load_matrix_sync(fal[i], As_l + (m_base + i * 16) * APAD + kk, APAD);
            }
#pragma unroll
            for (int j = 0; j < 2; j++) {
                wmma::fragment<wmma::matrix_b, 16, 16, 16, __half, wmma::row_major> fbh, fbl;
                wmma::load_matrix_sync(fbh, Bs_h + kk * BPAD + n_base + j * 16, BPAD);
                wmma::load_matrix_sync(fbl, Bs_l + kk * BPAD + n_base + j * 16, BPAD);
#pragma unroll
                for (int i = 0; i < 2; i++) {
                    wmma::mma_sync(fc[i][j], fah[i], fbh, fc[i][j]);
                    wmma::mma_sync(fc[i][j], fah[i], fbl, fc[i][j]);
                    wmma::mma_sync(fc[i][j], fal[i], fbh, fc[i][j]);
                }
            }
        }
        __syncthreads();
    }
#pragma unroll
    for (int i = 0; i < 2; i++)
#pragma unroll
        for (int j = 0; j < 2; j++)
            wmma::store_matrix_sync(
                g_h1 + (size_t)(m0 + m_base + i * 16) * Cc + n_base + j * 16,
                fc[i][j], Cc, wmma::mem_row_major);
}

// ---------------- degree count ----------------
__global__ void k_degree(const int* __restrict__ ei) {
    int i = blockIdx.x * blockDim.x + threadIdx.x;
    if (i >= ET) return;
    int dst = (i < Ee) ? ei[Ee + i] : (i - Ee);
    atomicAdd(&g_deg[dst], 1);
}

// ---------------- parallel scan ----------------
__global__ void k_scanA() {
    __shared__ int sh[256];
    int b = blockIdx.x, t = threadIdx.x;
    int i = b * 256 + t;
    int d = (i < Nn) ? g_deg[i] : 0;
    sh[t] = d;
    __syncthreads();
    for (int off = 1; off < 256; off <<= 1) {
        int v = (t >= off) ? sh[t - off] : 0;
        __syncthreads();
        sh[t] += v;
        __syncthreads();
    }
    if (i < Nn) g_ptr[i] = sh[t] - d;
    if (t == 255) g_blk[b] = sh[255];
}
__global__ void k_scanB() {
    __shared__ int sb[128];
    int b = blockIdx.x, t = threadIdx.x;
    if (t < 128) sb[t] = (t < SB) ? g_blk[t] : 0;
    __syncthreads();
    for (int off = 1; off < 128; off <<= 1) {
        int v = 0;
        if (t < 128 && t >= off) v = sb[t - off];
        __syncthreads();
        if (t < 128) sb[t] += v;
        __syncthreads();
    }
    int offb = (b > 0) ? sb[b - 1] : 0;
    int i = b * 256 + t;
    if (i < Nn) {
        int p = g_ptr[i] + offb;
        g_ptr[i] = p;
        g_cur[i] = p;
        if (i == Nn - 1) g_ptr[Nn] = p + g_deg[i];
    }
}

// ---------------- fused edge ----------
__global__ void k_edge(const int* __restrict__ ei) {
    int i = blockIdx.x * blockDim.x + threadIdx.x;
    if (i >= ET) return;
    int src, dst;
    if (i < Ee) { src = ei[i]; dst = ei[Ee + i]; }
    else        { src = dst = i - Ee; }
    float2 as = *(const float2*)(g_as + src * 2);
    float2 ad = *(const float2*)(g_ad + dst * 2);
    float l0 = as.x + ad.x; l0 = l0 > 0.f ? l0 : 0.2f * l0;
    float l1 = as.y + ad.y; l1 = l1 > 0.f ? l1 : 0.2f * l1;
    float w0 = __expf(l0), w1 = __expf(l1);
    int pos = atomicAdd(&g_cur[dst], 1);
    g_csre[pos] = make_int4(src, __float_as_int(w0), __float_as_int(w1), 0);
}

// ---------------- aggregation: warp/dst, record-prefetch pipeline ---------------
__device__ __forceinline__ void fma8h(float* a, uint4 v, float wt) {
    __half2* h = (__half2*)&v;
#pragma unroll
    for (int i = 0; i < 4; i++) {
        float2 f = __half22float2(h[i]);
        a[2 * i]     += f.x * wt;
        a[2 * i + 1] += f.y * wt;
    }
}
__global__ void __launch_bounds__(256) k_agg(const float* __restrict__ gbias) {
    int w = (blockIdx.x * blockDim.x + threadIdx.x) >> 5;
    int lane = threadIdx.x & 31;
    if (w >= Nn) return;
    int beg = g_ptr[w], end = g_ptr[w + 1];
    const uint4* xh = (const uint4*)g_xph;
    bool hside = lane >= 16;
    float acc[8] = {0.f, 0.f, 0.f, 0.f, 0.f, 0.f, 0.f, 0.f};
    float ws = 0.f;
    int e = beg;
    int4 rc0 = __ldg(&g_csre[e]);
    int4 rc1 = (e + 1 < end) ? __ldg(&g_csre[e + 1]) : rc0;
    for (; e + 1 < end; e += 2) {
        int4 c0 = rc0, c1 = rc1;
        if (e + 3 < end)      { rc0 = __ldg(&g_csre[e + 2]); rc1 = __ldg(&g_csre[e + 3]); }
        else if (e + 2 < end) { rc0 = __ldg(&g_csre[e + 2]); }
        uint4 v0 = __ldg(xh + (size_t)c0.x * 32 + lane);
        uint4 v1 = __ldg(xh + (size_t)c1.x * 32 + lane);
        float w0 = __int_as_float(hside ? c0.z : c0.y);
        float w1 = __int_as_float(hside ? c1.z : c1.y);
        fma8h(acc, v0, w0);
        fma8h(acc, v1, w1);
        ws += w0 + w1;
    }
    if (e < end) {
        uint4 v0 = __ldg(xh + (size_t)rc0.x * 32 + lane);
        float w0 = __int_as_float(hside ? rc0.z : rc0.y);
        fma8h(acc, v0, w0);
        ws += w0;
    }
    float rd = 1.f / ws;
    __half hb[8], lb[8];
#pragma unroll
    for (int i = 0; i < 8; i++) {
        float u = acc[i] * rd + __ldg(gbias + lane * 8 + i);
        u = u > 0.f ? u : (__expf(u) - 1.f);
        hb[i] = __float2half(u);
        lb[i] = __float2half(u - __half2float(hb[i]));
    }
    *(uint4*)(g_acch + (size_t)w * HC + lane * 8) = *(uint4*)hb;
    *(uint4*)(g_accl + (size_t)w * HC + lane * 8) = *(uint4*)lb;
}

// ---------------- fused pool(raw) + BN0 stats (+mlp bias) ---------------
__global__ void k_poolstats(const int* __restrict__ batch, const float* __restrict__ mb) {
    int c = threadIdx.x;
    int per = (Nn + gridDim.x - 1) / gridDim.x;
    int s = blockIdx.x * per;
    int e = min(Nn, s + per);
    if (s >= e) return;
    float bias = __ldg(mb + c);
    float sum = 0.f, sum2 = 0.f;
    int cur = batch[s];
    float a = 0.f;
    int cnt = 0;
    for (int n = s; n < e; n++) {
        float v = g_h1[(size_t)n * Cc + c] + bias;
        sum += v; sum2 += v * v;
        int gi = batch[n];
        if (gi != cur) {
            atomicAdd(&g_hp[cur * Cc + c], a);
            if (c == 0) atomicAdd(&g_gcnt[cur], cnt);
            a = 0.f; cnt = 0; cur = gi;
        }
        a += v; cnt++;
    }
    atomicAdd(&g_hp[cur * Cc + c], a);
    if (c == 0) atomicAdd(&g_gcnt[cur], cnt);
    atomicAdd(&g_bnsum[c], sum);
    atomicAdd(&g_bnsum[Cc + c], sum2);
}

__global__ void k_bn0_final(const float* __restrict__ g, const float* __restrict__ b) {
    int c = threadIdx.x;
    if (c < Cc) {
        float mean = g_bnsum[c] / (float)Nn;
        float var  = fmaxf(g_bnsum[Cc + c] / (float)Nn - mean * mean, 0.f);
        float sc = g[c] * rsqrtf(var + EPSB);
        g_sc0[c] = sc;
        g_sh0[c] = b[c] - mean * sc;
    }
}

__global__ void k_hpfix() {
    int i = blockIdx.x * blockDim.x + threadIdx.x;
    if (i < Gg * Cc) {
        int g = i >> 7, c = i & 127;
        g_hp[i] = g_hp[i] * g_sc0[c] + (float)g_gcnt[g] * g_sh0[c];
    }
}

// ---------------- FC stack ----------------
__global__ void k_fc1(const float* __restrict__ w, const float* __restrict__ b) {
    int idx = blockIdx.x * blockDim.x + threadIdx.x;
    if (idx >= Gg * 512) return;
    int c = idx & 511, r = idx >> 9;
    float s = b[c];
#pragma unroll 8
    for (int k = 0; k < Cc; k++) s += g_hp[r * Cc + k] * w[k * 512 + c];
    g_z1[idx] = s;
}

__global__ void k_bn1(const float* __restrict__ g, const float* __restrict__ b) {
    int c = blockIdx.x * blockDim.x + threadIdx.x;
    if (c >= 512) return;
    float s = 0.f, s2 = 0.f;
    for (int r = 0; r < Gg; r++) { float v = g_z1[r * 512 + c]; s += v; s2 += v * v; }
    float mean = s / (float)Gg;
    float var = fmaxf(s2 / (float)Gg - mean * mean, 0.f);
    float sc = g[c] * rsqrtf(var + EPSB);
    g_sc1[c] = sc; g_sh1[c] = b[c] - mean * sc;
}

__global__ void k_fc2(const float* __restrict__ w, const float* __restrict__ b) {
    int idx = blockIdx.x * blockDim.x + threadIdx.x;
    if (idx >= Gg * 256) return;
    int c = idx & 255, r = idx >> 8;
    float s = b[c];
#pragma unroll 8
    for (int k = 0; k < 512; k++) {
        float v = fmaxf(g_z1[r * 512 + k] * g_sc1[k] + g_sh1[k], 0.f);
        s += v * w[k * 256 + c];
    }
    g_z2[idx] = s;
}

__global__ void k_bn2(const float* __restrict__ g, const float* __restrict__ b) {
    int c = threadIdx.x;
    if (c >= 256) return;
    float s = 0.f, s2 = 0.f;
    for (int r = 0; r < Gg; r++) { float v = g_z2[r * 256 + c]; s += v; s2 += v * v; }
    float mean = s / (float)Gg;
    float var = fmaxf(s2 / (float)Gg - mean * mean, 0.f);
    float sc = g[c] * rsqrtf(var + EPSB);
    g_sc2[c] = sc; g_sh2[c] = b[c] - mean * sc;
}

__global__ void k_fc3(const float* __restrict__ w, const float* __restrict__ b,
                      const float* __restrict__ g3, const float* __restrict__ b3,
                      float* __restrict__ out) {
    __shared__ float red[256];
    __shared__ float z3[64];
    __shared__ float mv[2];
    int t = threadIdx.x;
    int r = t >> 2, p = t & 3;
    float s = 0.f;
    for (int k = p * 64; k < p * 64 + 64; k++) {
        float v = fmaxf(g_z2[r * 256 + k] * g_sc2[k] + g_sh2[k], 0.f);
        s += v * w[k];
    }
    red[t] = s;
    __syncthreads();
    if (p == 0) z3[r] = red[t] + red[t + 1] + red[t + 2] + red[t + 3] + b[0];
    __syncthreads();
    if (t == 0) {
        float m = 0.f;
        for (int i = 0; i < 64; i++) m += z3[i];
        m /= 64.f;
        float v = 0.f;
        for (int i = 0; i < 64; i++) { float d = z3[i] - m; v += d * d; }
        v /= 64.f;
        mv[0] = m; mv[1] = rsqrtf(v + EPSB);
    }
    __syncthreads();
    if (t < 64) out[t] = (z3[t] - mv[0]) * mv[1] * g3[0] + b3[0];
}

// ---------------- launch ----------------
extern "C" void kernel_launch(void* const* d_in, const int* in_sizes, int n_in,
                              void* d_out, int out_size) {
    const float* x        = (const float*)d_in[0];
    const float* gat_w    = (const float*)d_in[1];
    const float* gat_asrc = (const float*)d_in[2];
    const float* gat_adst = (const float*)d_in[3];
    const float* gat_bias = (const float*)d_in[4];
    const float* mlp_w    = (const float*)d_in[5];
    const float* mlp_b    = (const float*)d_in[6];
    const float* bn0_g    = (const float*)d_in[7];
    const float* bn0_b    = (const float*)d_in[8];
    const float* fc1_w    = (const float*)d_in[9];
    const float* fc1_b    = (const float*)d_in[10];
    const float* bn1_g    = (const float*)d_in[11];
    const float* bn1_b    = (const float*)d_in[12];
    const float* fc2_w    = (const float*)d_in[13];
    const float* fc2_b    = (const float*)d_in[14];
    const float* bn2_g    = (const float*)d_in[15];
    const float* bn2_b    = (const float*)d_in[16];
    const float* fc3_w    = (const float*)d_in[17];
    const float* fc3_b    = (const float*)d_in[18];
    const float* bn3_g    = (const float*)d_in[19];
    const float* bn3_b    = (const float*)d_in[20];
    const int*   ei       = (const int*)d_in[21];
    const int*   batch    = (const int*)d_in[22];
    float* out = (float*)d_out;

    // gemm0 is the 4th launch (profile slot)
    k_init<<<(Nn + 255) / 256, 256>>>();
    k_prepw<<<(448 * 256 + 255) / 256, 256>>>(gat_w, mlp_w);
    k_prepv<<<14, 1024>>>(gat_w, gat_asrc, gat_adst);
    k_gemm0<<<dim3(NP / 64, 2), 256>>>(x);
    k_degree<<<(ET + 255) / 256, 256>>>(ei);
    k_scanA<<<SB, 256>>>();
    k_scanB<<<SB, 256>>>();
    k_edge<<<(ET + 255) / 256, 256>>>(ei);
    k_agg<<<(Nn * 32 + 255) / 256, 256>>>(gat_bias);
    k_gemm1<<<NP / 64, 256>>>();
    k_poolstats<<<200, 128>>>(batch, mlp_b);
    k_bn0_final<<<1, 128>>>(bn0_g, bn0_b);
    k_hpfix<<<(Gg * Cc + 255) / 256, 256>>>();
    k_fc1<<<(Gg * 512 + 255) / 256, 256>>>(fc1_w, fc1_b);
    k_bn1<<<2, 256>>>(bn1_g, bn1_b);
    k_fc2<<<(Gg * 256 + 255) / 256, 256>>>(fc2_w, fc2_b);
    k_bn2<<<1, 256>>>(bn2_g, bn2_b);
    k_fc3<<<1, 256>>>(fc3_w, fc3_b, bn3_g, bn3_b, out);
}

// round 17
// speedup vs baseline: 1.8278x; 1.0235x over previous
#include <cuda_runtime.h>
#include <cuda_fp16.h>
#include <mma.h>
#include <math.h>

using namespace nvcuda;

#define Nn 30000
#define NP 30016
#define Ee 960000
#define ET (Ee + Nn)
#define Hh 2
#define Cc 128
#define HC 256
#define Gg 64
#define EPSB 1e-5f
#define SB 118

// ---------------- scratch ----------------
__device__ __half g_xph[(size_t)NP * HC];
__device__ float4 g_asd[Nn];                 // {as_h0, as_h1, ad_h0, ad_h1}
__device__ int    g_deg[Nn];
__device__ int    g_ptr[Nn + 1];
__device__ int    g_cur[Nn];
__device__ int    g_blk[SB];
__device__ int4   g_csre[ET];
__device__ __half g_acch[(size_t)NP * HC];
__device__ __half g_accl[(size_t)NP * HC];
__device__ __half g_w0h[448 * 256];
__device__ __half g_w1h[256 * 128], g_w1l[256 * 128];
__device__ float4 g_w4[448];
__device__ float  g_h1[(size_t)NP * Cc];
__device__ float  g_bnsum[2 * Cc];
__device__ float  g_sc0[Cc], g_sh0[Cc];
__device__ int    g_gcnt[Gg];
__device__ float  g_hp[Gg * Cc];
__device__ float  g_z1[Gg * 512];
__device__ float  g_sc1[512], g_sh1[512];
__device__ float  g_z2[Gg * 256];
__device__ float  g_sc2[256], g_sh2[256];

// ---------------- init ----------------
__global__ void k_init() {
    int i = blockIdx.x * blockDim.x + threadIdx.x;
    if (i < Nn)      g_deg[i] = 0;
    if (i < Gg * Cc) g_hp[i] = 0.f;
    if (i < 2 * Cc)  g_bnsum[i] = 0.f;
    if (i < Gg)      g_gcnt[i] = 0;
    if (i < (NP - Nn) * HC) {
        g_acch[(size_t)Nn * HC + i] = __float2half(0.f);
        g_accl[(size_t)Nn * HC + i] = __float2half(0.f);
    }
}

// ---------------- weight prep ----------------
__global__ void k_prepw(const float* __restrict__ w0, const float* __restrict__ w1) {
    int i = blockIdx.x * blockDim.x + threadIdx.x;
    if (i < 448 * 256) g_w0h[i] = __float2half(w0[i]);
    if (i < 256 * 128) {
        float v = w1[i];
        __half h = __float2half(v);
        g_w1h[i] = h;
        g_w1l[i] = __float2half(v - __half2float(h));
    }
}

// ---------------- fused attention vectors ----------------
__global__ void k_prepv(const float* __restrict__ w0,
                        const float* __restrict__ asrc, const float* __restrict__ adst) {
    int wid = (blockIdx.x * blockDim.x + threadIdx.x) >> 5;
    int lane = threadIdx.x & 31;
    if (wid >= 448) return;
    const float* row = w0 + wid * 256;
    float p0 = 0.f, p1 = 0.f, p2 = 0.f, p3 = 0.f;
#pragma unroll
    for (int j = 0; j < 4; j++) {
        int c = lane * 4 + j;
        float v0 = row[c], v1 = row[128 + c];
        p0 += v0 * asrc[c];       p1 += v1 * asrc[128 + c];
        p2 += v0 * adst[c];       p3 += v1 * adst[128 + c];
    }
#pragma unroll
    for (int m = 16; m; m >>= 1) {
        p0 += __shfl_down_sync(0xFFFFFFFFu, p0, m);
        p1 += __shfl_down_sync(0xFFFFFFFFu, p1, m);
        p2 += __shfl_down_sync(0xFFFFFFFFu, p2, m);
        p3 += __shfl_down_sync(0xFFFFFFFFu, p3, m);
    }
    if (lane == 0) g_w4[wid] = make_float4(p0, p1, p2, p3);
}

#define APAD 40
#define BPAD 264

// ---------------- gemm0: 64x256 tile (x read ONCE), fused exact dots ------------
__global__ void __launch_bounds__(256, 2)
k_gemm0(const float* __restrict__ x) {
    constexpr int K = 448, Nc = 256;
    __shared__ __align__(16) char smem_raw[33024];
    __half* As = (__half*)smem_raw;            // [64][40]
    __half* Bs = As + 64 * APAD;               // [32][264]
    int t = threadIdx.x;
    int w = t >> 5;
    int m_base = (w & 1) * 32;                 // 2 warps along M
    int n_base = (w >> 1) * 64;                // 4 warps along N
    int m0 = blockIdx.x * 64;
    int r_own = t >> 3, ko = (t & 7) << 2;
    float dt[8] = {0.f, 0.f, 0.f, 0.f, 0.f, 0.f, 0.f, 0.f};

    wmma::fragment<wmma::accumulator, 16, 16, 16, float> fc[2][4];
#pragma unroll
    for (int i = 0; i < 2; i++)
#pragma unroll
        for (int j = 0; j < 4; j++) wmma::fill_fragment(fc[i][j], 0.f);

    for (int c = 0; c < K / 32; c++) {
        int k0 = c * 32;
        float4 av[2];
        uint4 bvh[4];
#pragma unroll
        for (int q = 0; q < 2; q++) {
            int gr = m0 + r_own + q * 32;
            av[q] = make_float4(0.f, 0.f, 0.f, 0.f);
            if (gr < Nn)
                av[q] = *(const float4*)(x + (size_t)gr * K + k0 + ko);
        }
#pragma unroll
        for (int q = 0; q < 2; q++) {
            float f[4] = {av[q].x, av[q].y, av[q].z, av[q].w};
#pragma unroll
            for (int j = 0; j < 4; j++) {
                float4 wv = __ldg(&g_w4[k0 + ko + j]);
                dt[q * 4 + 0] += f[j] * wv.x;
                dt[q * 4 + 1] += f[j] * wv.y;
                dt[q * 4 + 2] += f[j] * wv.z;
                dt[q * 4 + 3] += f[j] * wv.w;
            }
        }
#pragma unroll
        for (int q = 0; q < 4; q++) {
            int idx = t + (q << 8);
            int br = idx >> 5, bc8 = (idx & 31) << 3;
            bvh[q] = *(const uint4*)(g_w0h + (size_t)(k0 + br) * Nc + bc8);
        }
        __syncthreads();
#pragma unroll
        for (int q = 0; q < 2; q++) {
            float f[4] = {av[q].x, av[q].y, av[q].z, av[q].w};
            __half hh[4];
#pragma unroll
            for (int j = 0; j < 4; j++) hh[j] = __float2half(f[j]);
            *(uint2*)(As + (r_own + q * 32) * APAD + ko) = *(uint2*)hh;
        }
#pragma unroll
        for (int q = 0; q < 4; q++) {
            int idx = t + (q << 8);
            int br = idx >> 5, bc8 = (idx & 31) << 3;
            *(uint4*)(Bs + br * BPAD + bc8) = bvh[q];
        }
        __syncthreads();
#pragma unroll
        for (int kk = 0; kk < 32; kk += 16) {
            wmma::fragment<wmma::matrix_a, 16, 16, 16, __half, wmma::row_major> fa[2];
#pragma unroll
            for (int i = 0; i < 2; i++)
                wmma::load_matrix_sync(fa[i], As + (m_base + i * 16) * APAD + kk, APAD);
#pragma unroll
            for (int j = 0; j < 4; j++) {
                wmma::fragment<wmma::matrix_b, 16, 16, 16, __half, wmma::row_major> fb;
                wmma::load_matrix_sync(fb, Bs + kk * BPAD + n_base + j * 16, BPAD);
#pragma unroll
                for (int i = 0; i < 2; i++)
                    wmma::mma_sync(fc[i][j], fa[i], fb, fc[i][j]);
            }
        }
        __syncthreads();
    }

    // exact dot writeback (packed float4)
#pragma unroll
    for (int p = 0; p < 8; p++) {
        dt[p] += __shfl_xor_sync(0xFFFFFFFFu, dt[p], 1);
        dt[p] += __shfl_xor_sync(0xFFFFFFFFu, dt[p], 2);
        dt[p] += __shfl_xor_sync(0xFFFFFFFFu, dt[p], 4);
    }
    if ((t & 7) == 0) {
        int gr0 = m0 + r_own;
        if (gr0 < Nn) g_asd[gr0] = make_float4(dt[0], dt[1], dt[2], dt[3]);
        int gr1 = gr0 + 32;
        if (gr1 < Nn) g_asd[gr1] = make_float4(dt[4], dt[5], dt[6], dt[7]);
    }

    // epilogue: two N-half passes through 32KB smem
    float* Cs = (float*)smem_raw;   // [64][128]
#pragma unroll
    for (int p = 0; p < 2; p++) {
        if ((w >> 2) == p) {
            int nb = n_base - p * 128;
#pragma unroll
            for (int i = 0; i < 2; i++)
#pragma unroll
                for (int j = 0; j < 4; j++)
                    wmma::store_matrix_sync(Cs + (m_base + i * 16) * 128 + nb + j * 16,
                                            fc[i][j], 128, wmma::mem_row_major);
        }
        __syncthreads();
        int r = t >> 2, q = t & 3;
        int gr = m0 + r;
        int c0 = q * 32;
        __half hbuf[32];
#pragma unroll
        for (int cc = 0; cc < 32; cc += 4) {
            float4 v = *(const float4*)(Cs + r * 128 + c0 + cc);
            hbuf[cc + 0] = __float2half(v.x); hbuf[cc + 1] = __float2half(v.y);
            hbuf[cc + 2] = __float2half(v.z); hbuf[cc + 3] = __float2half(v.w);
        }
        __half* outp = g_xph + (size_t)gr * HC + p * 128 + c0;
        *(uint4*)(outp)      = *(uint4*)(hbuf);
        *(uint4*)(outp + 8)  = *(uint4*)(hbuf + 8);
        *(uint4*)(outp + 16) = *(uint4*)(hbuf + 16);
        *(uint4*)(outp + 24) = *(uint4*)(hbuf + 24);
        __syncthreads();
    }
}

// ---------------- gemm1: 3-term split (accuracy anchor) ----------------
#define BPAD1 136
__global__ void __launch_bounds__(256, 2)
k_gemm1() {
    constexpr int K = 256, Nc = 128;
    __shared__ __align__(16) __half As_h[64 * APAD];
    __shared__ __align__(16) __half As_l[64 * APAD];
    __shared__ __align__(16) __half Bs_h[32 * BPAD1];
    __shared__ __align__(16) __half Bs_l[32 * BPAD1];
    int t = threadIdx.x;
    int w = t >> 5;
    int m_base = (w & 1) * 32, n_base = (w >> 1) * 32;
    int m0 = blockIdx.x * 64;
    int arow = t >> 2, ak8 = (t & 3) << 3;

    wmma::fragment<wmma::accumulator, 16, 16, 16, float> fc[2][2];
#pragma unroll
    for (int i = 0; i < 2; i++)
#pragma unroll
        for (int j = 0; j < 2; j++) wmma::fill_fragment(fc[i][j], 0.f);

    for (int c = 0; c < K / 32; c++) {
        int k0 = c * 32;
        uint4 avh = *(const uint4*)(g_acch + (size_t)(m0 + arow) * K + k0 + ak8);
        uint4 avl = *(const uint4*)(g_accl + (size_t)(m0 + arow) * K + k0 + ak8);
        uint4 bvh[2], bvl[2];
#pragma unroll
        for (int q = 0; q < 2; q++) {
            int idx = t + (q << 8);
            int br = idx >> 4, bc8 = (idx & 15) << 3;
            bvh[q] = *(const uint4*)(g_w1h + (size_t)(k0 + br) * Nc + bc8);
            bvl[q] = *(const uint4*)(g_w1l + (size_t)(k0 + br) * Nc + bc8);
        }
        __syncthreads();
        *(uint4*)(As_h + arow * APAD + ak8) = avh;
        *(uint4*)(As_l + arow * APAD + ak8) = avl;
#pragma unroll
        for (int q = 0; q < 2; q++) {
            int idx = t + (q << 8);
            int br = idx >> 4, bc8 = (idx & 15) << 3;
            *(uint4*)(Bs_h + br * BPAD1 + bc8) = bvh[q];
            *(uint4*)(Bs_l + br * BPAD1 + bc8) = bvl[q];
        }
        __syncthreads();
#pragma unroll
        for (int kk = 0; kk < 32; kk += 16) {
            wmma::fragment<wmma::matrix_a, 16, 16, 16, __half, wmma::row_major> fah[2], fal[2];
#pragma unroll
            for (int i = 0; i < 2; i++) {
                wmma::load_matrix_sync(fah[i], As_h + (m_base + i * 16) * APAD + kk, APAD);
                wmma::load_matrix_sync(fal[i], As_l + (m_base + i * 16) * APAD + kk, APAD);
            }
#pragma unroll
            for (int j = 0; j < 2; j++) {
                wmma::fragment<wmma::matrix_b, 16, 16, 16, __half, wmma::row_major> fbh, fbl;
                wmma::load_matrix_sync(fbh, Bs_h + kk * BPAD1 + n_base + j * 16, BPAD1);
                wmma::load_matrix_sync(fbl, Bs_l + kk * BPAD1 + n_base + j * 16, BPAD1);
#pragma unroll
                for (int i = 0; i < 2; i++) {
                    wmma::mma_sync(fc[i][j], fah[i], fbh, fc[i][j]);
                    wmma::mma_sync(fc[i][j], fah[i], fbl, fc[i][j]);
                    wmma::mma_sync(fc[i][j], fal[i], fbh, fc[i][j]);
                }
            }
        }
        __syncthreads();
    }
#pragma unroll
    for (int i = 0; i < 2; i++)
#pragma unroll
        for (int j = 0; j < 2; j++)
            wmma::store_matrix_sync(
                g_h1 + (size_t)(m0 + m_base + i * 16) * Cc + n_base + j * 16,
                fc[i][j], Cc, wmma::mem_row_major);
}

// ---------------- degree count ----------------
__global__ void k_degree(const int* __restrict__ ei) {
    int i = blockIdx.x * blockDim.x + threadIdx.x;
    if (i >= ET) return;
    int dst = (i < Ee) ? ei[Ee + i] : (i - Ee);
    atomicAdd(&g_deg[dst], 1);
}

// ---------------- parallel scan ----------------
__global__ void k_scanA() {
    __shared__ int sh[256];
    int b = blockIdx.x, t = threadIdx.x;
    int i = b * 256 + t;
    int d = (i < Nn) ? g_deg[i] : 0;
    sh[t] = d;
    __syncthreads();
    for (int off = 1; off < 256; off <<= 1) {
        int v = (t >= off) ? sh[t - off] : 0;
        __syncthreads();
        sh[t] += v;
        __syncthreads();
    }
    if (i < Nn) g_ptr[i] = sh[t] - d;
    if (t == 255) g_blk[b] = sh[255];
}
__global__ void k_scanB() {
    __shared__ int sb[128];
    int b = blockIdx.x, t = threadIdx.x;
    if (t < 128) sb[t] = (t < SB) ? g_blk[t] : 0;
    __syncthreads();
    for (int off = 1; off < 128; off <<= 1) {
        int v = 0;
        if (t < 128 && t >= off) v = sb[t - off];
        __syncthreads();
        if (t < 128) sb[t] += v;
        __syncthreads();
    }
    int offb = (b > 0) ? sb[b - 1] : 0;
    int i = b * 256 + t;
    if (i < Nn) {
        int p = g_ptr[i] + offb;
        g_ptr[i] = p;
        g_cur[i] = p;
        if (i == Nn - 1) g_ptr[Nn] = p + g_deg[i];
    }
}

// ---------------- fused edge (packed dot loads) ----------
__global__ void k_edge(const int* __restrict__ ei) {
    int i = blockIdx.x * blockDim.x + threadIdx.x;
    if (i >= ET) return;
    int src, dst;
    if (i < Ee) { src = ei[i]; dst = ei[Ee + i]; }
    else        { src = dst = i - Ee; }
    float4 s = __ldg(&g_asd[src]);
    float4 d = __ldg(&g_asd[dst]);
    float l0 = s.x + d.z; l0 = l0 > 0.f ? l0 : 0.2f * l0;
    float l1 = s.y + d.w; l1 = l1 > 0.f ? l1 : 0.2f * l1;
    float w0 = __expf(l0), w1 = __expf(l1);
    int pos = atomicAdd(&g_cur[dst], 1);
    g_csre[pos] = make_int4(src, __float_as_int(w0), __float_as_int(w1), 0);
}

// ---------------- aggregation: warp/dst, record-prefetch pipeline ---------------
__device__ __forceinline__ void fma8h(float* a, uint4 v, float wt) {
    __half2* h = (__half2*)&v;
#pragma unroll
    for (int i = 0; i < 4; i++) {
        float2 f = __half22float2(h[i]);
        a[2 * i]     += f.x * wt;
        a[2 * i + 1] += f.y * wt;
    }
}
__global__ void __launch_bounds__(256) k_agg(const float* __restrict__ gbias) {
    int w = (blockIdx.x * blockDim.x + threadIdx.x) >> 5;
    int lane = threadIdx.x & 31;
    if (w >= Nn) return;
    int beg = g_ptr[w], end = g_ptr[w + 1];
    const uint4* xh = (const uint4*)g_xph;
    bool hside = lane >= 16;
    float acc[8] = {0.f, 0.f, 0.f, 0.f, 0.f, 0.f, 0.f, 0.f};
    float ws = 0.f;
    int e = beg;
    int4 rc0 = __ldg(&g_csre[e]);
    int4 rc1 = (e + 1 < end) ? __ldg(&g_csre[e + 1]) : rc0;
    for (; e + 1 < end; e += 2) {
        int4 c0 = rc0, c1 = rc1;
        if (e + 3 < end)      { rc0 = __ldg(&g_csre[e + 2]); rc1 = __ldg(&g_csre[e + 3]); }
        else if (e + 2 < end) { rc0 = __ldg(&g_csre[e + 2]); }
        uint4 v0 = __ldg(xh + (size_t)c0.x * 32 + lane);
        uint4 v1 = __ldg(xh + (size_t)c1.x * 32 + lane);
        float w0 = __int_as_float(hside ? c0.z : c0.y);
        float w1 = __int_as_float(hside ? c1.z : c1.y);
        fma8h(acc, v0, w0);
        fma8h(acc, v1, w1);
        ws += w0 + w1;
    }
    if (e < end) {
        uint4 v0 = __ldg(xh + (size_t)rc0.x * 32 + lane);
        float w0 = __int_as_float(hside ? rc0.z : rc0.y);
        fma8h(acc, v0, w0);
        ws += w0;
    }
    float rd = 1.f / ws;
    __half hb[8], lb[8];
#pragma unroll
    for (int i = 0; i < 8; i++) {
        float u = acc[i] * rd + __ldg(gbias + lane * 8 + i);
        u = u > 0.f ? u : (__expf(u) - 1.f);
        hb[i] = __float2half(u);
        lb[i] = __float2half(u - __half2float(hb[i]));
    }
    *(uint4*)(g_acch + (size_t)w * HC + lane * 8) = *(uint4*)hb;
    *(uint4*)(g_accl + (size_t)w * HC + lane * 8) = *(uint4*)lb;
}

// ---------------- fused pool(raw) + BN0 stats (+mlp bias) ---------------
__global__ void k_poolstats(const int* __restrict__ batch, const float* __restrict__ mb) {
    int c = threadIdx.x;
    int per = (Nn + gridDim.x - 1) / gridDim.x;
    int s = blockIdx.x * per;
    int e = min(Nn, s + per);
    if (s >= e) return;
    float bias = __ldg(mb + c);
    float sum = 0.f, sum2 = 0.f;
    int cur = batch[s];
    float a = 0.f;
    int cnt = 0;
    for (int n = s; n < e; n++) {
        float v = g_h1[(size_t)n * Cc + c] + bias;
        sum += v; sum2 += v * v;
        int gi = batch[n];
        if (gi != cur) {
            atomicAdd(&g_hp[cur * Cc + c], a);
            if (c == 0) atomicAdd(&g_gcnt[cur], cnt);
            a = 0.f; cnt = 0; cur = gi;
        }
        a += v; cnt++;
    }
    atomicAdd(&g_hp[cur * Cc + c], a);
    if (c == 0) atomicAdd(&g_gcnt[cur], cnt);
    atomicAdd(&g_bnsum[c], sum);
    atomicAdd(&g_bnsum[Cc + c], sum2);
}

__global__ void k_bn0_final(const float* __restrict__ g, const float* __restrict__ b) {
    int c = threadIdx.x;
    if (c < Cc) {
        float mean = g_bnsum[c] / (float)Nn;
        float var  = fmaxf(g_bnsum[Cc + c] / (float)Nn - mean * mean, 0.f);
        float sc = g[c] * rsqrtf(var + EPSB);
        g_sc0[c] = sc;
        g_sh0[c] = b[c] - mean * sc;
    }
}

__global__ void k_hpfix() {
    int i = blockIdx.x * blockDim.x + threadIdx.x;
    if (i < Gg * Cc) {
        int g = i >> 7, c = i & 127;
        g_hp[i] = g_hp[i] * g_sc0[c] + (float)g_gcnt[g] * g_sh0[c];
    }
}

// ---------------- FC stack ----------------
__global__ void k_fc1(const float* __restrict__ w, const float* __restrict__ b) {
    int idx = blockIdx.x * blockDim.x + threadIdx.x;
    if (idx >= Gg * 512) return;
    int c = idx & 511, r = idx >> 9;
    float s = b[c];
#pragma unroll 8
    for (int k = 0; k < Cc; k++) s += g_hp[r * Cc + k] * w[k * 512 + c];
    g_z1[idx] = s;
}

__global__ void k_bn1(const float* __restrict__ g, const float* __restrict__ b) {
    int c = blockIdx.x * blockDim.x + threadIdx.x;
    if (c >= 512) return;
    float s = 0.f, s2 = 0.f;
    for (int r = 0; r < Gg; r++) { float v = g_z1[r * 512 + c]; s += v; s2 += v * v; }
    float mean = s / (float)Gg;
    float var = fmaxf(s2 / (float)Gg - mean * mean, 0.f);
    float sc = g[c] * rsqrtf(var + EPSB);
    g_sc1[c] = sc; g_sh1[c] = b[c] - mean * sc;
}

__global__ void k_fc2(const float* __restrict__ w, const float* __restrict__ b) {
    int idx = blockIdx.x * blockDim.x + threadIdx.x;
    if (idx >= Gg * 256) return;
    int c = idx & 255, r = idx >> 8;
    float s = b[c];
#pragma unroll 8
    for (int k = 0; k < 512; k++) {
        float v = fmaxf(g_z1[r * 512 + k] * g_sc1[k] + g_sh1[k], 0.f);
        s += v * w[k * 256 + c];
    }
    g_z2[idx] = s;
}

__global__ void k_bn2(const float* __restrict__ g, const float* __restrict__ b) {
    int c = threadIdx.x;
    if (c >= 256) return;
    float s = 0.f, s2 = 0.f;
    for (int r = 0; r < Gg; r++) { float v = g_z2[r * 256 + c]; s += v; s2 += v * v; }
    float mean = s / (float)Gg;
    float var = fmaxf(s2 / (float)Gg - mean * mean, 0.f);
    float sc = g[c] * rsqrtf(var + EPSB);
    g_sc2[c] = sc; g_sh2[c] = b[c] - mean * sc;
}

__global__ void k_fc3(const float* __restrict__ w, const float* __restrict__ b,
                      const float* __restrict__ g3, const float* __restrict__ b3,
                      float* __restrict__ out) {
    __shared__ float red[256];
    __shared__ float z3[64];
    __shared__ float mv[2];
    int t = threadIdx.x;
    int r = t >> 2, p = t & 3;
    float s = 0.f;
    for (int k = p * 64; k < p * 64 + 64; k++) {
        float v = fmaxf(g_z2[r * 256 + k] * g_sc2[k] + g_sh2[k], 0.f);
        s += v * w[k];
    }
    red[t] = s;
    __syncthreads();
    if (p == 0) z3[r] = red[t] + red[t + 1] + red[t + 2] + red[t + 3] + b[0];
    __syncthreads();
    if (t == 0) {
        float m = 0.f;
        for (int i = 0; i < 64; i++) m += z3[i];
        m /= 64.f;
        float v = 0.f;
        for (int i = 0; i < 64; i++) { float d = z3[i] - m; v += d * d; }
        v /= 64.f;
        mv[0] = m; mv[1] = rsqrtf(v + EPSB);
    }
    __syncthreads();
    if (t < 64) out[t] = (z3[t] - mv[0]) * mv[1] * g3[0] + b3[0];
}

// ---------------- launch ----------------
extern "C" void kernel_launch(void* const* d_in, const int* in_sizes, int n_in,
                              void* d_out, int out_size) {
    const float* x        = (const float*)d_in[0];
    const float* gat_w    = (const float*)d_in[1];
    const float* gat_asrc = (const float*)d_in[2];
    const float* gat_adst = (const float*)d_in[3];
    const float* gat_bias = (const float*)d_in[4];
    const float* mlp_w    = (const float*)d_in[5];
    const float* mlp_b    = (const float*)d_in[6];
    const float* bn0_g    = (const float*)d_in[7];
    const float* bn0_b    = (const float*)d_in[8];
    const float* fc1_w    = (const float*)d_in[9];
    const float* fc1_b    = (const float*)d_in[10];
    const float* bn1_g    = (const float*)d_in[11];
    const float* bn1_b    = (const float*)d_in[12];
    const float* fc2_w    = (const float*)d_in[13];
    const float* fc2_b    = (const float*)d_in[14];
    const float* bn2_g    = (const float*)d_in[15];
    const float* bn2_b    = (const float*)d_in[16];
    const float* fc3_w    = (const float*)d_in[17];
    const float* fc3_b    = (const float*)d_in[18];
    const float* bn3_g    = (const float*)d_in[19];
    const float* bn3_b    = (const float*)d_in[20];
    const int*   ei       = (const int*)d_in[21];
    const int*   batch    = (const int*)d_in[22];
    float* out = (float*)d_out;

    // gemm0 is the 4th launch (profile slot)
    k_init<<<(Nn + 255) / 256, 256>>>();
    k_prepw<<<(448 * 256 + 255) / 256, 256>>>(gat_w, mlp_w);
    k_prepv<<<14, 1024>>>(gat_w, gat_asrc, gat_adst);
    k_gemm0<<<NP / 64, 256>>>(x);
    k_degree<<<(ET + 255) / 256, 256>>>(ei);
    k_scanA<<<SB, 256>>>();
    k_scanB<<<SB, 256>>>();
    k_edge<<<(ET + 255) / 256, 256>>>(ei);
    k_agg<<<(Nn * 32 + 255) / 256, 256>>>(gat_bias);
    k_gemm1<<<NP / 64, 256>>>();
    k_poolstats<<<200, 128>>>(batch, mlp_b);
    k_bn0_final<<<1, 128>>>(bn0_g, bn0_b);
    k_hpfix<<<(Gg * Cc + 255) / 256, 256>>>();
    k_fc1<<<(Gg * 512 + 255) / 256, 256>>>(fc1_w, fc1_b);
    k_bn1<<<2, 256>>>(bn1_g, bn1_b);
    k_fc2<<<(Gg * 256 + 255) / 256, 256>>>(fc2_w, fc2_b);
    k_bn2<<<1, 256>>>(bn2_g, bn2_b);
    k_fc3<<<1, 256>>>(fc3_w, fc3_b, bn3_g, bn3_b, out);
}